// round 3
// baseline (speedup 1.0000x reference)
#include <cuda_runtime.h>
#include <cuda_bf16.h>
#include <math.h>
#include <stdint.h>

// ---------------- problem constants ----------------
#define NTOK 16384
#define DIM  1024
#define HID  4096
#define NOUT 1024
#define NEXP 8
#define NB   4
#define RLO  16
#define PMAX 33792            // 2*NTOK + 8*128 padding, multiple of 128

// ---------------- device scratch (static: no allocs allowed) ----------------
__device__ float g_h[(size_t)PMAX * HID];      // post-gelu hidden, fp32 (~553 MB)
__device__ float g_t1[(size_t)PMAX * 64];      // 2*(x @ A1) expanded over bands
__device__ float g_t2[(size_t)PMAX * 64];      // 2*(h @ A2) expanded over bands
__device__ int   g_token[PMAX];
__device__ int   g_band[PMAX];
__device__ int   g_expert[PMAX];
__device__ float g_gate[PMAX];
__device__ int   g_top2_idx[NTOK * 2];
__device__ float g_top2_gate[NTOK * 2];
__device__ int   g_counts[NEXP];
__device__ int   g_cursor[NEXP];
__device__ int   g_po[NEXP + 1];
__device__ int   g_total;

// ---------------- small helpers ----------------
__device__ __forceinline__ void cp16(void* smem, const void* gmem) {
    uint32_t s = (uint32_t)__cvta_generic_to_shared(smem);
    asm volatile("cp.async.cg.shared.global [%0], [%1], 16;" :: "r"(s), "l"(gmem));
}
__device__ __forceinline__ void cp_commit() {
    asm volatile("cp.async.commit_group;" ::: "memory");
}
template <int n>
__device__ __forceinline__ void cp_wait() {
    asm volatile("cp.async.wait_group %0;" :: "n"(n) : "memory");
}
__device__ __forceinline__ uint32_t f2tf32(float f) {
    uint32_t r;
    asm("cvt.rna.tf32.f32 %0, %1;" : "=r"(r) : "f"(f));
    return r;
}
__device__ __forceinline__ void mma_tf32(float* c, const uint32_t* a, const uint32_t* b) {
    asm volatile(
        "mma.sync.aligned.m16n8k8.row.col.f32.tf32.tf32.f32 "
        "{%0,%1,%2,%3}, {%4,%5,%6,%7}, {%8,%9}, {%0,%1,%2,%3};"
        : "+f"(c[0]), "+f"(c[1]), "+f"(c[2]), "+f"(c[3])
        : "r"(a[0]), "r"(a[1]), "r"(a[2]), "r"(a[3]), "r"(b[0]), "r"(b[1]));
}
__device__ __forceinline__ float gelu_exact(float x) {
    return 0.5f * x * (1.0f + erff(x * 0.70710678118654752440f));
}

// ---------------- 1. init: zero y + dispatch state ----------------
__global__ void k_init(float* __restrict__ y) {
    size_t i = (size_t)blockIdx.x * 256 + threadIdx.x;   // 16384*256 = NTOK*NOUT/4
    float4 z = make_float4(0.f, 0.f, 0.f, 0.f);
    reinterpret_cast<float4*>(y)[i] = z;
    if (i < PMAX) {
        g_token[i] = 0;
        g_band[i] = 0;
        g_expert[i] = 0;
        g_gate[i] = 0.f;
    }
    if (i < NEXP) { g_counts[i] = 0; g_cursor[i] = 0; }
}

// ---------------- 2. gating: logits, top-2, softmax ----------------
__global__ void k_gate(const float* __restrict__ x, const float* __restrict__ wg) {
    int gtid = blockIdx.x * blockDim.x + threadIdx.x;
    int tok  = gtid >> 5;
    int lane = threadIdx.x & 31;
    if (tok >= NTOK) return;

    const float* xr = x + (size_t)tok * DIM;
    float acc[NEXP];
#pragma unroll
    for (int e = 0; e < NEXP; e++) acc[e] = 0.f;
    for (int d = lane; d < DIM; d += 32) {
        float xv = xr[d];
        const float4* w4 = reinterpret_cast<const float4*>(wg + (size_t)d * NEXP);
        float4 wa = w4[0], wb = w4[1];
        acc[0] += xv * wa.x; acc[1] += xv * wa.y; acc[2] += xv * wa.z; acc[3] += xv * wa.w;
        acc[4] += xv * wb.x; acc[5] += xv * wb.y; acc[6] += xv * wb.z; acc[7] += xv * wb.w;
    }
#pragma unroll
    for (int e = 0; e < NEXP; e++) {
#pragma unroll
        for (int off = 16; off; off >>= 1)
            acc[e] += __shfl_xor_sync(0xffffffffu, acc[e], off);
    }
    // top-2 (strict > keeps lowest index on ties, matching lax.top_k)
    int i0 = 0; float v0 = acc[0];
#pragma unroll
    for (int e = 1; e < NEXP; e++) if (acc[e] > v0) { v0 = acc[e]; i0 = e; }
    int i1 = -1; float v1 = -3.4e38f;
#pragma unroll
    for (int e = 0; e < NEXP; e++) if (e != i0 && acc[e] > v1) { v1 = acc[e]; i1 = e; }

    float ex = expf(v1 - v0);
    float den = 1.f + ex;
    float g0 = 1.f / den;
    float g1 = ex / den;

    if (lane == 0) {
        g_top2_idx[tok * 2]      = i0;
        g_top2_idx[tok * 2 + 1]  = i1;
        g_top2_gate[tok * 2]     = g0;
        g_top2_gate[tok * 2 + 1] = g1;
        atomicAdd(&g_counts[i0], 1);
        atomicAdd(&g_counts[i1], 1);
    }
}

// ---------------- 3. offsets + loss (1 block, deterministic) ----------------
__global__ void k_offsets(float* __restrict__ out, int out_size) {
    __shared__ float simp[256][NEXP];
    __shared__ float s_imp[NEXP];
    int tid = threadIdx.x;
    float local[NEXP];
#pragma unroll
    for (int e = 0; e < NEXP; e++) local[e] = 0.f;
    for (int i = tid; i < 2 * NTOK; i += 256) {
        int e = g_top2_idx[i];
        float gv = g_top2_gate[i];
#pragma unroll
        for (int q = 0; q < NEXP; q++) local[q] += (q == e) ? gv : 0.f;
    }
#pragma unroll
    for (int e = 0; e < NEXP; e++) simp[tid][e] = local[e];
    __syncthreads();
    if (tid < NEXP) {
        float s = 0.f;
        for (int i = 0; i < 256; i++) s += simp[i][tid];
        s_imp[tid] = s;
    }
    __syncthreads();
    if (tid == 0) {
        int p = 0;
        for (int e = 0; e < NEXP; e++) {
            g_po[e] = p;
            p += (g_counts[e] + 127) & ~127;
        }
        g_po[NEXP] = p;
        g_total = p;

        float mi = 0.f, ml = 0.f;
        for (int e = 0; e < NEXP; e++) { mi += s_imp[e]; ml += (float)g_counts[e]; }
        mi *= (1.f / NEXP); ml *= (1.f / NEXP);
        float vi = 0.f, vl = 0.f;
        for (int e = 0; e < NEXP; e++) {
            float di = s_imp[e] - mi;  vi += di * di;
            float dl = (float)g_counts[e] - ml; vl += dl * dl;
        }
        vi *= (1.f / (NEXP - 1)); vl *= (1.f / (NEXP - 1));
        float loss = 0.01f * (vi / (mi * mi + 1e-10f) + vl / (ml * ml + 1e-10f));
        if (out_size > NTOK * NOUT) out[(size_t)NTOK * NOUT] = loss;
    }
}

// ---------------- 4. scatter dispatch ----------------
__global__ void k_scatter(const int* __restrict__ band) {
    int i = blockIdx.x * 256 + threadIdx.x;
    if (i >= 2 * NTOK) return;
    int t = i >> 1;
    int e = g_top2_idx[i];
    int pos = g_po[e] + atomicAdd(&g_cursor[e], 1);
    g_token[pos]  = t;
    g_gate[pos]   = g_top2_gate[i];
    g_band[pos]   = band[t];
    g_expert[pos] = e;
}

// ---------------- 5. lora down-proj, layer 1: t1 = 2*(x @ A1[e,band]) ----------------
__global__ void k_lora1(const float* __restrict__ x, const float* __restrict__ A1) {
    int row  = blockIdx.x * 8 + (threadIdx.x >> 5);
    int lane = threadIdx.x & 31;
    if (row >= g_total) return;
    int tok = g_token[row], band = g_band[row], e = g_expert[row];
    const float* a = A1 + (size_t)(e * NB + band) * DIM * RLO;
    const float* xr = x + (size_t)tok * DIM;
    float acc[RLO];
#pragma unroll
    for (int r = 0; r < RLO; r++) acc[r] = 0.f;
    for (int d = lane; d < DIM; d += 32) {
        float xv = xr[d];
        const float* ar = a + (size_t)d * RLO;
#pragma unroll
        for (int r = 0; r < RLO; r++) acc[r] += xv * ar[r];
    }
    float mine = 0.f;
#pragma unroll
    for (int r = 0; r < RLO; r++) {
        float s = acc[r];
#pragma unroll
        for (int off = 16; off; off >>= 1) s += __shfl_xor_sync(0xffffffffu, s, off);
        if (lane == r) mine = s;
    }
    float* dst = g_t1 + (size_t)row * 64;
    for (int j = lane; j < 64; j += 32) dst[j] = 0.f;
    __syncwarp();
    if (lane < RLO) dst[band * RLO + lane] = 2.0f * mine;
}

// ---------------- 7. lora down-proj, layer 2: t2 = 2*(h @ A2[e,band]) ----------------
__global__ void k_lora2(const float* __restrict__ A2) {
    int row  = blockIdx.x * 8 + (threadIdx.x >> 5);
    int lane = threadIdx.x & 31;
    if (row >= g_total) return;
    int band = g_band[row], e = g_expert[row];
    const float* a = A2 + (size_t)(e * NB + band) * HID * RLO;
    const float* hr = g_h + (size_t)row * HID;
    float acc[RLO];
#pragma unroll
    for (int r = 0; r < RLO; r++) acc[r] = 0.f;
    for (int d = lane; d < HID; d += 32) {
        float hv = hr[d];
        const float* ar = a + (size_t)d * RLO;
#pragma unroll
        for (int r = 0; r < RLO; r++) acc[r] += hv * ar[r];
    }
    float mine = 0.f;
#pragma unroll
    for (int r = 0; r < RLO; r++) {
        float s = acc[r];
#pragma unroll
        for (int off = 16; off; off >>= 1) s += __shfl_xor_sync(0xffffffffu, s, off);
        if (lane == r) mine = s;
    }
    float* dst = g_t2 + (size_t)row * 64;
    for (int j = lane; j < 64; j += 32) dst[j] = 0.f;
    __syncwarp();
    if (lane < RLO) dst[band * RLO + lane] = 2.0f * mine;
}

// ---------------- 6/8. grouped GEMM (tf32 mma.sync), LoRA folded into K ----------------
// C[128,128] tile; K = KMAIN (+64 lora-ext columns). SECOND=false: h = gelu(x@W1+b1+lora)
// SECOND=true: y += gate * (h@W2 + b2 + lora) via red.global.add
template <int KMAIN, int NW, bool SECOND>
__global__ void __launch_bounds__(256, 2)
k_gemm(const float* __restrict__ Ain,
       const float* __restrict__ Bmain,
       const float* __restrict__ Bext,
       const float* __restrict__ bias,
       float* __restrict__ Cout) {
    const int tile_r = blockIdx.y * 128;
    if (tile_r >= g_total) return;
    const int tile_c = blockIdx.x * 128;
    const int e = g_expert[tile_r];

    __shared__ float As[2][128][20];    // padded: conflict-free A-frag lds
    __shared__ float Bs[2][16][136];    // padded: conflict-free B-frag lds
    __shared__ int   stok[128];

    const int tid  = threadIdx.x;
    const int wid  = tid >> 5;
    const int lane = tid & 31;
    const int gq   = lane >> 2;          // group id (0..7)
    const int tq   = lane & 3;           // thread-in-group (0..3)
    const int m0   = (wid & 1) * 64;
    const int n0   = (wid >> 1) * 32;

    if (tid < 128) stok[tid] = SECOND ? (tile_r + tid) : g_token[tile_r + tid];
    __syncthreads();

    const float* Bm = Bmain + (size_t)e * KMAIN * NW;
    const float* Be = Bext + (size_t)e * 64 * NW;
    const float* Aext = SECOND ? g_t2 : g_t1;

    auto load_tiles = [&](int it, int buf) {
        int k0 = it * 16;
        bool mainreg = (k0 < KMAIN);
#pragma unroll
        for (int s = 0; s < 2; s++) {
            int idx = tid + s * 256;
            int r = idx >> 2, kq = idx & 3;
            const float* src;
            if (mainreg) {
                const float* abase = SECOND ? (g_h + (size_t)stok[r] * KMAIN)
                                            : (Ain + (size_t)stok[r] * KMAIN);
                src = abase + k0 + kq * 4;
            } else {
                src = Aext + (size_t)(tile_r + r) * 64 + (k0 - KMAIN) + kq * 4;
            }
            cp16(&As[buf][r][kq * 4], src);
        }
#pragma unroll
        for (int s = 0; s < 2; s++) {
            int idx = tid + s * 256;
            int k = idx >> 5, cq = idx & 31;
            const float* src = mainreg
                ? Bm + (size_t)(k0 + k) * NW + tile_c + cq * 4
                : Be + (size_t)(k0 - KMAIN + k) * NW + tile_c + cq * 4;
            cp16(&Bs[buf][k][cq * 4], src);
        }
        cp_commit();
    };

    float c[4][4][4];
#pragma unroll
    for (int mi = 0; mi < 4; mi++)
#pragma unroll
        for (int nj = 0; nj < 4; nj++)
#pragma unroll
            for (int q = 0; q < 4; q++) c[mi][nj][q] = 0.f;

    constexpr int NIT = (KMAIN + 64) / 16;
    load_tiles(0, 0);

    for (int it = 0; it < NIT; ++it) {
        int buf = it & 1;
        if (it + 1 < NIT) {
            load_tiles(it + 1, buf ^ 1);
            cp_wait<1>();
        } else {
            cp_wait<0>();
        }
        __syncthreads();

#pragma unroll
        for (int kk = 0; kk < 2; kk++) {
            int kb = kk * 8;
            uint32_t a[4][4], b[4][2];
#pragma unroll
            for (int mi = 0; mi < 4; mi++) {
                int r = m0 + mi * 16 + gq;
                a[mi][0] = f2tf32(As[buf][r][kb + tq]);
                a[mi][1] = f2tf32(As[buf][r + 8][kb + tq]);
                a[mi][2] = f2tf32(As[buf][r][kb + tq + 4]);
                a[mi][3] = f2tf32(As[buf][r + 8][kb + tq + 4]);
            }
#pragma unroll
            for (int nj = 0; nj < 4; nj++) {
                int cb = n0 + nj * 8 + gq;
                b[nj][0] = f2tf32(Bs[buf][kb + tq][cb]);
                b[nj][1] = f2tf32(Bs[buf][kb + tq + 4][cb]);
            }
#pragma unroll
            for (int mi = 0; mi < 4; mi++)
#pragma unroll
                for (int nj = 0; nj < 4; nj++)
                    mma_tf32(c[mi][nj], a[mi], b[nj]);
        }
        __syncthreads();
    }

    // epilogue
#pragma unroll
    for (int mi = 0; mi < 4; mi++) {
#pragma unroll
        for (int rs = 0; rs < 2; rs++) {
            int rloc = m0 + mi * 16 + gq + rs * 8;
            int grow = tile_r + rloc;
            float gt = 0.f;
            int tok = 0;
            if (SECOND) { gt = g_gate[grow]; tok = g_token[grow]; }
#pragma unroll
            for (int nj = 0; nj < 4; nj++) {
                int gcol = tile_c + n0 + nj * 8 + tq * 2;
                float v0 = c[mi][nj][rs * 2 + 0] + bias[e * NW + gcol];
                float v1 = c[mi][nj][rs * 2 + 1] + bias[e * NW + gcol + 1];
                if (!SECOND) {
                    g_h[(size_t)grow * NW + gcol]     = gelu_exact(v0);
                    g_h[(size_t)grow * NW + gcol + 1] = gelu_exact(v1);
                } else {
                    atomicAdd(&Cout[(size_t)tok * NW + gcol],     v0 * gt);
                    atomicAdd(&Cout[(size_t)tok * NW + gcol + 1], v1 * gt);
                }
            }
        }
    }
}

// ---------------- launch ----------------
extern "C" void kernel_launch(void* const* d_in, const int* in_sizes, int n_in,
                              void* d_out, int out_size) {
    const float* x      = (const float*)d_in[0];
    const int*   band   = (const int*)d_in[1];
    const float* w_gate = (const float*)d_in[2];
    const float* W1     = (const float*)d_in[3];
    const float* b1     = (const float*)d_in[4];
    const float* W2     = (const float*)d_in[5];
    const float* b2     = (const float*)d_in[6];
    const float* A1     = (const float*)d_in[7];
    const float* B1     = (const float*)d_in[8];
    const float* A2     = (const float*)d_in[9];
    const float* B2     = (const float*)d_in[10];
    float* y = (float*)d_out;

    k_init<<<16384, 256>>>(y);                                   // zero y + state
    k_gate<<<2048, 256>>>(x, w_gate);                            // logits + top2
    k_offsets<<<1, 256>>>(y, out_size);                          // offsets + loss
    k_scatter<<<128, 256>>>(band);                               // build dispatch
    k_lora1<<<4224, 256>>>(x, A1);                               // t1ext
    k_gemm<DIM, HID, false><<<dim3(32, 264), 256>>>(x, W1, B1, b1, y);   // h = gelu(...)
    k_lora2<<<4224, 256>>>(A2);                                  // t2ext
    k_gemm<HID, NOUT, true><<<dim3(8, 264), 256>>>(x, W2, B2, b2, y);    // y += gate*(...)
}

// round 8
// speedup vs baseline: 1.0172x; 1.0172x over previous
#include <cuda_runtime.h>
#include <cuda_bf16.h>
#include <math.h>
#include <stdint.h>

// ---------------- problem constants ----------------
#define NTOK 16384
#define DIM  1024
#define HID  4096
#define NOUT 1024
#define NEXP 8
#define NB   4
#define RLO  16
#define PMAX 34816            // 136*256: 2*NTOK + 8*256 worst-case expert padding (256-aligned!)

// ---------------- device scratch (static: no allocs allowed) ----------------
__device__ float g_h  [(size_t)PMAX * HID];            // post-gelu hidden (rna-rounded fp32)
__device__ float g_xr [(size_t)NTOK * DIM];            // rna-rounded x
__device__ float g_w1r[(size_t)NEXP * DIM * HID];      // rna(W1) [E][D][H]
__device__ float g_b1r[(size_t)NEXP * 64 * HID];       // rna(B1) [E][64][H]
__device__ float g_w2r[(size_t)NEXP * HID * NOUT];     // rna(W2) [E][H][O]
__device__ float g_b2r[(size_t)NEXP * 64 * NOUT];      // rna(B2) [E][64][O]
__device__ float g_t1 [(size_t)PMAX * 64];
__device__ float g_t2 [(size_t)PMAX * 64];
__device__ int   g_token[PMAX];
__device__ int   g_band[PMAX];
__device__ int   g_expert[PMAX];
__device__ float g_gate[PMAX];
__device__ int   g_top2_idx[NTOK * 2];
__device__ float g_top2_gate[NTOK * 2];
__device__ int   g_cnt_eb[NEXP * NB];
__device__ int   g_cur_eb[NEXP * NB];
__device__ int   g_pob[NEXP * NB];
__device__ int   g_total;

// ---------------- helpers ----------------
__device__ __forceinline__ void cp16(const void* smem, const void* gmem) {
    uint32_t s = (uint32_t)__cvta_generic_to_shared(smem);
    asm volatile("cp.async.cg.shared.global [%0], [%1], 16;" :: "r"(s), "l"(gmem));
}
__device__ __forceinline__ void cp_commit() { asm volatile("cp.async.commit_group;" ::: "memory"); }
template <int n> __device__ __forceinline__ void cp_wait() {
    asm volatile("cp.async.wait_group %0;" :: "n"(n) : "memory");
}
__device__ __forceinline__ uint32_t f2tf32(float f) {
    uint32_t r; asm("cvt.rna.tf32.f32 %0, %1;" : "=r"(r) : "f"(f)); return r;
}
__device__ __forceinline__ float rnaf(float v) { return __uint_as_float(f2tf32(v)); }
__device__ __forceinline__ void mma_tf32(float* c, const uint32_t* a, const uint32_t* b) {
    asm volatile(
        "mma.sync.aligned.m16n8k8.row.col.f32.tf32.tf32.f32 "
        "{%0,%1,%2,%3}, {%4,%5,%6,%7}, {%8,%9}, {%0,%1,%2,%3};"
        : "+f"(c[0]), "+f"(c[1]), "+f"(c[2]), "+f"(c[3])
        : "r"(a[0]), "r"(a[1]), "r"(a[2]), "r"(a[3]), "r"(b[0]), "r"(b[1]));
}
__device__ __forceinline__ float gelu_exact(float x) {
    return 0.5f * x * (1.0f + erff(x * 0.70710678118654752440f));
}

// ---------------- 1. init ----------------
__global__ void k_init(float* __restrict__ y) {
    size_t i = (size_t)blockIdx.x * 256 + threadIdx.x;
    reinterpret_cast<float4*>(y)[i] = make_float4(0.f, 0.f, 0.f, 0.f);
    if (i < PMAX) { g_token[i] = 0; g_band[i] = 0; g_expert[i] = 0; g_gate[i] = 0.f; }
    if (i < NEXP * NB) { g_cnt_eb[i] = 0; g_cur_eb[i] = 0; }
}

// ---------------- 1b. rna-rounded copies ----------------
__global__ void k_xr(const float* __restrict__ x) {
    size_t i = (size_t)blockIdx.x * 256 + threadIdx.x;
    float4 v = reinterpret_cast<const float4*>(x)[i];
    v.x = rnaf(v.x); v.y = rnaf(v.y); v.z = rnaf(v.z); v.w = rnaf(v.w);
    reinterpret_cast<float4*>(g_xr)[i] = v;
}
__global__ void k_rnacopy(float* __restrict__ dst, const float* __restrict__ src) {
    size_t i = (size_t)blockIdx.x * 256 + threadIdx.x;
    float4 v = reinterpret_cast<const float4*>(src)[i];
    v.x = rnaf(v.x); v.y = rnaf(v.y); v.z = rnaf(v.z); v.w = rnaf(v.w);
    reinterpret_cast<float4*>(dst)[i] = v;
}

// ---------------- 2. gating ----------------
__global__ void k_gate(const float* __restrict__ x, const float* __restrict__ wg,
                       const int* __restrict__ band) {
    int gtid = blockIdx.x * blockDim.x + threadIdx.x;
    int tok  = gtid >> 5;
    int lane = threadIdx.x & 31;
    if (tok >= NTOK) return;
    const float* xr = x + (size_t)tok * DIM;
    float acc[NEXP];
#pragma unroll
    for (int e = 0; e < NEXP; e++) acc[e] = 0.f;
    for (int d = lane; d < DIM; d += 32) {
        float xv = xr[d];
        const float4* w4 = reinterpret_cast<const float4*>(wg + (size_t)d * NEXP);
        float4 wa = w4[0], wb = w4[1];
        acc[0] += xv * wa.x; acc[1] += xv * wa.y; acc[2] += xv * wa.z; acc[3] += xv * wa.w;
        acc[4] += xv * wb.x; acc[5] += xv * wb.y; acc[6] += xv * wb.z; acc[7] += xv * wb.w;
    }
#pragma unroll
    for (int e = 0; e < NEXP; e++)
#pragma unroll
        for (int off = 16; off; off >>= 1)
            acc[e] += __shfl_xor_sync(0xffffffffu, acc[e], off);
    int i0 = 0; float v0 = acc[0];
#pragma unroll
    for (int e = 1; e < NEXP; e++) if (acc[e] > v0) { v0 = acc[e]; i0 = e; }
    int i1 = -1; float v1 = -3.4e38f;
#pragma unroll
    for (int e = 0; e < NEXP; e++) if (e != i0 && acc[e] > v1) { v1 = acc[e]; i1 = e; }
    float ex = expf(v1 - v0);
    float den = 1.f + ex;
    if (lane == 0) {
        int b = band[tok];
        g_top2_idx[tok * 2] = i0;  g_top2_idx[tok * 2 + 1] = i1;
        g_top2_gate[tok * 2] = 1.f / den;  g_top2_gate[tok * 2 + 1] = ex / den;
        atomicAdd(&g_cnt_eb[i0 * NB + b], 1);
        atomicAdd(&g_cnt_eb[i1 * NB + b], 1);
    }
}

// ---------------- 3. offsets + loss (1 block, deterministic) ----------------
__global__ void k_offsets(float* __restrict__ out, int out_size) {
    __shared__ float simp[256][NEXP];
    __shared__ float s_imp[NEXP];
    int tid = threadIdx.x;
    float local[NEXP];
#pragma unroll
    for (int e = 0; e < NEXP; e++) local[e] = 0.f;
    for (int i = tid; i < 2 * NTOK; i += 256) {
        int e = g_top2_idx[i];
        float gv = g_top2_gate[i];
#pragma unroll
        for (int q = 0; q < NEXP; q++) local[q] += (q == e) ? gv : 0.f;
    }
#pragma unroll
    for (int e = 0; e < NEXP; e++) simp[tid][e] = local[e];
    __syncthreads();
    if (tid < NEXP) {
        float s = 0.f;
        for (int i = 0; i < 256; i++) s += simp[i][tid];
        s_imp[tid] = s;
    }
    __syncthreads();
    if (tid == 0) {
        int p = 0; int cnt_e[NEXP];
        for (int e = 0; e < NEXP; e++) {
            int cum = 0;
            for (int b = 0; b < NB; b++) { g_pob[e * NB + b] = p + cum; cum += g_cnt_eb[e * NB + b]; }
            cnt_e[e] = cum;
            p += (cum + 255) & ~255;     // 256-pad: GEMM M-tile (256 rows) never straddles experts
        }
        g_total = p;
        float mi = 0.f, ml = 0.f;
        for (int e = 0; e < NEXP; e++) { mi += s_imp[e]; ml += (float)cnt_e[e]; }
        mi *= (1.f / NEXP); ml *= (1.f / NEXP);
        float vi = 0.f, vl = 0.f;
        for (int e = 0; e < NEXP; e++) {
            float di = s_imp[e] - mi;        vi += di * di;
            float dl = (float)cnt_e[e] - ml; vl += dl * dl;
        }
        vi *= (1.f / (NEXP - 1)); vl *= (1.f / (NEXP - 1));
        float loss = 0.01f * (vi / (mi * mi + 1e-10f) + vl / (ml * ml + 1e-10f));
        if (out_size > NTOK * NOUT) out[(size_t)NTOK * NOUT] = loss;
    }
}

// ---------------- 4. scatter (sorted by expert, band) ----------------
__global__ void k_scatter(const int* __restrict__ band) {
    int i = blockIdx.x * 256 + threadIdx.x;
    if (i >= 2 * NTOK) return;
    int t = i >> 1;
    int e = g_top2_idx[i];
    int b = band[t];
    int pos = g_pob[e * NB + b] + atomicAdd(&g_cur_eb[e * NB + b], 1);
    g_token[pos]  = t;
    g_gate[pos]   = g_top2_gate[i];
    g_band[pos]   = b;
    g_expert[pos] = e;
}

// ---------------- 5/7. lora down-projections ----------------
template <int KD, bool SECOND>
__global__ void k_lora(const float* __restrict__ xin, const float* __restrict__ A) {
    int row  = blockIdx.x * 8 + (threadIdx.x >> 5);
    int lane = threadIdx.x & 31;
    if (row >= g_total) return;
    int band = g_band[row], e = g_expert[row];
    const float* a = A + (size_t)(e * NB + band) * KD * RLO;
    const float* xr = SECOND ? (g_h + (size_t)row * KD) : (xin + (size_t)g_token[row] * KD);
    float acc[RLO];
#pragma unroll
    for (int r = 0; r < RLO; r++) acc[r] = 0.f;
    for (int d = lane; d < KD; d += 32) {
        float xv = xr[d];
        const float* ar = a + (size_t)d * RLO;
#pragma unroll
        for (int r = 0; r < RLO; r++) acc[r] += xv * ar[r];
    }
    float mine = 0.f;
#pragma unroll
    for (int r = 0; r < RLO; r++) {
        float s = acc[r];
#pragma unroll
        for (int off = 16; off; off >>= 1) s += __shfl_xor_sync(0xffffffffu, s, off);
        if (lane == r) mine = s;
    }
    float* dst = (SECOND ? g_t2 : g_t1) + (size_t)row * 64;
    for (int j = lane; j < 64; j += 32) dst[j] = 0.f;
    __syncwarp();
    if (lane < RLO) dst[band * RLO + lane] = rnaf(2.0f * mine);
}

// ---------------- 6/8. grouped GEMM: tf32 mma.sync, 256x128x32 tiles --------------
// All operands pre-rounded to tf32 -> NO cvt in the inner loop.
// !SECOND: g_h = rna(gelu(acc + b1));  SECOND: y[token] += gate*(acc + b2).
#define ASTR 36
#define BSTR 136
#define ABUF (256 * ASTR)
#define BBUF (32 * BSTR)
#define GEMM_SMEM ((2 * ABUF + 2 * BBUF) * 4 + 1024)

template <int KMAIN, int NWW, bool SECOND>
__global__ void __launch_bounds__(512, 1)
k_gemm(const float* __restrict__ Bmain, const float* __restrict__ Bext,
       const float* __restrict__ bias, float* __restrict__ y) {
    const int tile_r = blockIdx.y * 256;
    if (tile_r >= g_total) return;
    const int tile_c = blockIdx.x * 128;
    const int e = g_expert[tile_r];   // valid for all 256 rows: expert regions are 256-aligned

    extern __shared__ float sm[];
    float* Asm = sm;
    float* Bsm = sm + 2 * ABUF;
    int*   stok = (int*)(sm + 2 * ABUF + 2 * BBUF);

    const int tid  = threadIdx.x;
    const int wid  = tid >> 5;
    const int lane = tid & 31;
    const int gq   = lane >> 2;
    const int tq   = lane & 3;
    const int m0   = (wid & 3) * 64;
    const int n0   = (wid >> 2) * 32;

    if (!SECOND && tid < 256) stok[tid] = g_token[tile_r + tid];
    __syncthreads();

    const float* Bm = Bmain + (size_t)e * KMAIN * NWW + tile_c;
    const float* Be = Bext  + (size_t)e * 64 * NWW + tile_c;
    const float* Aext = (SECOND ? g_t2 : g_t1) + (size_t)tile_r * 64;

    auto load_stage = [&](int s, int buf) {
        const int k0 = s * 32;
        const bool mn = (k0 < KMAIN);
        float* Ab = Asm + buf * ABUF;
        float* Bb = Bsm + buf * BBUF;
#pragma unroll
        for (int i = 0; i < 4; i++) {
            int idx = tid + i * 512;
            int r = idx >> 3, c = (idx & 7) * 4;
            const float* src;
            if (mn) src = (SECOND ? (g_h + (size_t)(tile_r + r) * KMAIN)
                                  : (g_xr + (size_t)stok[r] * KMAIN)) + k0 + c;
            else    src = Aext + (size_t)r * 64 + (k0 - KMAIN) + c;
            cp16(Ab + r * ASTR + c, src);
        }
#pragma unroll
        for (int i = 0; i < 2; i++) {
            int idx = tid + i * 512;
            int k = idx >> 5, c = (idx & 31) * 4;
            const float* src = mn ? (Bm + (size_t)(k0 + k) * NWW + c)
                                  : (Be + (size_t)(k0 - KMAIN + k) * NWW + c);
            cp16(Bb + k * BSTR + c, src);
        }
        cp_commit();
    };

    float c[4][4][4];
#pragma unroll
    for (int mi = 0; mi < 4; mi++)
#pragma unroll
        for (int nj = 0; nj < 4; nj++)
#pragma unroll
            for (int q = 0; q < 4; q++) c[mi][nj][q] = 0.f;

    constexpr int NIT = (KMAIN + 64) / 32;
    load_stage(0, 0);

    for (int it = 0; it < NIT; ++it) {
        const int buf = it & 1;
        if (it + 1 < NIT) { load_stage(it + 1, buf ^ 1); cp_wait<1>(); }
        else              { cp_wait<0>(); }
        __syncthreads();

        const float* Ab = Asm + buf * ABUF;
        const float* Bb = Bsm + buf * BBUF;
#pragma unroll
        for (int kk = 0; kk < 4; kk++) {
            const int kb = kk * 8;
            uint32_t a[4][4], b[4][2];
#pragma unroll
            for (int mi = 0; mi < 4; mi++) {
                int r = m0 + mi * 16 + gq;
                a[mi][0] = __float_as_uint(Ab[r * ASTR + kb + tq]);
                a[mi][1] = __float_as_uint(Ab[(r + 8) * ASTR + kb + tq]);
                a[mi][2] = __float_as_uint(Ab[r * ASTR + kb + tq + 4]);
                a[mi][3] = __float_as_uint(Ab[(r + 8) * ASTR + kb + tq + 4]);
            }
#pragma unroll
            for (int nj = 0; nj < 4; nj++) {
                int cb = n0 + nj * 8 + gq;
                b[nj][0] = __float_as_uint(Bb[(kb + tq) * BSTR + cb]);
                b[nj][1] = __float_as_uint(Bb[(kb + tq + 4) * BSTR + cb]);
            }
#pragma unroll
            for (int mi = 0; mi < 4; mi++)
#pragma unroll
                for (int nj = 0; nj < 4; nj++)
                    mma_tf32(c[mi][nj], a[mi], b[nj]);
        }
        __syncthreads();
    }

#pragma unroll
    for (int mi = 0; mi < 4; mi++) {
#pragma unroll
        for (int rs = 0; rs < 2; rs++) {
            int rloc = m0 + mi * 16 + gq + rs * 8;
            int grow = tile_r + rloc;
            float gt = 0.f; int tok = 0;
            if (SECOND) { gt = g_gate[grow]; tok = g_token[grow]; }
#pragma unroll
            for (int nj = 0; nj < 4; nj++) {
                int gcol = tile_c + n0 + nj * 8 + tq * 2;
                float v0 = c[mi][nj][rs * 2 + 0] + bias[e * NWW + gcol];
                float v1 = c[mi][nj][rs * 2 + 1] + bias[e * NWW + gcol + 1];
                if (!SECOND) {
                    g_h[(size_t)grow * NWW + gcol]     = rnaf(gelu_exact(v0));
                    g_h[(size_t)grow * NWW + gcol + 1] = rnaf(gelu_exact(v1));
                } else {
                    atomicAdd(&y[(size_t)tok * NWW + gcol],     v0 * gt);
                    atomicAdd(&y[(size_t)tok * NWW + gcol + 1], v1 * gt);
                }
            }
        }
    }
}

// ---------------- launch ----------------
extern "C" void kernel_launch(void* const* d_in, const int* in_sizes, int n_in,
                              void* d_out, int out_size) {
    const float* x      = (const float*)d_in[0];
    const int*   band   = (const int*)d_in[1];
    const float* w_gate = (const float*)d_in[2];
    const float* W1     = (const float*)d_in[3];
    const float* b1     = (const float*)d_in[4];
    const float* W2     = (const float*)d_in[5];
    const float* b2     = (const float*)d_in[6];
    const float* A1     = (const float*)d_in[7];
    const float* B1     = (const float*)d_in[8];
    const float* A2     = (const float*)d_in[9];
    const float* B2     = (const float*)d_in[10];
    float* y = (float*)d_out;

    float *w1r, *b1r, *w2r, *b2r;
    cudaGetSymbolAddress((void**)&w1r, g_w1r);
    cudaGetSymbolAddress((void**)&b1r, g_b1r);
    cudaGetSymbolAddress((void**)&w2r, g_w2r);
    cudaGetSymbolAddress((void**)&b2r, g_b2r);
    cudaFuncSetAttribute(k_gemm<DIM, HID, false>,
                         cudaFuncAttributeMaxDynamicSharedMemorySize, GEMM_SMEM);
    cudaFuncSetAttribute(k_gemm<HID, NOUT, true>,
                         cudaFuncAttributeMaxDynamicSharedMemorySize, GEMM_SMEM);

    k_init<<<16384, 256>>>(y);
    k_xr<<<16384, 256>>>(x);
    k_rnacopy<<<NEXP * DIM * HID / 1024, 256>>>(w1r, W1);
    k_rnacopy<<<NEXP * 64 * HID / 1024, 256>>>(b1r, B1);
    k_rnacopy<<<NEXP * HID * NOUT / 1024, 256>>>(w2r, W2);
    k_rnacopy<<<NEXP * 64 * NOUT / 1024, 256>>>(b2r, B2);
    k_gate<<<2048, 256>>>(x, w_gate, band);
    k_offsets<<<1, 256>>>(y, out_size);
    k_scatter<<<128, 256>>>(band);
    k_lora<DIM, false><<<PMAX / 8, 256>>>(x, A1);
    k_gemm<DIM, HID, false><<<dim3(HID / 128, PMAX / 256), 512, GEMM_SMEM>>>(w1r, b1r, b1, y);
    k_lora<HID, true><<<PMAX / 8, 256>>>(nullptr, A2);
    k_gemm<HID, NOUT, true><<<dim3(NOUT / 128, PMAX / 256), 512, GEMM_SMEM>>>(w2r, b2r, b2, y);
}

// round 9
// speedup vs baseline: 2.0654x; 2.0304x over previous
#include <cuda_runtime.h>
#include <cuda_bf16.h>
#include <math.h>
#include <stdint.h>

// ---------------- problem constants ----------------
#define NTOK 16384
#define DIM  1024
#define HID  4096
#define NOUT 1024
#define NEXP 8
#define NB   4
#define RLO  16
#define PMAX 34816            // 136*256: 2*NTOK + 8*256 worst-case expert padding (256-aligned)

// ---------------- device scratch (static: no allocs allowed) ----------------
__device__ float g_h  [(size_t)PMAX * HID];            // post-gelu hidden (rna-rounded fp32)
__device__ float g_xr [(size_t)NTOK * DIM];            // rna-rounded x
__device__ float g_w1r[(size_t)NEXP * DIM * HID];      // rna(W1) [E][D][H]
__device__ float g_b1r[(size_t)NEXP * 64 * HID];       // rna(B1) [E][64][H]
__device__ float g_w2r[(size_t)NEXP * HID * NOUT];     // rna(W2) [E][H][O]
__device__ float g_b2r[(size_t)NEXP * 64 * NOUT];      // rna(B2) [E][64][O]
__device__ float g_a1x[(size_t)NEXP * DIM * 64];       // rna(A1) packed [E][D][b*16+r]
__device__ float g_a2x[(size_t)NEXP * HID * 64];       // rna(A2) packed [E][H][b*16+r]
__device__ float g_t1 [(size_t)PMAX * 64];
__device__ float g_t2 [(size_t)PMAX * 64];
__device__ int   g_token[PMAX];
__device__ int   g_band[PMAX];
__device__ int   g_expert[PMAX];
__device__ float g_gate[PMAX];
__device__ int   g_top2_idx[NTOK * 2];
__device__ float g_top2_gate[NTOK * 2];
__device__ int   g_cnt_eb[NEXP * NB];
__device__ int   g_cur_eb[NEXP * NB];
__device__ int   g_total;

// ---------------- helpers ----------------
__device__ __forceinline__ void cp16(const void* smem, const void* gmem) {
    uint32_t s = (uint32_t)__cvta_generic_to_shared(smem);
    asm volatile("cp.async.cg.shared.global [%0], [%1], 16;" :: "r"(s), "l"(gmem));
}
__device__ __forceinline__ void cp_commit() { asm volatile("cp.async.commit_group;" ::: "memory"); }
template <int n> __device__ __forceinline__ void cp_wait() {
    asm volatile("cp.async.wait_group %0;" :: "n"(n) : "memory");
}
__device__ __forceinline__ uint32_t f2tf32(float f) {
    uint32_t r; asm("cvt.rna.tf32.f32 %0, %1;" : "=r"(r) : "f"(f)); return r;
}
__device__ __forceinline__ float rnaf(float v) { return __uint_as_float(f2tf32(v)); }
__device__ __forceinline__ void mma_tf32(float* c, const uint32_t* a, const uint32_t* b) {
    asm volatile(
        "mma.sync.aligned.m16n8k8.row.col.f32.tf32.tf32.f32 "
        "{%0,%1,%2,%3}, {%4,%5,%6,%7}, {%8,%9}, {%0,%1,%2,%3};"
        : "+f"(c[0]), "+f"(c[1]), "+f"(c[2]), "+f"(c[3])
        : "r"(a[0]), "r"(a[1]), "r"(a[2]), "r"(a[3]), "r"(b[0]), "r"(b[1]));
}
__device__ __forceinline__ float gelu_exact(float x) {
    return 0.5f * x * (1.0f + erff(x * 0.70710678118654752440f));
}

// ---------------- 1. init: zero y, rounded x, dispatch state ----------------
__global__ void k_init(float* __restrict__ y, const float* __restrict__ x) {
    size_t i = (size_t)blockIdx.x * 256 + threadIdx.x;      // 16384*256 = NTOK*NOUT/4 exactly
    reinterpret_cast<float4*>(y)[i] = make_float4(0.f, 0.f, 0.f, 0.f);
    float4 v = reinterpret_cast<const float4*>(x)[i];       // x is same element count as y
    v.x = rnaf(v.x); v.y = rnaf(v.y); v.z = rnaf(v.z); v.w = rnaf(v.w);
    reinterpret_cast<float4*>(g_xr)[i] = v;
    if (i < PMAX) { g_token[i] = 0; g_band[i] = 0; g_expert[i] = 0; g_gate[i] = 0.f; }
    if (i < NEXP * NB) { g_cnt_eb[i] = 0; g_cur_eb[i] = 0; }
}

// ---------------- 2. prep: all rna weight copies + A packs in ONE kernel ----------
#define P_T0 8388608ull                      // W1 float4
#define P_T1 (P_T0 + 8388608ull)             // W2 float4
#define P_T2 (P_T1 + 524288ull)              // B1 float4
#define P_T3 (P_T2 + 131072ull)              // B2 float4
#define P_T4 (P_T3 + 524288ull)              // A1 scalar pack
#define P_T5 (P_T4 + 2097152ull)             // A2 scalar pack
#define P_BLOCKS 78336                        // P_T5 / 256

__global__ void k_prep(const float* __restrict__ W1, const float* __restrict__ B1,
                       const float* __restrict__ W2, const float* __restrict__ B2,
                       const float* __restrict__ A1, const float* __restrict__ A2) {
    size_t i = (size_t)blockIdx.x * 256 + threadIdx.x;
    if (i < P_T0) {
        float4 v = reinterpret_cast<const float4*>(W1)[i];
        v.x = rnaf(v.x); v.y = rnaf(v.y); v.z = rnaf(v.z); v.w = rnaf(v.w);
        reinterpret_cast<float4*>(g_w1r)[i] = v;
    } else if (i < P_T1) {
        size_t j = i - P_T0;
        float4 v = reinterpret_cast<const float4*>(W2)[j];
        v.x = rnaf(v.x); v.y = rnaf(v.y); v.z = rnaf(v.z); v.w = rnaf(v.w);
        reinterpret_cast<float4*>(g_w2r)[j] = v;
    } else if (i < P_T2) {
        size_t j = i - P_T1;
        float4 v = reinterpret_cast<const float4*>(B1)[j];
        v.x = rnaf(v.x); v.y = rnaf(v.y); v.z = rnaf(v.z); v.w = rnaf(v.w);
        reinterpret_cast<float4*>(g_b1r)[j] = v;
    } else if (i < P_T3) {
        size_t j = i - P_T2;
        float4 v = reinterpret_cast<const float4*>(B2)[j];
        v.x = rnaf(v.x); v.y = rnaf(v.y); v.z = rnaf(v.z); v.w = rnaf(v.w);
        reinterpret_cast<float4*>(g_b2r)[j] = v;
    } else if (i < P_T4) {
        size_t j = i - P_T3;                 // A1 [E][NB][D][R] -> [E][D][b*16+r]
        int r = (int)(j & 15);
        int d = (int)((j >> 4) & 1023);
        int b = (int)((j >> 14) & 3);
        int e = (int)(j >> 16);
        g_a1x[((size_t)e * DIM + d) * 64 + b * 16 + r] = rnaf(A1[j]);
    } else if (i < P_T5) {
        size_t j = i - P_T4;                 // A2 [E][NB][H][R] -> [E][H][b*16+r]
        int r = (int)(j & 15);
        int d = (int)((j >> 4) & 4095);
        int b = (int)((j >> 16) & 3);
        int e = (int)(j >> 18);
        g_a2x[((size_t)e * HID + d) * 64 + b * 16 + r] = rnaf(A2[j]);
    }
}

// ---------------- 3. gating ----------------
__global__ void k_gate(const float* __restrict__ x, const float* __restrict__ wg,
                       const int* __restrict__ band) {
    int gtid = blockIdx.x * blockDim.x + threadIdx.x;
    int tok  = gtid >> 5;
    int lane = threadIdx.x & 31;
    if (tok >= NTOK) return;
    const float* xr = x + (size_t)tok * DIM;
    float acc[NEXP];
#pragma unroll
    for (int e = 0; e < NEXP; e++) acc[e] = 0.f;
    for (int d = lane; d < DIM; d += 32) {
        float xv = xr[d];
        const float4* w4 = reinterpret_cast<const float4*>(wg + (size_t)d * NEXP);
        float4 wa = w4[0], wb = w4[1];
        acc[0] += xv * wa.x; acc[1] += xv * wa.y; acc[2] += xv * wa.z; acc[3] += xv * wa.w;
        acc[4] += xv * wb.x; acc[5] += xv * wb.y; acc[6] += xv * wb.z; acc[7] += xv * wb.w;
    }
#pragma unroll
    for (int e = 0; e < NEXP; e++)
#pragma unroll
        for (int off = 16; off; off >>= 1)
            acc[e] += __shfl_xor_sync(0xffffffffu, acc[e], off);
    int i0 = 0; float v0 = acc[0];
#pragma unroll
    for (int e = 1; e < NEXP; e++) if (acc[e] > v0) { v0 = acc[e]; i0 = e; }
    int i1 = -1; float v1 = -3.4e38f;
#pragma unroll
    for (int e = 0; e < NEXP; e++) if (e != i0 && acc[e] > v1) { v1 = acc[e]; i1 = e; }
    float ex = expf(v1 - v0);
    float den = 1.f + ex;
    if (lane == 0) {
        int b = band[tok];
        g_top2_idx[tok * 2] = i0;  g_top2_idx[tok * 2 + 1] = i1;
        g_top2_gate[tok * 2] = 1.f / den;  g_top2_gate[tok * 2 + 1] = ex / den;
        atomicAdd(&g_cnt_eb[i0 * NB + b], 1);
        atomicAdd(&g_cnt_eb[i1 * NB + b], 1);
    }
}

// ---------------- 4. scatter: each thread derives the 32-entry offset prefix ------
__global__ void k_scatter(const int* __restrict__ band) {
    int i = blockIdx.x * 256 + threadIdx.x;
    if (i >= 2 * NTOK) return;
    int pob[NEXP * NB];
    int p = 0;
#pragma unroll
    for (int e = 0; e < NEXP; e++) {
        int cum = 0;
#pragma unroll
        for (int b = 0; b < NB; b++) {
            pob[e * NB + b] = p + cum;
            cum += __ldg(&g_cnt_eb[e * NB + b]);
        }
        p += (cum + 255) & ~255;             // 256-pad: expert regions 256-aligned
    }
    if (i == 0) g_total = p;
    int t = i >> 1;
    int e = g_top2_idx[i];
    int b = band[t];
    int pos = pob[e * NB + b] + atomicAdd(&g_cur_eb[e * NB + b], 1);
    g_token[pos]  = t;
    g_gate[pos]   = g_top2_gate[i];
    g_band[pos]   = b;
    g_expert[pos] = e;
}

// ---------------- 5/7. lora down-proj as tensor mma: t = mask_band(2 * A @ Apk[e]) ----
// Tile 128 rows x 64 cols, K staged 32. Rows sorted/256-aligned per expert.
#define L_ASTR 36
#define L_BSTR 72
#define L_ABUF (128 * L_ASTR)
#define L_BBUF (32 * L_BSTR)
#define LMMA_SMEM ((2 * L_ABUF + 2 * L_BBUF) * 4 + 2048)

template <int KD, bool SECOND>
__global__ void __launch_bounds__(256, 2)
k_lmma() {
    const int tile_r = blockIdx.x * 128;
    if (tile_r >= g_total) return;
    const int e = g_expert[tile_r];

    extern __shared__ float sm[];
    float* Asm = sm;
    float* Bsm = sm + 2 * L_ABUF;
    int*   stok  = (int*)(sm + 2 * L_ABUF + 2 * L_BBUF);
    int*   sband = stok + 128;

    const int tid  = threadIdx.x;
    const int wid  = tid >> 5;
    const int lane = tid & 31;
    const int gq   = lane >> 2;
    const int tq   = lane & 3;
    const int m0   = (wid & 3) * 32;
    const int n0   = (wid >> 2) * 32;

    if (tid < 128) {
        stok[tid]  = SECOND ? (tile_r + tid) : g_token[tile_r + tid];
        sband[tid] = g_band[tile_r + tid];
    }
    __syncthreads();

    const float* Bp = (SECOND ? g_a2x : g_a1x) + (size_t)e * KD * 64;

    auto load_stage = [&](int s, int buf) {
        const int k0 = s * 32;
        float* Ab = Asm + buf * L_ABUF;
        float* Bb = Bsm + buf * L_BBUF;
#pragma unroll
        for (int i2 = 0; i2 < 4; i2++) {       // A: 128x32 = 1024 float4
            int idx = tid + i2 * 256;
            int r = idx >> 3, c = (idx & 7) * 4;
            const float* src = (SECOND ? (g_h + (size_t)(tile_r + r) * KD)
                                       : (g_xr + (size_t)stok[r] * KD)) + k0 + c;
            cp16(Ab + r * L_ASTR + c, src);
        }
#pragma unroll
        for (int i2 = 0; i2 < 2; i2++) {       // B: 32x64 = 512 float4
            int idx = tid + i2 * 256;
            int k = idx >> 4, c = (idx & 15) * 4;
            cp16(Bb + k * L_BSTR + c, Bp + (size_t)(k0 + k) * 64 + c);
        }
        cp_commit();
    };

    float c[2][4][4];
#pragma unroll
    for (int mi = 0; mi < 2; mi++)
#pragma unroll
        for (int nj = 0; nj < 4; nj++)
#pragma unroll
            for (int q = 0; q < 4; q++) c[mi][nj][q] = 0.f;

    constexpr int NIT = KD / 32;
    load_stage(0, 0);
    for (int it = 0; it < NIT; ++it) {
        const int buf = it & 1;
        if (it + 1 < NIT) { load_stage(it + 1, buf ^ 1); cp_wait<1>(); }
        else              { cp_wait<0>(); }
        __syncthreads();
        const float* Ab = Asm + buf * L_ABUF;
        const float* Bb = Bsm + buf * L_BBUF;
#pragma unroll
        for (int kk = 0; kk < 4; kk++) {
            const int kb = kk * 8;
            uint32_t a[2][4], b[4][2];
#pragma unroll
            for (int mi = 0; mi < 2; mi++) {
                int r = m0 + mi * 16 + gq;
                a[mi][0] = __float_as_uint(Ab[r * L_ASTR + kb + tq]);
                a[mi][1] = __float_as_uint(Ab[(r + 8) * L_ASTR + kb + tq]);
                a[mi][2] = __float_as_uint(Ab[r * L_ASTR + kb + tq + 4]);
                a[mi][3] = __float_as_uint(Ab[(r + 8) * L_ASTR + kb + tq + 4]);
            }
#pragma unroll
            for (int nj = 0; nj < 4; nj++) {
                int cb = n0 + nj * 8 + gq;
                b[nj][0] = __float_as_uint(Bb[(kb + tq) * L_BSTR + cb]);
                b[nj][1] = __float_as_uint(Bb[(kb + tq + 4) * L_BSTR + cb]);
            }
#pragma unroll
            for (int mi = 0; mi < 2; mi++)
#pragma unroll
                for (int nj = 0; nj < 4; nj++)
                    mma_tf32(c[mi][nj], a[mi], b[nj]);
        }
        __syncthreads();
    }

    float* T = (SECOND ? g_t2 : g_t1);
#pragma unroll
    for (int mi = 0; mi < 2; mi++) {
#pragma unroll
        for (int rs = 0; rs < 2; rs++) {
            int rloc = m0 + mi * 16 + gq + rs * 8;
            int bd = sband[rloc];
            float* trow = T + (size_t)(tile_r + rloc) * 64;
#pragma unroll
            for (int nj = 0; nj < 4; nj++) {
                int gcol = n0 + nj * 8 + tq * 2;
                bool in0 = ((gcol >> 4) == bd);
                float v0 = in0 ? rnaf(2.0f * c[mi][nj][rs * 2 + 0]) : 0.f;
                float v1 = in0 ? rnaf(2.0f * c[mi][nj][rs * 2 + 1]) : 0.f;
                trow[gcol]     = v0;
                trow[gcol + 1] = v1;
            }
        }
    }
}

// ---------------- 6/8. grouped GEMM: tf32 mma.sync, 256x128x32 tiles --------------
#define ASTR 36
#define BSTR 136
#define ABUF (256 * ASTR)
#define BBUF (32 * BSTR)
#define GEMM_SMEM ((2 * ABUF + 2 * BBUF) * 4 + 1024)

template <int KMAIN, int NWW, bool SECOND>
__global__ void __launch_bounds__(512, 1)
k_gemm(const float* __restrict__ Bmain, const float* __restrict__ Bext,
       const float* __restrict__ bias, float* __restrict__ y) {
    const int tile_r = blockIdx.y * 256;
    if (tile_r >= g_total) return;
    const int tile_c = blockIdx.x * 128;
    const int e = g_expert[tile_r];

    extern __shared__ float sm[];
    float* Asm = sm;
    float* Bsm = sm + 2 * ABUF;
    int*   stok = (int*)(sm + 2 * ABUF + 2 * BBUF);

    const int tid  = threadIdx.x;
    const int wid  = tid >> 5;
    const int lane = tid & 31;
    const int gq   = lane >> 2;
    const int tq   = lane & 3;
    const int m0   = (wid & 3) * 64;
    const int n0   = (wid >> 2) * 32;

    if (!SECOND && tid < 256) stok[tid] = g_token[tile_r + tid];
    __syncthreads();

    const float* Bm = Bmain + (size_t)e * KMAIN * NWW + tile_c;
    const float* Be = Bext  + (size_t)e * 64 * NWW + tile_c;
    const float* Aext = (SECOND ? g_t2 : g_t1) + (size_t)tile_r * 64;

    auto load_stage = [&](int s, int buf) {
        const int k0 = s * 32;
        const bool mn = (k0 < KMAIN);
        float* Ab = Asm + buf * ABUF;
        float* Bb = Bsm + buf * BBUF;
#pragma unroll
        for (int i = 0; i < 4; i++) {
            int idx = tid + i * 512;
            int r = idx >> 3, c = (idx & 7) * 4;
            const float* src;
            if (mn) src = (SECOND ? (g_h + (size_t)(tile_r + r) * KMAIN)
                                  : (g_xr + (size_t)stok[r] * KMAIN)) + k0 + c;
            else    src = Aext + (size_t)r * 64 + (k0 - KMAIN) + c;
            cp16(Ab + r * ASTR + c, src);
        }
#pragma unroll
        for (int i = 0; i < 2; i++) {
            int idx = tid + i * 512;
            int k = idx >> 5, c = (idx & 31) * 4;
            const float* src = mn ? (Bm + (size_t)(k0 + k) * NWW + c)
                                  : (Be + (size_t)(k0 - KMAIN + k) * NWW + c);
            cp16(Bb + k * BSTR + c, src);
        }
        cp_commit();
    };

    float c[4][4][4];
#pragma unroll
    for (int mi = 0; mi < 4; mi++)
#pragma unroll
        for (int nj = 0; nj < 4; nj++)
#pragma unroll
            for (int q = 0; q < 4; q++) c[mi][nj][q] = 0.f;

    constexpr int NIT = (KMAIN + 64) / 32;
    load_stage(0, 0);

    for (int it = 0; it < NIT; ++it) {
        const int buf = it & 1;
        if (it + 1 < NIT) { load_stage(it + 1, buf ^ 1); cp_wait<1>(); }
        else              { cp_wait<0>(); }
        __syncthreads();

        const float* Ab = Asm + buf * ABUF;
        const float* Bb = Bsm + buf * BBUF;
#pragma unroll
        for (int kk = 0; kk < 4; kk++) {
            const int kb = kk * 8;
            uint32_t a[4][4], b[4][2];
#pragma unroll
            for (int mi = 0; mi < 4; mi++) {
                int r = m0 + mi * 16 + gq;
                a[mi][0] = __float_as_uint(Ab[r * ASTR + kb + tq]);
                a[mi][1] = __float_as_uint(Ab[(r + 8) * ASTR + kb + tq]);
                a[mi][2] = __float_as_uint(Ab[r * ASTR + kb + tq + 4]);
                a[mi][3] = __float_as_uint(Ab[(r + 8) * ASTR + kb + tq + 4]);
            }
#pragma unroll
            for (int nj = 0; nj < 4; nj++) {
                int cb = n0 + nj * 8 + gq;
                b[nj][0] = __float_as_uint(Bb[(kb + tq) * BSTR + cb]);
                b[nj][1] = __float_as_uint(Bb[(kb + tq + 4) * BSTR + cb]);
            }
#pragma unroll
            for (int mi = 0; mi < 4; mi++)
#pragma unroll
                for (int nj = 0; nj < 4; nj++)
                    mma_tf32(c[mi][nj], a[mi], b[nj]);
        }
        __syncthreads();
    }

#pragma unroll
    for (int mi = 0; mi < 4; mi++) {
#pragma unroll
        for (int rs = 0; rs < 2; rs++) {
            int rloc = m0 + mi * 16 + gq + rs * 8;
            int grow = tile_r + rloc;
            float gt = 0.f; int tok = 0;
            if (SECOND) { gt = g_gate[grow]; tok = g_token[grow]; }
#pragma unroll
            for (int nj = 0; nj < 4; nj++) {
                int gcol = tile_c + n0 + nj * 8 + tq * 2;
                float v0 = c[mi][nj][rs * 2 + 0] + bias[e * NWW + gcol];
                float v1 = c[mi][nj][rs * 2 + 1] + bias[e * NWW + gcol + 1];
                if (!SECOND) {
                    g_h[(size_t)grow * NWW + gcol]     = rnaf(gelu_exact(v0));
                    g_h[(size_t)grow * NWW + gcol + 1] = rnaf(gelu_exact(v1));
                } else {
                    atomicAdd(&y[(size_t)tok * NWW + gcol],     v0 * gt);
                    atomicAdd(&y[(size_t)tok * NWW + gcol + 1], v1 * gt);
                }
            }
        }
    }
}

// ---------------- 9. loss (runs last; independent of GEMMs) ----------------
__global__ void k_loss(float* __restrict__ out, int out_size) {
    __shared__ float simp[256][NEXP];
    __shared__ float s_imp[NEXP];
    int tid = threadIdx.x;
    float local[NEXP];
#pragma unroll
    for (int e = 0; e < NEXP; e++) local[e] = 0.f;
    for (int i = tid; i < 2 * NTOK; i += 256) {
        int e = g_top2_idx[i];
        float gv = g_top2_gate[i];
#pragma unroll
        for (int q = 0; q < NEXP; q++) local[q] += (q == e) ? gv : 0.f;
    }
#pragma unroll
    for (int e = 0; e < NEXP; e++) simp[tid][e] = local[e];
    __syncthreads();
    if (tid < NEXP) {
        float s = 0.f;
        for (int i = 0; i < 256; i++) s += simp[i][tid];
        s_imp[tid] = s;
    }
    __syncthreads();
    if (tid == 0) {
        int cnt_e[NEXP];
        for (int e = 0; e < NEXP; e++) {
            int cum = 0;
            for (int b = 0; b < NB; b++) cum += g_cnt_eb[e * NB + b];
            cnt_e[e] = cum;
        }
        float mi = 0.f, ml = 0.f;
        for (int e = 0; e < NEXP; e++) { mi += s_imp[e]; ml += (float)cnt_e[e]; }
        mi *= (1.f / NEXP); ml *= (1.f / NEXP);
        float vi = 0.f, vl = 0.f;
        for (int e = 0; e < NEXP; e++) {
            float di = s_imp[e] - mi;        vi += di * di;
            float dl = (float)cnt_e[e] - ml; vl += dl * dl;
        }
        vi *= (1.f / (NEXP - 1)); vl *= (1.f / (NEXP - 1));
        float loss = 0.01f * (vi / (mi * mi + 1e-10f) + vl / (ml * ml + 1e-10f));
        if (out_size > NTOK * NOUT) out[(size_t)NTOK * NOUT] = loss;
    }
}

// ---------------- launch ----------------
extern "C" void kernel_launch(void* const* d_in, const int* in_sizes, int n_in,
                              void* d_out, int out_size) {
    const float* x      = (const float*)d_in[0];
    const int*   band   = (const int*)d_in[1];
    const float* w_gate = (const float*)d_in[2];
    const float* W1     = (const float*)d_in[3];
    const float* b1     = (const float*)d_in[4];
    const float* W2     = (const float*)d_in[5];
    const float* b2     = (const float*)d_in[6];
    const float* A1     = (const float*)d_in[7];
    const float* B1     = (const float*)d_in[8];
    const float* A2     = (const float*)d_in[9];
    const float* B2     = (const float*)d_in[10];
    float* y = (float*)d_out;

    float *w1r, *b1r, *w2r, *b2r;
    cudaGetSymbolAddress((void**)&w1r, g_w1r);
    cudaGetSymbolAddress((void**)&b1r, g_b1r);
    cudaGetSymbolAddress((void**)&w2r, g_w2r);
    cudaGetSymbolAddress((void**)&b2r, g_b2r);
    cudaFuncSetAttribute(k_gemm<DIM, HID, false>,
                         cudaFuncAttributeMaxDynamicSharedMemorySize, GEMM_SMEM);
    cudaFuncSetAttribute(k_gemm<HID, NOUT, true>,
                         cudaFuncAttributeMaxDynamicSharedMemorySize, GEMM_SMEM);
    cudaFuncSetAttribute(k_lmma<DIM, false>,
                         cudaFuncAttributeMaxDynamicSharedMemorySize, LMMA_SMEM);
    cudaFuncSetAttribute(k_lmma<HID, true>,
                         cudaFuncAttributeMaxDynamicSharedMemorySize, LMMA_SMEM);

    k_init<<<16384, 256>>>(y, x);                                            // 1
    k_prep<<<P_BLOCKS, 256>>>(W1, B1, W2, B2, A1, A2);                       // 2
    k_gate<<<2048, 256>>>(x, w_gate, band);                                  // 3
    k_scatter<<<128, 256>>>(band);                                           // 4
    k_lmma<DIM, false><<<PMAX / 128, 256, LMMA_SMEM>>>();                    // 5
    k_gemm<DIM, HID, false><<<dim3(HID / 128, PMAX / 256), 512, GEMM_SMEM>>>(w1r, b1r, b1, y);   // 6 <- ncu
    k_lmma<HID, true><<<PMAX / 128, 256, LMMA_SMEM>>>();                     // 7
    k_gemm<HID, NOUT, true><<<dim3(NOUT / 128, PMAX / 256), 512, GEMM_SMEM>>>(w2r, b2r, b2, y);  // 8
    k_loss<<<1, 256>>>(y, out_size);                                         // 9
}

// round 10
// speedup vs baseline: 2.1995x; 1.0649x over previous
#include <cuda_runtime.h>
#include <cuda_bf16.h>
#include <math.h>
#include <stdint.h>

// ---------------- problem constants ----------------
#define NTOK 16384
#define DIM  1024
#define HID  4096
#define NOUT 1024
#define NEXP 8
#define NB   4
#define RLO  16
#define PMAX 34816            // 136*256: 2*NTOK + 8*256 worst-case expert padding (256-aligned)

// ---------------- device scratch (static: no allocs allowed) ----------------
__device__ float g_h  [(size_t)PMAX * HID];            // post-gelu hidden (rna-rounded fp32)
__device__ float g_xr [(size_t)NTOK * DIM];            // rna-rounded x
__device__ float g_w1r[(size_t)NEXP * DIM * HID];      // rna(W1) [E][D][H]
__device__ float g_b1r[(size_t)NEXP * 64 * HID];       // rna(B1) [E][64][H]
__device__ float g_w2r[(size_t)NEXP * HID * NOUT];     // rna(W2) [E][H][O]
__device__ float g_b2r[(size_t)NEXP * 64 * NOUT];      // rna(B2) [E][64][O]
__device__ float g_a1x[(size_t)NEXP * DIM * 64];       // rna(A1) packed [E][D][b*16+r]
__device__ float g_a2x[(size_t)NEXP * HID * 64];       // rna(A2) packed [E][H][b*16+r]
__device__ float g_t1 [(size_t)PMAX * 64];
__device__ float g_t2 [(size_t)PMAX * 64];
__device__ int   g_token[PMAX];
__device__ int   g_band[PMAX];
__device__ int   g_expert[PMAX];
__device__ float g_gate[PMAX];
__device__ int   g_top2_idx[NTOK * 2];
__device__ float g_top2_gate[NTOK * 2];
__device__ int   g_cnt_eb[NEXP * NB];
__device__ int   g_cur_eb[NEXP * NB];
__device__ int   g_total;

// ---------------- helpers ----------------
__device__ __forceinline__ void cp16(const void* smem, const void* gmem) {
    uint32_t s = (uint32_t)__cvta_generic_to_shared(smem);
    asm volatile("cp.async.cg.shared.global [%0], [%1], 16;" :: "r"(s), "l"(gmem));
}
__device__ __forceinline__ void cp_commit() { asm volatile("cp.async.commit_group;" ::: "memory"); }
template <int n> __device__ __forceinline__ void cp_wait() {
    asm volatile("cp.async.wait_group %0;" :: "n"(n) : "memory");
}
__device__ __forceinline__ uint32_t f2tf32(float f) {
    uint32_t r; asm("cvt.rna.tf32.f32 %0, %1;" : "=r"(r) : "f"(f)); return r;
}
__device__ __forceinline__ float rnaf(float v) { return __uint_as_float(f2tf32(v)); }
__device__ __forceinline__ void mma_tf32(float* c, const uint32_t* a, const uint32_t* b) {
    asm volatile(
        "mma.sync.aligned.m16n8k8.row.col.f32.tf32.tf32.f32 "
        "{%0,%1,%2,%3}, {%4,%5,%6,%7}, {%8,%9}, {%0,%1,%2,%3};"
        : "+f"(c[0]), "+f"(c[1]), "+f"(c[2]), "+f"(c[3])
        : "r"(a[0]), "r"(a[1]), "r"(a[2]), "r"(a[3]), "r"(b[0]), "r"(b[1]));
}
// b16 ldmatrix on b32 data: thread t gets b32 elem (row t/4, col t%4) of each 8x4 matrix
__device__ __forceinline__ void ldsm_x4(uint32_t* d, uint32_t addr) {
    asm volatile("ldmatrix.sync.aligned.m8n8.x4.shared.b16 {%0,%1,%2,%3}, [%4];"
                 : "=r"(d[0]), "=r"(d[1]), "=r"(d[2]), "=r"(d[3]) : "r"(addr));
}
__device__ __forceinline__ float gelu_exact(float x) {
    return 0.5f * x * (1.0f + erff(x * 0.70710678118654752440f));
}

// ---------------- 1. init: zero y, rounded x, dispatch state ----------------
__global__ void k_init(float* __restrict__ y, const float* __restrict__ x) {
    size_t i = (size_t)blockIdx.x * 256 + threadIdx.x;
    reinterpret_cast<float4*>(y)[i] = make_float4(0.f, 0.f, 0.f, 0.f);
    float4 v = reinterpret_cast<const float4*>(x)[i];
    v.x = rnaf(v.x); v.y = rnaf(v.y); v.z = rnaf(v.z); v.w = rnaf(v.w);
    reinterpret_cast<float4*>(g_xr)[i] = v;
    if (i < PMAX) { g_token[i] = 0; g_band[i] = 0; g_expert[i] = 0; g_gate[i] = 0.f; }
    if (i < NEXP * NB) { g_cnt_eb[i] = 0; g_cur_eb[i] = 0; }
}

// ---------------- 2. prep: all rna weight copies + A packs in ONE kernel ----------
#define P_T0 8388608ull
#define P_T1 (P_T0 + 8388608ull)
#define P_T2 (P_T1 + 524288ull)
#define P_T3 (P_T2 + 131072ull)
#define P_T4 (P_T3 + 524288ull)
#define P_T5 (P_T4 + 2097152ull)
#define P_BLOCKS 78336

__global__ void k_prep(const float* __restrict__ W1, const float* __restrict__ B1,
                       const float* __restrict__ W2, const float* __restrict__ B2,
                       const float* __restrict__ A1, const float* __restrict__ A2) {
    size_t i = (size_t)blockIdx.x * 256 + threadIdx.x;
    if (i < P_T0) {
        float4 v = reinterpret_cast<const float4*>(W1)[i];
        v.x = rnaf(v.x); v.y = rnaf(v.y); v.z = rnaf(v.z); v.w = rnaf(v.w);
        reinterpret_cast<float4*>(g_w1r)[i] = v;
    } else if (i < P_T1) {
        size_t j = i - P_T0;
        float4 v = reinterpret_cast<const float4*>(W2)[j];
        v.x = rnaf(v.x); v.y = rnaf(v.y); v.z = rnaf(v.z); v.w = rnaf(v.w);
        reinterpret_cast<float4*>(g_w2r)[j] = v;
    } else if (i < P_T2) {
        size_t j = i - P_T1;
        float4 v = reinterpret_cast<const float4*>(B1)[j];
        v.x = rnaf(v.x); v.y = rnaf(v.y); v.z = rnaf(v.z); v.w = rnaf(v.w);
        reinterpret_cast<float4*>(g_b1r)[j] = v;
    } else if (i < P_T3) {
        size_t j = i - P_T2;
        float4 v = reinterpret_cast<const float4*>(B2)[j];
        v.x = rnaf(v.x); v.y = rnaf(v.y); v.z = rnaf(v.z); v.w = rnaf(v.w);
        reinterpret_cast<float4*>(g_b2r)[j] = v;
    } else if (i < P_T4) {
        size_t j = i - P_T3;                 // A1 [E][NB][D][R] -> [E][D][b*16+r]
        int r = (int)(j & 15);
        int d = (int)((j >> 4) & 1023);
        int b = (int)((j >> 14) & 3);
        int e = (int)(j >> 16);
        g_a1x[((size_t)e * DIM + d) * 64 + b * 16 + r] = rnaf(A1[j]);
    } else if (i < P_T5) {
        size_t j = i - P_T4;                 // A2 [E][NB][H][R] -> [E][H][b*16+r]
        int r = (int)(j & 15);
        int d = (int)((j >> 4) & 4095);
        int b = (int)((j >> 16) & 3);
        int e = (int)(j >> 18);
        g_a2x[((size_t)e * HID + d) * 64 + b * 16 + r] = rnaf(A2[j]);
    }
}

// ---------------- 3. gating ----------------
__global__ void k_gate(const float* __restrict__ x, const float* __restrict__ wg,
                       const int* __restrict__ band) {
    int gtid = blockIdx.x * blockDim.x + threadIdx.x;
    int tok  = gtid >> 5;
    int lane = threadIdx.x & 31;
    if (tok >= NTOK) return;
    const float* xr = x + (size_t)tok * DIM;
    float acc[NEXP];
#pragma unroll
    for (int e = 0; e < NEXP; e++) acc[e] = 0.f;
    for (int d = lane; d < DIM; d += 32) {
        float xv = xr[d];
        const float4* w4 = reinterpret_cast<const float4*>(wg + (size_t)d * NEXP);
        float4 wa = w4[0], wb = w4[1];
        acc[0] += xv * wa.x; acc[1] += xv * wa.y; acc[2] += xv * wa.z; acc[3] += xv * wa.w;
        acc[4] += xv * wb.x; acc[5] += xv * wb.y; acc[6] += xv * wb.z; acc[7] += xv * wb.w;
    }
#pragma unroll
    for (int e = 0; e < NEXP; e++)
#pragma unroll
        for (int off = 16; off; off >>= 1)
            acc[e] += __shfl_xor_sync(0xffffffffu, acc[e], off);
    int i0 = 0; float v0 = acc[0];
#pragma unroll
    for (int e = 1; e < NEXP; e++) if (acc[e] > v0) { v0 = acc[e]; i0 = e; }
    int i1 = -1; float v1 = -3.4e38f;
#pragma unroll
    for (int e = 0; e < NEXP; e++) if (e != i0 && acc[e] > v1) { v1 = acc[e]; i1 = e; }
    float ex = expf(v1 - v0);
    float den = 1.f + ex;
    if (lane == 0) {
        int b = band[tok];
        g_top2_idx[tok * 2] = i0;  g_top2_idx[tok * 2 + 1] = i1;
        g_top2_gate[tok * 2] = 1.f / den;  g_top2_gate[tok * 2 + 1] = ex / den;
        atomicAdd(&g_cnt_eb[i0 * NB + b], 1);
        atomicAdd(&g_cnt_eb[i1 * NB + b], 1);
    }
}

// ---------------- 4. scatter: each thread derives the 32-entry offset prefix ------
__global__ void k_scatter(const int* __restrict__ band) {
    int i = blockIdx.x * 256 + threadIdx.x;
    if (i >= 2 * NTOK) return;
    int pob[NEXP * NB];
    int p = 0;
#pragma unroll
    for (int e = 0; e < NEXP; e++) {
        int cum = 0;
#pragma unroll
        for (int b = 0; b < NB; b++) {
            pob[e * NB + b] = p + cum;
            cum += __ldg(&g_cnt_eb[e * NB + b]);
        }
        p += (cum + 255) & ~255;             // 256-pad: expert regions 256-aligned
    }
    if (i == 0) g_total = p;
    int t = i >> 1;
    int e = g_top2_idx[i];
    int b = band[t];
    int pos = pob[e * NB + b] + atomicAdd(&g_cur_eb[e * NB + b], 1);
    g_token[pos]  = t;
    g_gate[pos]   = g_top2_gate[i];
    g_band[pos]   = b;
    g_expert[pos] = e;
}

// ---------------- 5/7. lora down-proj as tensor mma: t = mask_band(2 * A @ Apk[e]) ----
#define L_ASTR 36
#define L_BSTR 72
#define L_ABUF (128 * L_ASTR)
#define L_BBUF (32 * L_BSTR)
#define LMMA_SMEM ((2 * L_ABUF + 2 * L_BBUF) * 4 + 2048)

template <int KD, bool SECOND>
__global__ void __launch_bounds__(256, 2)
k_lmma() {
    const int tile_r = blockIdx.x * 128;
    if (tile_r >= g_total) return;
    const int e = g_expert[tile_r];

    extern __shared__ float sm[];
    float* Asm = sm;
    float* Bsm = sm + 2 * L_ABUF;
    int*   stok  = (int*)(sm + 2 * L_ABUF + 2 * L_BBUF);
    int*   sband = stok + 128;

    const int tid  = threadIdx.x;
    const int wid  = tid >> 5;
    const int lane = tid & 31;
    const int gq   = lane >> 2;
    const int tq   = lane & 3;
    const int m0   = (wid & 3) * 32;
    const int n0   = (wid >> 2) * 32;

    if (tid < 128) {
        stok[tid]  = SECOND ? (tile_r + tid) : g_token[tile_r + tid];
        sband[tid] = g_band[tile_r + tid];
    }
    __syncthreads();

    const float* Bp = (SECOND ? g_a2x : g_a1x) + (size_t)e * KD * 64;

    auto load_stage = [&](int s, int buf) {
        const int k0 = s * 32;
        float* Ab = Asm + buf * L_ABUF;
        float* Bb = Bsm + buf * L_BBUF;
#pragma unroll
        for (int i2 = 0; i2 < 4; i2++) {
            int idx = tid + i2 * 256;
            int r = idx >> 3, c = (idx & 7) * 4;
            const float* src = (SECOND ? (g_h + (size_t)(tile_r + r) * KD)
                                       : (g_xr + (size_t)stok[r] * KD)) + k0 + c;
            cp16(Ab + r * L_ASTR + c, src);
        }
#pragma unroll
        for (int i2 = 0; i2 < 2; i2++) {
            int idx = tid + i2 * 256;
            int k = idx >> 4, c = (idx & 15) * 4;
            cp16(Bb + k * L_BSTR + c, Bp + (size_t)(k0 + k) * 64 + c);
        }
        cp_commit();
    };

    float c[2][4][4];
#pragma unroll
    for (int mi = 0; mi < 2; mi++)
#pragma unroll
        for (int nj = 0; nj < 4; nj++)
#pragma unroll
            for (int q = 0; q < 4; q++) c[mi][nj][q] = 0.f;

    constexpr int NIT = KD / 32;
    load_stage(0, 0);
    for (int it = 0; it < NIT; ++it) {
        const int buf = it & 1;
        if (it + 1 < NIT) { load_stage(it + 1, buf ^ 1); cp_wait<1>(); }
        else              { cp_wait<0>(); }
        __syncthreads();
        const float* Ab = Asm + buf * L_ABUF;
        const float* Bb = Bsm + buf * L_BBUF;
#pragma unroll
        for (int kk = 0; kk < 4; kk++) {
            const int kb = kk * 8;
            uint32_t a[2][4], b[4][2];
#pragma unroll
            for (int mi = 0; mi < 2; mi++) {
                int r = m0 + mi * 16 + gq;
                a[mi][0] = __float_as_uint(Ab[r * L_ASTR + kb + tq]);
                a[mi][1] = __float_as_uint(Ab[(r + 8) * L_ASTR + kb + tq]);
                a[mi][2] = __float_as_uint(Ab[r * L_ASTR + kb + tq + 4]);
                a[mi][3] = __float_as_uint(Ab[(r + 8) * L_ASTR + kb + tq + 4]);
            }
#pragma unroll
            for (int nj = 0; nj < 4; nj++) {
                int cb = n0 + nj * 8 + gq;
                b[nj][0] = __float_as_uint(Bb[(kb + tq) * L_BSTR + cb]);
                b[nj][1] = __float_as_uint(Bb[(kb + tq + 4) * L_BSTR + cb]);
            }
#pragma unroll
            for (int mi = 0; mi < 2; mi++)
#pragma unroll
                for (int nj = 0; nj < 4; nj++)
                    mma_tf32(c[mi][nj], a[mi], b[nj]);
        }
        __syncthreads();
    }

    float* T = (SECOND ? g_t2 : g_t1);
#pragma unroll
    for (int mi = 0; mi < 2; mi++) {
#pragma unroll
        for (int rs = 0; rs < 2; rs++) {
            int rloc = m0 + mi * 16 + gq + rs * 8;
            int bd = sband[rloc];
            float* trow = T + (size_t)(tile_r + rloc) * 64;
#pragma unroll
            for (int nj = 0; nj < 4; nj++) {
                int gcol = n0 + nj * 8 + tq * 2;
                bool in0 = ((gcol >> 4) == bd);
                float v0 = in0 ? rnaf(2.0f * c[mi][nj][rs * 2 + 0]) : 0.f;
                float v1 = in0 ? rnaf(2.0f * c[mi][nj][rs * 2 + 1]) : 0.f;
                trow[gcol]     = v0;
                trow[gcol + 1] = v1;
            }
        }
    }
}

// ---------------- 6/8. grouped GEMM: tf32 mma.sync, 256x128x32 tiles --------------
// 4-buffer cp.async pipeline, ONE barrier per K-stage, A-frags via ldmatrix.x4.
#define ASTR 36
#define BSTR 136
#define ABUF (256 * ASTR)
#define BBUF (32 * BSTR)
#define NBUF 4
#define GEMM_SMEM ((NBUF * ABUF + NBUF * BBUF) * 4 + 1024)

template <int KMAIN, int NWW, bool SECOND>
__global__ void __launch_bounds__(512, 1)
k_gemm(const float* __restrict__ Bmain, const float* __restrict__ Bext,
       const float* __restrict__ bias, float* __restrict__ y) {
    const int tile_r = blockIdx.y * 256;
    if (tile_r >= g_total) return;
    const int tile_c = blockIdx.x * 128;
    const int e = g_expert[tile_r];

    extern __shared__ float sm[];
    float* Asm = sm;
    float* Bsm = sm + NBUF * ABUF;
    int*   stok = (int*)(sm + NBUF * ABUF + NBUF * BBUF);

    const int tid  = threadIdx.x;
    const int wid  = tid >> 5;
    const int lane = tid & 31;
    const int gq   = lane >> 2;
    const int tq   = lane & 3;
    const int m0   = (wid & 3) * 64;
    const int n0   = (wid >> 2) * 32;

    if (!SECOND && tid < 256) stok[tid] = g_token[tile_r + tid];
    __syncthreads();

    const float* Bm = Bmain + (size_t)e * KMAIN * NWW + tile_c;
    const float* Be = Bext  + (size_t)e * 64 * NWW + tile_c;
    const float* Aext = (SECOND ? g_t2 : g_t1) + (size_t)tile_r * 64;

    auto load_stage = [&](int s, int buf) {
        const int k0 = s * 32;
        const bool mn = (k0 < KMAIN);
        float* Ab = Asm + buf * ABUF;
        float* Bb = Bsm + buf * BBUF;
#pragma unroll
        for (int i = 0; i < 4; i++) {
            int idx = tid + i * 512;
            int r = idx >> 3, c = (idx & 7) * 4;
            const float* src;
            if (mn) src = (SECOND ? (g_h + (size_t)(tile_r + r) * KMAIN)
                                  : (g_xr + (size_t)stok[r] * KMAIN)) + k0 + c;
            else    src = Aext + (size_t)r * 64 + (k0 - KMAIN) + c;
            cp16(Ab + r * ASTR + c, src);
        }
#pragma unroll
        for (int i = 0; i < 2; i++) {
            int idx = tid + i * 512;
            int k = idx >> 5, c = (idx & 31) * 4;
            const float* src = mn ? (Bm + (size_t)(k0 + k) * NWW + c)
                                  : (Be + (size_t)(k0 - KMAIN + k) * NWW + c);
            cp16(Bb + k * BSTR + c, src);
        }
        cp_commit();
    };

    // per-lane ldmatrix offsets (bytes, relative to A buffer base) for the 4 mi tiles
    const uint32_t a_base = (uint32_t)__cvta_generic_to_shared(Asm);
    const int q = lane >> 3, rr = lane & 7;
    uint32_t offA[4];
#pragma unroll
    for (int mi = 0; mi < 4; mi++)
        offA[mi] = (uint32_t)(((m0 + mi * 16 + (q & 1) * 8 + rr) * ASTR + (q >> 1) * 4) * 4);

    float c[4][4][4];
#pragma unroll
    for (int mi = 0; mi < 4; mi++)
#pragma unroll
        for (int nj = 0; nj < 4; nj++)
#pragma unroll
            for (int qq = 0; qq < 4; qq++) c[mi][nj][qq] = 0.f;

    constexpr int NIT = (KMAIN + 64) / 32;
    load_stage(0, 0);
    load_stage(1, 1);
    load_stage(2, 2);

    for (int it = 0; it < NIT; ++it) {
        const int buf = it & 3;
        cp_wait<2>();                       // FIFO groups: all groups <= it complete
        __syncthreads();                    // single barrier: everyone done with stage it-1
        if (it + 3 < NIT) load_stage(it + 3, (it + 3) & 3);   // writes buf (it-1)&3: safe
        else              cp_commit();      // empty group keeps wait<2> arithmetic valid

        const uint32_t abuf = a_base + (uint32_t)(buf * (ABUF * 4));
        const float* Bb = Bsm + buf * BBUF;
#pragma unroll
        for (int kk = 0; kk < 4; kk++) {
            uint32_t a[4][4], b[4][2];
#pragma unroll
            for (int mi = 0; mi < 4; mi++)
                ldsm_x4(a[mi], abuf + offA[mi] + (uint32_t)(kk * 32));
#pragma unroll
            for (int nj = 0; nj < 4; nj++) {
                int cb = n0 + nj * 8 + gq;
                b[nj][0] = __float_as_uint(Bb[(kk * 8 + tq) * BSTR + cb]);
                b[nj][1] = __float_as_uint(Bb[(kk * 8 + tq + 4) * BSTR + cb]);
            }
#pragma unroll
            for (int mi = 0; mi < 4; mi++)
#pragma unroll
                for (int nj = 0; nj < 4; nj++)
                    mma_tf32(c[mi][nj], a[mi], b[nj]);
        }
    }

#pragma unroll
    for (int mi = 0; mi < 4; mi++) {
#pragma unroll
        for (int rs = 0; rs < 2; rs++) {
            int rloc = m0 + mi * 16 + gq + rs * 8;
            int grow = tile_r + rloc;
            float gt = 0.f; int tok = 0;
            if (SECOND) { gt = g_gate[grow]; tok = g_token[grow]; }
#pragma unroll
            for (int nj = 0; nj < 4; nj++) {
                int gcol = tile_c + n0 + nj * 8 + tq * 2;
                float v0 = c[mi][nj][rs * 2 + 0] + bias[e * NWW + gcol];
                float v1 = c[mi][nj][rs * 2 + 1] + bias[e * NWW + gcol + 1];
                if (!SECOND) {
                    g_h[(size_t)grow * NWW + gcol]     = rnaf(gelu_exact(v0));
                    g_h[(size_t)grow * NWW + gcol + 1] = rnaf(gelu_exact(v1));
                } else {
                    atomicAdd(&y[(size_t)tok * NWW + gcol],     v0 * gt);
                    atomicAdd(&y[(size_t)tok * NWW + gcol + 1], v1 * gt);
                }
            }
        }
    }
}

// ---------------- 9. loss (runs last; independent of GEMMs) ----------------
__global__ void k_loss(float* __restrict__ out, int out_size) {
    __shared__ float simp[256][NEXP];
    __shared__ float s_imp[NEXP];
    int tid = threadIdx.x;
    float local[NEXP];
#pragma unroll
    for (int e = 0; e < NEXP; e++) local[e] = 0.f;
    for (int i = tid; i < 2 * NTOK; i += 256) {
        int e = g_top2_idx[i];
        float gv = g_top2_gate[i];
#pragma unroll
        for (int q = 0; q < NEXP; q++) local[q] += (q == e) ? gv : 0.f;
    }
#pragma unroll
    for (int e = 0; e < NEXP; e++) simp[tid][e] = local[e];
    __syncthreads();
    if (tid < NEXP) {
        float s = 0.f;
        for (int i = 0; i < 256; i++) s += simp[i][tid];
        s_imp[tid] = s;
    }
    __syncthreads();
    if (tid == 0) {
        int cnt_e[NEXP];
        for (int e = 0; e < NEXP; e++) {
            int cum = 0;
            for (int b = 0; b < NB; b++) cum += g_cnt_eb[e * NB + b];
            cnt_e[e] = cum;
        }
        float mi = 0.f, ml = 0.f;
        for (int e = 0; e < NEXP; e++) { mi += s_imp[e]; ml += (float)cnt_e[e]; }
        mi *= (1.f / NEXP); ml *= (1.f / NEXP);
        float vi = 0.f, vl = 0.f;
        for (int e = 0; e < NEXP; e++) {
            float di = s_imp[e] - mi;        vi += di * di;
            float dl = (float)cnt_e[e] - ml; vl += dl * dl;
        }
        vi *= (1.f / (NEXP - 1)); vl *= (1.f / (NEXP - 1));
        float loss = 0.01f * (vi / (mi * mi + 1e-10f) + vl / (ml * ml + 1e-10f));
        if (out_size > NTOK * NOUT) out[(size_t)NTOK * NOUT] = loss;
    }
}

// ---------------- launch ----------------
extern "C" void kernel_launch(void* const* d_in, const int* in_sizes, int n_in,
                              void* d_out, int out_size) {
    const float* x      = (const float*)d_in[0];
    const int*   band   = (const int*)d_in[1];
    const float* w_gate = (const float*)d_in[2];
    const float* W1     = (const float*)d_in[3];
    const float* b1     = (const float*)d_in[4];
    const float* W2     = (const float*)d_in[5];
    const float* b2     = (const float*)d_in[6];
    const float* A1     = (const float*)d_in[7];
    const float* B1     = (const float*)d_in[8];
    const float* A2     = (const float*)d_in[9];
    const float* B2     = (const float*)d_in[10];
    float* y = (float*)d_out;

    float *w1r, *b1r, *w2r, *b2r;
    cudaGetSymbolAddress((void**)&w1r, g_w1r);
    cudaGetSymbolAddress((void**)&b1r, g_b1r);
    cudaGetSymbolAddress((void**)&w2r, g_w2r);
    cudaGetSymbolAddress((void**)&b2r, g_b2r);
    cudaFuncSetAttribute(k_gemm<DIM, HID, false>,
                         cudaFuncAttributeMaxDynamicSharedMemorySize, GEMM_SMEM);
    cudaFuncSetAttribute(k_gemm<HID, NOUT, true>,
                         cudaFuncAttributeMaxDynamicSharedMemorySize, GEMM_SMEM);
    cudaFuncSetAttribute(k_lmma<DIM, false>,
                         cudaFuncAttributeMaxDynamicSharedMemorySize, LMMA_SMEM);
    cudaFuncSetAttribute(k_lmma<HID, true>,
                         cudaFuncAttributeMaxDynamicSharedMemorySize, LMMA_SMEM);

    k_init<<<16384, 256>>>(y, x);                                            // 1
    k_prep<<<P_BLOCKS, 256>>>(W1, B1, W2, B2, A1, A2);                       // 2
    k_gate<<<2048, 256>>>(x, w_gate, band);                                  // 3
    k_scatter<<<128, 256>>>(band);                                           // 4
    k_lmma<DIM, false><<<PMAX / 128, 256, LMMA_SMEM>>>();                    // 5
    k_gemm<DIM, HID, false><<<dim3(HID / 128, PMAX / 256), 512, GEMM_SMEM>>>(w1r, b1r, b1, y);   // 6
    k_lmma<HID, true><<<PMAX / 128, 256, LMMA_SMEM>>>();                     // 7
    k_gemm<HID, NOUT, true><<<dim3(NOUT / 128, PMAX / 256), 512, GEMM_SMEM>>>(w2r, b2r, b2, y);  // 8
    k_loss<<<1, 256>>>(y, out_size);                                         // 9
}

// round 11
// speedup vs baseline: 3.3138x; 1.5066x over previous
#include <cuda_runtime.h>
#include <cuda_fp16.h>
#include <math.h>
#include <stdint.h>

// ---------------- problem constants ----------------
#define NTOK 16384
#define DIM  1024
#define HID  4096
#define NOUT 1024
#define NEXP 8
#define NB   4
#define PMAX 34816            // 136*256: 2*NTOK + 8*256 worst-case expert padding (256-aligned)

// ---------------- device scratch (static: no allocs allowed) ----------------
__device__ __half g_h  [(size_t)PMAX * HID];              // post-gelu hidden (fp16)
__device__ __half g_xh [(size_t)NTOK * DIM];              // fp16(x)
__device__ __half g_w1h[(size_t)NEXP * HID * (DIM + 64)]; // [E][H][1088] = W1^T ++ B1^T (fp16)
__device__ __half g_w2h[(size_t)NEXP * NOUT * (HID + 64)];// [E][O][4160] = W2^T ++ B2^T (fp16)
__device__ __half g_a1t[(size_t)NEXP * 64 * DIM];         // [E][j=b*16+r][D]  fp16(A1)
__device__ __half g_a2t[(size_t)NEXP * 64 * HID];         // [E][j][H]        fp16(A2)
__device__ __half g_t1 [(size_t)PMAX * 64];
__device__ __half g_t2 [(size_t)PMAX * 64];
__device__ int   g_token[PMAX];
__device__ int   g_band[PMAX];
__device__ int   g_expert[PMAX];
__device__ float g_gate[PMAX];
__device__ int   g_top2_idx[NTOK * 2];
__device__ float g_top2_gate[NTOK * 2];
__device__ int   g_cnt_eb[NEXP * NB];
__device__ int   g_cur_eb[NEXP * NB];
__device__ int   g_total;

// ---------------- helpers ----------------
__device__ __forceinline__ void cp16(const void* smem, const void* gmem) {
    uint32_t s = (uint32_t)__cvta_generic_to_shared(smem);
    asm volatile("cp.async.cg.shared.global [%0], [%1], 16;" :: "r"(s), "l"(gmem));
}
__device__ __forceinline__ void cp_commit() { asm volatile("cp.async.commit_group;" ::: "memory"); }
template <int n> __device__ __forceinline__ void cp_wait() {
    asm volatile("cp.async.wait_group %0;" :: "n"(n) : "memory");
}
__device__ __forceinline__ void mma_f16(float* c, const uint32_t* a, const uint32_t* b) {
    asm volatile(
        "mma.sync.aligned.m16n8k16.row.col.f32.f16.f16.f32 "
        "{%0,%1,%2,%3}, {%4,%5,%6,%7}, {%8,%9}, {%0,%1,%2,%3};"
        : "+f"(c[0]), "+f"(c[1]), "+f"(c[2]), "+f"(c[3])
        : "r"(a[0]), "r"(a[1]), "r"(a[2]), "r"(a[3]), "r"(b[0]), "r"(b[1]));
}
__device__ __forceinline__ void ldsm_x4(uint32_t* d, uint32_t addr) {
    asm volatile("ldmatrix.sync.aligned.m8n8.x4.shared.b16 {%0,%1,%2,%3}, [%4];"
                 : "=r"(d[0]), "=r"(d[1]), "=r"(d[2]), "=r"(d[3]) : "r"(addr));
}
__device__ __forceinline__ float gelu_exact(float x) {
    return 0.5f * x * (1.0f + erff(x * 0.70710678118654752440f));
}

// ---------------- 1. init: zero y, fp16 x, dispatch state ----------------
__global__ void k_init(float* __restrict__ y, const float* __restrict__ x) {
    size_t i = (size_t)blockIdx.x * 256 + threadIdx.x;       // 16384 blocks covers both
    reinterpret_cast<float4*>(y)[i] = make_float4(0.f, 0.f, 0.f, 0.f);
    float4 v = reinterpret_cast<const float4*>(x)[i];        // NTOK*DIM/4 elements
    __half2* d = reinterpret_cast<__half2*>(g_xh + i * 4);
    d[0] = __floats2half2_rn(v.x, v.y);
    d[1] = __floats2half2_rn(v.z, v.w);
    if (i < PMAX) { g_token[i] = 0; g_band[i] = 0; g_expert[i] = 0; g_gate[i] = 0.f; }
    if (i < NEXP * NB) { g_cnt_eb[i] = 0; g_cur_eb[i] = 0; }
}

// ---------------- 2. mega-prep: transposes + ext/A packs, ONE kernel ----------------
// seg0: W1^T tiles (32768 blk)  seg1: W2^T tiles (32768)  seg2: B1 ext (8192)
// seg3: B2 ext (2048)  seg4: A1 pack (2048)  seg5: A2 pack (8192)   total 86016
#define PS0 32768
#define PS1 65536
#define PS2 73728
#define PS3 75776
#define PS4 77824
#define PS5 86016

__global__ void k_prep(const float* __restrict__ W1, const float* __restrict__ B1,
                       const float* __restrict__ W2, const float* __restrict__ B2,
                       const float* __restrict__ A1, const float* __restrict__ A2) {
    __shared__ float t[32][33];
    int bid = blockIdx.x;
    int tid = threadIdx.x;
    int tx = tid & 31, ty = tid >> 5;    // ty 0..7
    if (bid < PS1) {
        // tiled transpose: src [E][K][N] f32 -> dst [E][N][KROW] f16
        const float* src; __half* dst; int KD, NW, KROW, kt, nt, e;
        if (bid < PS0) {
            src = W1; dst = g_w1h; KD = DIM; NW = HID; KROW = DIM + 64;
            e = bid >> 12; int r2 = bid & 4095; kt = r2 >> 7; nt = r2 & 127;
        } else {
            int b2 = bid - PS0;
            src = W2; dst = g_w2h; KD = HID; NW = NOUT; KROW = HID + 64;
            e = b2 >> 12; int r2 = b2 & 4095; kt = r2 >> 5; nt = r2 & 31;
        }
        int k0 = kt * 32, n0 = nt * 32;
#pragma unroll
        for (int i = 0; i < 4; i++)
            t[ty + i * 8][tx] = src[((size_t)e * KD + k0 + ty + i * 8) * NW + n0 + tx];
        __syncthreads();
#pragma unroll
        for (int i = 0; i < 4; i++)
            dst[((size_t)e * NW + n0 + ty + i * 8) * KROW + k0 + tx] =
                __float2half(t[tx][ty + i * 8]);
    } else if (bid < PS2) {
        size_t idx = (size_t)(bid - PS1) * 256 + tid;    // E*HID*64
        int j = (int)(idx & 63); int n = (int)((idx >> 6) & 4095); int e = (int)(idx >> 18);
        g_w1h[((size_t)e * HID + n) * (DIM + 64) + DIM + j] =
            __float2half(B1[((size_t)e * 64 + j) * HID + n]);
    } else if (bid < PS3) {
        size_t idx = (size_t)(bid - PS2) * 256 + tid;    // E*NOUT*64
        int j = (int)(idx & 63); int n = (int)((idx >> 6) & 1023); int e = (int)(idx >> 16);
        g_w2h[((size_t)e * NOUT + n) * (HID + 64) + HID + j] =
            __float2half(B2[((size_t)e * 64 + j) * NOUT + n]);
    } else if (bid < PS4) {
        size_t idx = (size_t)(bid - PS3) * 256 + tid;    // E*64*DIM
        int d = (int)(idx & 1023); int j = (int)((idx >> 10) & 63); int e = (int)(idx >> 16);
        g_a1t[((size_t)e * 64 + j) * DIM + d] =
            __float2half(A1[(((size_t)e * NB + (j >> 4)) * DIM + d) * 16 + (j & 15)]);
    } else if (bid < PS5) {
        size_t idx = (size_t)(bid - PS4) * 256 + tid;    // E*64*HID
        int d = (int)(idx & 4095); int j = (int)((idx >> 12) & 63); int e = (int)(idx >> 18);
        g_a2t[((size_t)e * 64 + j) * HID + d] =
            __float2half(A2[(((size_t)e * NB + (j >> 4)) * HID + d) * 16 + (j & 15)]);
    }
}

// ---------------- 3. gating ----------------
__global__ void k_gate(const float* __restrict__ x, const float* __restrict__ wg,
                       const int* __restrict__ band) {
    int gtid = blockIdx.x * blockDim.x + threadIdx.x;
    int tok  = gtid >> 5;
    int lane = threadIdx.x & 31;
    if (tok >= NTOK) return;
    const float* xr = x + (size_t)tok * DIM;
    float acc[NEXP];
#pragma unroll
    for (int e = 0; e < NEXP; e++) acc[e] = 0.f;
    for (int d = lane; d < DIM; d += 32) {
        float xv = xr[d];
        const float4* w4 = reinterpret_cast<const float4*>(wg + (size_t)d * NEXP);
        float4 wa = w4[0], wb = w4[1];
        acc[0] += xv * wa.x; acc[1] += xv * wa.y; acc[2] += xv * wa.z; acc[3] += xv * wa.w;
        acc[4] += xv * wb.x; acc[5] += xv * wb.y; acc[6] += xv * wb.z; acc[7] += xv * wb.w;
    }
#pragma unroll
    for (int e = 0; e < NEXP; e++)
#pragma unroll
        for (int off = 16; off; off >>= 1)
            acc[e] += __shfl_xor_sync(0xffffffffu, acc[e], off);
    int i0 = 0; float v0 = acc[0];
#pragma unroll
    for (int e = 1; e < NEXP; e++) if (acc[e] > v0) { v0 = acc[e]; i0 = e; }
    int i1 = -1; float v1 = -3.4e38f;
#pragma unroll
    for (int e = 0; e < NEXP; e++) if (e != i0 && acc[e] > v1) { v1 = acc[e]; i1 = e; }
    float ex = expf(v1 - v0);
    float den = 1.f + ex;
    if (lane == 0) {
        int b = band[tok];
        g_top2_idx[tok * 2] = i0;  g_top2_idx[tok * 2 + 1] = i1;
        g_top2_gate[tok * 2] = 1.f / den;  g_top2_gate[tok * 2 + 1] = ex / den;
        atomicAdd(&g_cnt_eb[i0 * NB + b], 1);
        atomicAdd(&g_cnt_eb[i1 * NB + b], 1);
    }
}

// ---------------- 4. scatter ----------------
__global__ void k_scatter(const int* __restrict__ band) {
    int i = blockIdx.x * 256 + threadIdx.x;
    if (i >= 2 * NTOK) return;
    int pob[NEXP * NB];
    int p = 0;
#pragma unroll
    for (int e = 0; e < NEXP; e++) {
        int cum = 0;
#pragma unroll
        for (int b = 0; b < NB; b++) {
            pob[e * NB + b] = p + cum;
            cum += __ldg(&g_cnt_eb[e * NB + b]);
        }
        p += (cum + 255) & ~255;
    }
    if (i == 0) g_total = p;
    int t = i >> 1;
    int e = g_top2_idx[i];
    int b = band[t];
    int pos = pob[e * NB + b] + atomicAdd(&g_cur_eb[e * NB + b], 1);
    g_token[pos]  = t;
    g_gate[pos]   = g_top2_gate[i];
    g_band[pos]   = b;
    g_expert[pos] = e;
}

// ---------------- 5/7. lora down-proj mma (fp16): t = mask_band(2 * A @ Apk[e]^T) ----
#define L_ASTR 40
#define L_BSTR 40
#define L_ABUF (128 * L_ASTR)
#define L_BBUF (64 * L_BSTR)
#define LMMA_SMEM ((2 * (L_ABUF + L_BBUF)) * 2 + 2048)

template <int KD, bool SECOND>
__global__ void __launch_bounds__(256, 2)
k_lmma() {
    const int tile_r = blockIdx.x * 128;
    if (tile_r >= g_total) return;
    const int e = g_expert[tile_r];

    extern __shared__ __half smh[];
    __half* Asm = smh;
    __half* Bsm = smh + 2 * L_ABUF;
    int*   stok  = (int*)(smh + 2 * (L_ABUF + L_BBUF));
    int*   sband = stok + 128;

    const int tid  = threadIdx.x;
    const int wid  = tid >> 5;
    const int lane = tid & 31;
    const int gq   = lane >> 2;
    const int tq   = lane & 3;
    const int m0   = (wid & 3) * 32;
    const int n0   = (wid >> 2) * 32;

    if (tid < 128) {
        stok[tid]  = SECOND ? (tile_r + tid) : g_token[tile_r + tid];
        sband[tid] = g_band[tile_r + tid];
    }
    __syncthreads();

    const __half* Bp = (SECOND ? g_a2t : g_a1t) + (size_t)e * 64 * KD;

    auto load_stage = [&](int s, int buf) {
        const int k0 = s * 32;
        __half* Ab = Asm + buf * L_ABUF;
        __half* Bb = Bsm + buf * L_BBUF;
#pragma unroll
        for (int i2 = 0; i2 < 2; i2++) {                 // A: 128x32 halves = 512 cp16
            int idx = tid + i2 * 256;
            int r = idx >> 2, c = (idx & 3) * 8;
            const __half* src = (SECOND ? (g_h + (size_t)(tile_r + r) * KD)
                                        : (g_xh + (size_t)stok[r] * KD)) + k0 + c;
            cp16(Ab + r * L_ASTR + c, src);
        }
        {                                                 // B: 64x32 halves = 256 cp16
            int n = tid >> 2, c = (tid & 3) * 8;
            cp16(Bb + n * L_BSTR + c, Bp + (size_t)n * KD + k0 + c);
        }
        cp_commit();
    };

    const uint32_t a_base = (uint32_t)__cvta_generic_to_shared(Asm);
    const int lr = lane & 15, lc = lane >> 4;
    uint32_t offA[2];
#pragma unroll
    for (int mi = 0; mi < 2; mi++)
        offA[mi] = (uint32_t)(((m0 + mi * 16 + lr) * L_ASTR + lc * 8) * 2);

    float c[2][4][4];
#pragma unroll
    for (int mi = 0; mi < 2; mi++)
#pragma unroll
        for (int nj = 0; nj < 4; nj++)
#pragma unroll
            for (int q = 0; q < 4; q++) c[mi][nj][q] = 0.f;

    constexpr int NIT = KD / 32;
    load_stage(0, 0);
    for (int it = 0; it < NIT; ++it) {
        const int buf = it & 1;
        if (it + 1 < NIT) { load_stage(it + 1, buf ^ 1); cp_wait<1>(); }
        else              { cp_wait<0>(); }
        __syncthreads();
        const uint32_t abuf = a_base + (uint32_t)(buf * (L_ABUF * 2));
        const __half* Bb = Bsm + buf * L_BBUF;
#pragma unroll
        for (int kk = 0; kk < 2; kk++) {
            uint32_t a[2][4], b[4][2];
#pragma unroll
            for (int mi = 0; mi < 2; mi++)
                ldsm_x4(a[mi], abuf + offA[mi] + (uint32_t)(kk * 32));
#pragma unroll
            for (int nj = 0; nj < 4; nj++) {
                int n = n0 + nj * 8 + gq;
                const uint32_t* bp =
                    (const uint32_t*)(Bb + n * L_BSTR + kk * 16 + tq * 2);
                b[nj][0] = bp[0]; b[nj][1] = bp[4];
            }
#pragma unroll
            for (int mi = 0; mi < 2; mi++)
#pragma unroll
                for (int nj = 0; nj < 4; nj++)
                    mma_f16(c[mi][nj], a[mi], b[nj]);
        }
        __syncthreads();
    }

    __half* T = (SECOND ? g_t2 : g_t1);
#pragma unroll
    for (int mi = 0; mi < 2; mi++) {
#pragma unroll
        for (int rs = 0; rs < 2; rs++) {
            int rloc = m0 + mi * 16 + gq + rs * 8;
            int bd = sband[rloc];
            __half* trow = T + (size_t)(tile_r + rloc) * 64;
#pragma unroll
            for (int nj = 0; nj < 4; nj++) {
                int gcol = n0 + nj * 8 + tq * 2;
                bool in0 = ((gcol >> 4) == bd);
                float v0 = in0 ? 2.0f * c[mi][nj][rs * 2 + 0] : 0.f;
                float v1 = in0 ? 2.0f * c[mi][nj][rs * 2 + 1] : 0.f;
                *reinterpret_cast<__half2*>(trow + gcol) = __floats2half2_rn(v0, v1);
            }
        }
    }
}

// ---------------- 6/8. grouped GEMM: fp16 mma m16n8k16, 256x128x32 tiles ----------
// 4-buffer cp.async pipeline, ONE barrier per K-stage.  B packed [E][N][KMAIN+64].
#define ASTR 40
#define BSTR 40
#define ABUF (256 * ASTR)
#define BBUF (128 * BSTR)
#define NBUF 4
#define GEMM_SMEM ((NBUF * (ABUF + BBUF)) * 2 + 1024)

template <int KMAIN, int NWW, bool SECOND>
__global__ void __launch_bounds__(512, 1)
k_gemm(const __half* __restrict__ Bw, const float* __restrict__ bias,
       float* __restrict__ y) {
    const int tile_r = blockIdx.y * 256;
    if (tile_r >= g_total) return;
    const int tile_c = blockIdx.x * 128;
    const int e = g_expert[tile_r];
    constexpr int KROW = KMAIN + 64;

    extern __shared__ __half smh[];
    __half* Asm = smh;
    __half* Bsm = smh + NBUF * ABUF;
    int*   stok = (int*)(smh + NBUF * (ABUF + BBUF));

    const int tid  = threadIdx.x;
    const int wid  = tid >> 5;
    const int lane = tid & 31;
    const int gq   = lane >> 2;
    const int tq   = lane & 3;
    const int m0   = (wid & 3) * 64;
    const int n0   = (wid >> 2) * 32;

    if (!SECOND && tid < 256) stok[tid] = g_token[tile_r + tid];
    __syncthreads();

    const __half* Bp = Bw + ((size_t)e * NWW + tile_c) * KROW;
    const __half* Aext = (SECOND ? g_t2 : g_t1) + (size_t)tile_r * 64;

    auto load_stage = [&](int s, int buf) {
        const int k0 = s * 32;
        const bool mn = (k0 < KMAIN);
        __half* Ab = Asm + buf * ABUF;
        __half* Bb = Bsm + buf * BBUF;
#pragma unroll
        for (int i = 0; i < 2; i++) {                    // A: 256x32 halves = 1024 cp16
            int idx = tid + i * 512;
            int r = idx >> 2, c = (idx & 3) * 8;
            const __half* src;
            if (mn) src = (SECOND ? (g_h + (size_t)(tile_r + r) * KMAIN)
                                  : (g_xh + (size_t)stok[r] * KMAIN)) + k0 + c;
            else    src = Aext + (size_t)r * 64 + (k0 - KMAIN) + c;
            cp16(Ab + r * ASTR + c, src);
        }
        {                                                 // B: 128x32 halves = 512 cp16
            int n = tid >> 2, c = (tid & 3) * 8;
            cp16(Bb + n * BSTR + c, Bp + (size_t)n * KROW + k0 + c);
        }
        cp_commit();
    };

    const uint32_t a_base = (uint32_t)__cvta_generic_to_shared(Asm);
    const int lr = lane & 15, lc = lane >> 4;
    uint32_t offA[4];
#pragma unroll
    for (int mi = 0; mi < 4; mi++)
        offA[mi] = (uint32_t)(((m0 + mi * 16 + lr) * ASTR + lc * 8) * 2);

    float c[4][4][4];
#pragma unroll
    for (int mi = 0; mi < 4; mi++)
#pragma unroll
        for (int nj = 0; nj < 4; nj++)
#pragma unroll
            for (int qq = 0; qq < 4; qq++) c[mi][nj][qq] = 0.f;

    constexpr int NIT = KROW / 32;
    load_stage(0, 0);
    load_stage(1, 1);
    load_stage(2, 2);

    for (int it = 0; it < NIT; ++it) {
        const int buf = it & 3;
        cp_wait<2>();
        __syncthreads();
        if (it + 3 < NIT) load_stage(it + 3, (it + 3) & 3);
        else              cp_commit();

        const uint32_t abuf = a_base + (uint32_t)(buf * (ABUF * 2));
        const __half* Bb = Bsm + buf * BBUF;
#pragma unroll
        for (int kk = 0; kk < 2; kk++) {
            uint32_t a[4][4], b[4][2];
#pragma unroll
            for (int mi = 0; mi < 4; mi++)
                ldsm_x4(a[mi], abuf + offA[mi] + (uint32_t)(kk * 32));
#pragma unroll
            for (int nj = 0; nj < 4; nj++) {
                int n = n0 + nj * 8 + gq;
                const uint32_t* bp =
                    (const uint32_t*)(Bb + n * BSTR + kk * 16 + tq * 2);
                b[nj][0] = bp[0]; b[nj][1] = bp[4];
            }
#pragma unroll
            for (int mi = 0; mi < 4; mi++)
#pragma unroll
                for (int nj = 0; nj < 4; nj++)
                    mma_f16(c[mi][nj], a[mi], b[nj]);
        }
    }

#pragma unroll
    for (int mi = 0; mi < 4; mi++) {
#pragma unroll
        for (int rs = 0; rs < 2; rs++) {
            int rloc = m0 + mi * 16 + gq + rs * 8;
            int grow = tile_r + rloc;
            float gt = 0.f; int tok = 0;
            if (SECOND) { gt = g_gate[grow]; tok = g_token[grow]; }
#pragma unroll
            for (int nj = 0; nj < 4; nj++) {
                int gcol = tile_c + n0 + nj * 8 + tq * 2;
                float v0 = c[mi][nj][rs * 2 + 0] + bias[e * NWW + gcol];
                float v1 = c[mi][nj][rs * 2 + 1] + bias[e * NWW + gcol + 1];
                if (!SECOND) {
                    *reinterpret_cast<__half2*>(&g_h[(size_t)grow * NWW + gcol]) =
                        __floats2half2_rn(gelu_exact(v0), gelu_exact(v1));
                } else {
                    atomicAdd(&y[(size_t)tok * NWW + gcol],     v0 * gt);
                    atomicAdd(&y[(size_t)tok * NWW + gcol + 1], v1 * gt);
                }
            }
        }
    }
}

// ---------------- 9. loss ----------------
__global__ void k_loss(float* __restrict__ out, int out_size) {
    __shared__ float simp[256][NEXP];
    __shared__ float s_imp[NEXP];
    int tid = threadIdx.x;
    float local[NEXP];
#pragma unroll
    for (int e = 0; e < NEXP; e++) local[e] = 0.f;
    for (int i = tid; i < 2 * NTOK; i += 256) {
        int e = g_top2_idx[i];
        float gv = g_top2_gate[i];
#pragma unroll
        for (int q = 0; q < NEXP; q++) local[q] += (q == e) ? gv : 0.f;
    }
#pragma unroll
    for (int e = 0; e < NEXP; e++) simp[tid][e] = local[e];
    __syncthreads();
    if (tid < NEXP) {
        float s = 0.f;
        for (int i = 0; i < 256; i++) s += simp[i][tid];
        s_imp[tid] = s;
    }
    __syncthreads();
    if (tid == 0) {
        int cnt_e[NEXP];
        for (int e = 0; e < NEXP; e++) {
            int cum = 0;
            for (int b = 0; b < NB; b++) cum += g_cnt_eb[e * NB + b];
            cnt_e[e] = cum;
        }
        float mi = 0.f, ml = 0.f;
        for (int e = 0; e < NEXP; e++) { mi += s_imp[e]; ml += (float)cnt_e[e]; }
        mi *= (1.f / NEXP); ml *= (1.f / NEXP);
        float vi = 0.f, vl = 0.f;
        for (int e = 0; e < NEXP; e++) {
            float di = s_imp[e] - mi;        vi += di * di;
            float dl = (float)cnt_e[e] - ml; vl += dl * dl;
        }
        vi *= (1.f / (NEXP - 1)); vl *= (1.f / (NEXP - 1));
        float loss = 0.01f * (vi / (mi * mi + 1e-10f) + vl / (ml * ml + 1e-10f));
        if (out_size > NTOK * NOUT) out[(size_t)NTOK * NOUT] = loss;
    }
}

// ---------------- launch ----------------
extern "C" void kernel_launch(void* const* d_in, const int* in_sizes, int n_in,
                              void* d_out, int out_size) {
    const float* x      = (const float*)d_in[0];
    const int*   band   = (const int*)d_in[1];
    const float* w_gate = (const float*)d_in[2];
    const float* W1     = (const float*)d_in[3];
    const float* b1     = (const float*)d_in[4];
    const float* W2     = (const float*)d_in[5];
    const float* b2     = (const float*)d_in[6];
    const float* A1     = (const float*)d_in[7];
    const float* B1     = (const float*)d_in[8];
    const float* A2     = (const float*)d_in[9];
    const float* B2     = (const float*)d_in[10];
    float* y = (float*)d_out;

    __half *w1h, *w2h;
    cudaGetSymbolAddress((void**)&w1h, g_w1h);
    cudaGetSymbolAddress((void**)&w2h, g_w2h);
    cudaFuncSetAttribute(k_gemm<DIM, HID, false>,
                         cudaFuncAttributeMaxDynamicSharedMemorySize, GEMM_SMEM);
    cudaFuncSetAttribute(k_gemm<HID, NOUT, true>,
                         cudaFuncAttributeMaxDynamicSharedMemorySize, GEMM_SMEM);

    k_init<<<16384, 256>>>(y, x);                                            // 1
    k_prep<<<PS5, 256>>>(W1, B1, W2, B2, A1, A2);                            // 2
    k_gate<<<2048, 256>>>(x, w_gate, band);                                  // 3
    k_scatter<<<128, 256>>>(band);                                           // 4
    k_lmma<DIM, false><<<PMAX / 128, 256, LMMA_SMEM>>>();                    // 5
    k_gemm<DIM, HID, false><<<dim3(HID / 128, PMAX / 256), 512, GEMM_SMEM>>>(w1h, b1, y);   // 6
    k_lmma<HID, true><<<PMAX / 128, 256, LMMA_SMEM>>>();                     // 7
    k_gemm<HID, NOUT, true><<<dim3(NOUT / 128, PMAX / 256), 512, GEMM_SMEM>>>(w2h, b2, y);  // 8
    k_loss<<<1, 256>>>(y, out_size);                                         // 9
}

// round 12
// speedup vs baseline: 3.9293x; 1.1858x over previous
#include <cuda_runtime.h>
#include <cuda_fp16.h>
#include <math.h>
#include <stdint.h>

// ---------------- problem constants ----------------
#define NTOK 16384
#define DIM  1024
#define HID  4096
#define NOUT 1024
#define NEXP 8
#define NB   4
#define PMAX 34816            // 136*256: 2*NTOK + 8*256 worst-case expert padding (256-aligned)

// ---------------- device scratch (static: no allocs allowed) ----------------
__device__ __half g_h  [(size_t)PMAX * HID];              // post-gelu hidden (fp16)
__device__ __half g_xh [(size_t)NTOK * DIM];              // fp16(x)
__device__ __half g_w1h[(size_t)NEXP * HID * (DIM + 64)]; // [E][H][1088] = W1^T ++ B1^T
__device__ __half g_w2h[(size_t)NEXP * NOUT * (HID + 64)];// [E][O][4160] = W2^T ++ B2^T
__device__ __half g_a1t[(size_t)NEXP * 64 * DIM];         // [E][j=b*16+r][D]
__device__ __half g_a2t[(size_t)NEXP * 64 * HID];         // [E][j][H]
__device__ __half g_t1 [(size_t)PMAX * 64];
__device__ __half g_t2 [(size_t)PMAX * 64];
__device__ int   g_token[PMAX];
__device__ int   g_band[PMAX];
__device__ int   g_expert[PMAX];
__device__ float g_gate[PMAX];
__device__ int   g_top2_idx[NTOK * 2];
__device__ float g_top2_gate[NTOK * 2];
__device__ int   g_cnt_eb[NEXP * NB];
__device__ int   g_cur_eb[NEXP * NB];
__device__ int   g_total;

// ---------------- helpers ----------------
__device__ __forceinline__ void cp16(const void* smem, const void* gmem) {
    uint32_t s = (uint32_t)__cvta_generic_to_shared(smem);
    asm volatile("cp.async.cg.shared.global [%0], [%1], 16;" :: "r"(s), "l"(gmem));
}
__device__ __forceinline__ void cp_commit() { asm volatile("cp.async.commit_group;" ::: "memory"); }
template <int n> __device__ __forceinline__ void cp_wait() {
    asm volatile("cp.async.wait_group %0;" :: "n"(n) : "memory");
}
__device__ __forceinline__ void mma_f16(float* c, const uint32_t* a, const uint32_t* b) {
    asm volatile(
        "mma.sync.aligned.m16n8k16.row.col.f32.f16.f16.f32 "
        "{%0,%1,%2,%3}, {%4,%5,%6,%7}, {%8,%9}, {%0,%1,%2,%3};"
        : "+f"(c[0]), "+f"(c[1]), "+f"(c[2]), "+f"(c[3])
        : "r"(a[0]), "r"(a[1]), "r"(a[2]), "r"(a[3]), "r"(b[0]), "r"(b[1]));
}
__device__ __forceinline__ void ldsm_x4(uint32_t* d, uint32_t addr) {
    asm volatile("ldmatrix.sync.aligned.m8n8.x4.shared.b16 {%0,%1,%2,%3}, [%4];"
                 : "=r"(d[0]), "=r"(d[1]), "=r"(d[2]), "=r"(d[3]) : "r"(addr));
}
__device__ __forceinline__ float gelu_exact(float x) {
    return 0.5f * x * (1.0f + erff(x * 0.70710678118654752440f));
}

// ---------------- 1a. zinit: counters + dispatch arrays (fast, heads gating chain) ---
__global__ void k_zinit() {
    int i = blockIdx.x * 256 + threadIdx.x;          // grid 136 -> covers PMAX
    g_token[i] = 0; g_band[i] = 0; g_expert[i] = 0; g_gate[i] = 0.f;
    if (i < NEXP * NB) { g_cnt_eb[i] = 0; g_cur_eb[i] = 0; }
}

// ---------------- 1b. binit: zero y + fp16(x) (overlapped on side stream) ----------
__global__ void k_binit(float* __restrict__ y, const float* __restrict__ x) {
    size_t i = (size_t)blockIdx.x * 256 + threadIdx.x;   // 16384 blocks = NTOK*NOUT/4
    reinterpret_cast<float4*>(y)[i] = make_float4(0.f, 0.f, 0.f, 0.f);
    float4 v = reinterpret_cast<const float4*>(x)[i];
    __half2* d = reinterpret_cast<__half2*>(g_xh + i * 4);
    d[0] = __floats2half2_rn(v.x, v.y);
    d[1] = __floats2half2_rn(v.z, v.w);
}

// ---------------- 2. mega-prep: transposes + ext/A packs (side stream) -------------
#define PS0 32768
#define PS1 65536
#define PS2 73728
#define PS3 75776
#define PS4 77824
#define PS5 86016

__global__ void k_prep(const float* __restrict__ W1, const float* __restrict__ B1,
                       const float* __restrict__ W2, const float* __restrict__ B2,
                       const float* __restrict__ A1, const float* __restrict__ A2) {
    __shared__ float t[32][33];
    int bid = blockIdx.x;
    int tid = threadIdx.x;
    int tx = tid & 31, ty = tid >> 5;
    if (bid < PS1) {
        const float* src; __half* dst; int KD, NW, KROW, kt, nt, e;
        if (bid < PS0) {
            src = W1; dst = g_w1h; KD = DIM; NW = HID; KROW = DIM + 64;
            e = bid >> 12; int r2 = bid & 4095; kt = r2 >> 7; nt = r2 & 127;
        } else {
            int b2 = bid - PS0;
            src = W2; dst = g_w2h; KD = HID; NW = NOUT; KROW = HID + 64;
            e = b2 >> 12; int r2 = b2 & 4095; kt = r2 >> 5; nt = r2 & 31;
        }
        int k0 = kt * 32, n0 = nt * 32;
#pragma unroll
        for (int i = 0; i < 4; i++)
            t[ty + i * 8][tx] = src[((size_t)e * KD + k0 + ty + i * 8) * NW + n0 + tx];
        __syncthreads();
#pragma unroll
        for (int i = 0; i < 4; i++)
            dst[((size_t)e * NW + n0 + ty + i * 8) * KROW + k0 + tx] =
                __float2half(t[tx][ty + i * 8]);
    } else if (bid < PS2) {
        size_t idx = (size_t)(bid - PS1) * 256 + tid;
        int j = (int)(idx & 63); int n = (int)((idx >> 6) & 4095); int e = (int)(idx >> 18);
        g_w1h[((size_t)e * HID + n) * (DIM + 64) + DIM + j] =
            __float2half(B1[((size_t)e * 64 + j) * HID + n]);
    } else if (bid < PS3) {
        size_t idx = (size_t)(bid - PS2) * 256 + tid;
        int j = (int)(idx & 63); int n = (int)((idx >> 6) & 1023); int e = (int)(idx >> 16);
        g_w2h[((size_t)e * NOUT + n) * (HID + 64) + HID + j] =
            __float2half(B2[((size_t)e * 64 + j) * NOUT + n]);
    } else if (bid < PS4) {
        size_t idx = (size_t)(bid - PS3) * 256 + tid;
        int d = (int)(idx & 1023); int j = (int)((idx >> 10) & 63); int e = (int)(idx >> 16);
        g_a1t[((size_t)e * 64 + j) * DIM + d] =
            __float2half(A1[(((size_t)e * NB + (j >> 4)) * DIM + d) * 16 + (j & 15)]);
    } else if (bid < PS5) {
        size_t idx = (size_t)(bid - PS4) * 256 + tid;
        int d = (int)(idx & 4095); int j = (int)((idx >> 12) & 63); int e = (int)(idx >> 18);
        g_a2t[((size_t)e * 64 + j) * HID + d] =
            __float2half(A2[(((size_t)e * NB + (j >> 4)) * HID + d) * 16 + (j & 15)]);
    }
}

// ---------------- 3. gating ----------------
__global__ void k_gate(const float* __restrict__ x, const float* __restrict__ wg,
                       const int* __restrict__ band) {
    int gtid = blockIdx.x * blockDim.x + threadIdx.x;
    int tok  = gtid >> 5;
    int lane = threadIdx.x & 31;
    if (tok >= NTOK) return;
    const float* xr = x + (size_t)tok * DIM;
    float acc[NEXP];
#pragma unroll
    for (int e = 0; e < NEXP; e++) acc[e] = 0.f;
    for (int d = lane; d < DIM; d += 32) {
        float xv = xr[d];
        const float4* w4 = reinterpret_cast<const float4*>(wg + (size_t)d * NEXP);
        float4 wa = w4[0], wb = w4[1];
        acc[0] += xv * wa.x; acc[1] += xv * wa.y; acc[2] += xv * wa.z; acc[3] += xv * wa.w;
        acc[4] += xv * wb.x; acc[5] += xv * wb.y; acc[6] += xv * wb.z; acc[7] += xv * wb.w;
    }
#pragma unroll
    for (int e = 0; e < NEXP; e++)
#pragma unroll
        for (int off = 16; off; off >>= 1)
            acc[e] += __shfl_xor_sync(0xffffffffu, acc[e], off);
    int i0 = 0; float v0 = acc[0];
#pragma unroll
    for (int e = 1; e < NEXP; e++) if (acc[e] > v0) { v0 = acc[e]; i0 = e; }
    int i1 = -1; float v1 = -3.4e38f;
#pragma unroll
    for (int e = 0; e < NEXP; e++) if (e != i0 && acc[e] > v1) { v1 = acc[e]; i1 = e; }
    float ex = expf(v1 - v0);
    float den = 1.f + ex;
    if (lane == 0) {
        int b = band[tok];
        g_top2_idx[tok * 2] = i0;  g_top2_idx[tok * 2 + 1] = i1;
        g_top2_gate[tok * 2] = 1.f / den;  g_top2_gate[tok * 2 + 1] = ex / den;
        atomicAdd(&g_cnt_eb[i0 * NB + b], 1);
        atomicAdd(&g_cnt_eb[i1 * NB + b], 1);
    }
}

// ---------------- 4. scatter ----------------
__global__ void k_scatter(const int* __restrict__ band) {
    int i = blockIdx.x * 256 + threadIdx.x;
    if (i >= 2 * NTOK) return;
    int pob[NEXP * NB];
    int p = 0;
#pragma unroll
    for (int e = 0; e < NEXP; e++) {
        int cum = 0;
#pragma unroll
        for (int b = 0; b < NB; b++) {
            pob[e * NB + b] = p + cum;
            cum += __ldg(&g_cnt_eb[e * NB + b]);
        }
        p += (cum + 255) & ~255;
    }
    if (i == 0) g_total = p;
    int t = i >> 1;
    int e = g_top2_idx[i];
    int b = band[t];
    int pos = pob[e * NB + b] + atomicAdd(&g_cur_eb[e * NB + b], 1);
    g_token[pos]  = t;
    g_gate[pos]   = g_top2_gate[i];
    g_band[pos]   = b;
    g_expert[pos] = e;
}

// ---------------- 5/7. lora down-proj mma (fp16) ----------------
#define L_ASTR 40
#define L_BSTR 40
#define L_ABUF (128 * L_ASTR)
#define L_BBUF (64 * L_BSTR)
#define LMMA_SMEM ((2 * (L_ABUF + L_BBUF)) * 2 + 2048)

template <int KD, bool SECOND>
__global__ void __launch_bounds__(256, 2)
k_lmma() {
    const int tile_r = blockIdx.x * 128;
    if (tile_r >= g_total) return;
    const int e = g_expert[tile_r];

    extern __shared__ __half smh[];
    __half* Asm = smh;
    __half* Bsm = smh + 2 * L_ABUF;
    int*   stok  = (int*)(smh + 2 * (L_ABUF + L_BBUF));
    int*   sband = stok + 128;

    const int tid  = threadIdx.x;
    const int wid  = tid >> 5;
    const int lane = tid & 31;
    const int gq   = lane >> 2;
    const int tq   = lane & 3;
    const int m0   = (wid & 3) * 32;
    const int n0   = (wid >> 2) * 32;

    if (tid < 128) {
        stok[tid]  = SECOND ? (tile_r + tid) : g_token[tile_r + tid];
        sband[tid] = g_band[tile_r + tid];
    }
    __syncthreads();

    const __half* Bp = (SECOND ? g_a2t : g_a1t) + (size_t)e * 64 * KD;

    auto load_stage = [&](int s, int buf) {
        const int k0 = s * 32;
        __half* Ab = Asm + buf * L_ABUF;
        __half* Bb = Bsm + buf * L_BBUF;
#pragma unroll
        for (int i2 = 0; i2 < 2; i2++) {
            int idx = tid + i2 * 256;
            int r = idx >> 2, c = (idx & 3) * 8;
            const __half* src = (SECOND ? (g_h + (size_t)(tile_r + r) * KD)
                                        : (g_xh + (size_t)stok[r] * KD)) + k0 + c;
            cp16(Ab + r * L_ASTR + c, src);
        }
        {
            int n = tid >> 2, c = (tid & 3) * 8;
            cp16(Bb + n * L_BSTR + c, Bp + (size_t)n * KD + k0 + c);
        }
        cp_commit();
    };

    const uint32_t a_base = (uint32_t)__cvta_generic_to_shared(Asm);
    const int lr = lane & 15, lc = lane >> 4;
    uint32_t offA[2];
#pragma unroll
    for (int mi = 0; mi < 2; mi++)
        offA[mi] = (uint32_t)(((m0 + mi * 16 + lr) * L_ASTR + lc * 8) * 2);

    float c[2][4][4];
#pragma unroll
    for (int mi = 0; mi < 2; mi++)
#pragma unroll
        for (int nj = 0; nj < 4; nj++)
#pragma unroll
            for (int q = 0; q < 4; q++) c[mi][nj][q] = 0.f;

    constexpr int NIT = KD / 32;
    load_stage(0, 0);
    for (int it = 0; it < NIT; ++it) {
        const int buf = it & 1;
        if (it + 1 < NIT) { load_stage(it + 1, buf ^ 1); cp_wait<1>(); }
        else              { cp_wait<0>(); }
        __syncthreads();
        const uint32_t abuf = a_base + (uint32_t)(buf * (L_ABUF * 2));
        const __half* Bb = Bsm + buf * L_BBUF;
#pragma unroll
        for (int kk = 0; kk < 2; kk++) {
            uint32_t a[2][4], b[4][2];
#pragma unroll
            for (int mi = 0; mi < 2; mi++)
                ldsm_x4(a[mi], abuf + offA[mi] + (uint32_t)(kk * 32));
#pragma unroll
            for (int nj = 0; nj < 4; nj++) {
                int n = n0 + nj * 8 + gq;
                const uint32_t* bp =
                    (const uint32_t*)(Bb + n * L_BSTR + kk * 16 + tq * 2);
                b[nj][0] = bp[0]; b[nj][1] = bp[4];
            }
#pragma unroll
            for (int mi = 0; mi < 2; mi++)
#pragma unroll
                for (int nj = 0; nj < 4; nj++)
                    mma_f16(c[mi][nj], a[mi], b[nj]);
        }
        __syncthreads();
    }

    __half* T = (SECOND ? g_t2 : g_t1);
#pragma unroll
    for (int mi = 0; mi < 2; mi++) {
#pragma unroll
        for (int rs = 0; rs < 2; rs++) {
            int rloc = m0 + mi * 16 + gq + rs * 8;
            int bd = sband[rloc];
            __half* trow = T + (size_t)(tile_r + rloc) * 64;
#pragma unroll
            for (int nj = 0; nj < 4; nj++) {
                int gcol = n0 + nj * 8 + tq * 2;
                bool in0 = ((gcol >> 4) == bd);
                float v0 = in0 ? 2.0f * c[mi][nj][rs * 2 + 0] : 0.f;
                float v1 = in0 ? 2.0f * c[mi][nj][rs * 2 + 1] : 0.f;
                *reinterpret_cast<__half2*>(trow + gcol) = __floats2half2_rn(v0, v1);
            }
        }
    }
}

// ---------------- 6/8. grouped GEMM: fp16 m16n8k16, 256x128 tile, K-stage 64 ------
// 4-buffer cp.async pipeline, ONE barrier per 64-wide K-stage.
#define ASTR 72
#define BSTR 72
#define ABUF (256 * ASTR)
#define BBUF (128 * BSTR)
#define NBUF 4
#define GEMM_SMEM ((NBUF * (ABUF + BBUF)) * 2 + 1024)

template <int KMAIN, int NWW, bool SECOND>
__global__ void __launch_bounds__(512, 1)
k_gemm(const __half* __restrict__ Bw, const float* __restrict__ bias,
       float* __restrict__ y) {
    const int tile_r = blockIdx.y * 256;
    if (tile_r >= g_total) return;
    const int tile_c = blockIdx.x * 128;
    const int e = g_expert[tile_r];
    constexpr int KROW = KMAIN + 64;

    extern __shared__ __half smh[];
    __half* Asm = smh;
    __half* Bsm = smh + NBUF * ABUF;
    int*   stok = (int*)(smh + NBUF * (ABUF + BBUF));

    const int tid  = threadIdx.x;
    const int wid  = tid >> 5;
    const int lane = tid & 31;
    const int gq   = lane >> 2;
    const int tq   = lane & 3;
    const int m0   = (wid & 3) * 64;
    const int n0   = (wid >> 2) * 32;

    if (!SECOND && tid < 256) stok[tid] = g_token[tile_r + tid];
    __syncthreads();

    const __half* Bp = Bw + ((size_t)e * NWW + tile_c) * KROW;
    const __half* Aext = (SECOND ? g_t2 : g_t1) + (size_t)tile_r * 64;

    auto load_stage = [&](int s, int buf) {
        const int k0 = s * 64;
        const bool mn = (k0 < KMAIN);   // K-stage never straddles main/ext (both %64==0)
        __half* Ab = Asm + buf * ABUF;
        __half* Bb = Bsm + buf * BBUF;
#pragma unroll
        for (int i = 0; i < 4; i++) {                    // A: 256x64 halves = 2048 cp16
            int idx = tid + i * 512;
            int r = idx >> 3, c = (idx & 7) * 8;
            const __half* src;
            if (mn) src = (SECOND ? (g_h + (size_t)(tile_r + r) * KMAIN)
                                  : (g_xh + (size_t)stok[r] * KMAIN)) + k0 + c;
            else    src = Aext + (size_t)r * 64 + c;
            cp16(Ab + r * ASTR + c, src);
        }
#pragma unroll
        for (int i = 0; i < 2; i++) {                    // B: 128x64 halves = 1024 cp16
            int idx = tid + i * 512;
            int n = idx >> 3, c = (idx & 7) * 8;
            cp16(Bb + n * BSTR + c, Bp + (size_t)n * KROW + k0 + c);
        }
        cp_commit();
    };

    const uint32_t a_base = (uint32_t)__cvta_generic_to_shared(Asm);
    const int lr = lane & 15, lc = lane >> 4;
    uint32_t offA[4];
#pragma unroll
    for (int mi = 0; mi < 4; mi++)
        offA[mi] = (uint32_t)(((m0 + mi * 16 + lr) * ASTR + lc * 8) * 2);

    float c[4][4][4];
#pragma unroll
    for (int mi = 0; mi < 4; mi++)
#pragma unroll
        for (int nj = 0; nj < 4; nj++)
#pragma unroll
            for (int qq = 0; qq < 4; qq++) c[mi][nj][qq] = 0.f;

    constexpr int NIT = KROW / 64;
    load_stage(0, 0);
    load_stage(1, 1);
    load_stage(2, 2);

    for (int it = 0; it < NIT; ++it) {
        const int buf = it & 3;
        cp_wait<2>();
        __syncthreads();
        if (it + 3 < NIT) load_stage(it + 3, (it + 3) & 3);
        else              cp_commit();

        const uint32_t abuf = a_base + (uint32_t)(buf * (ABUF * 2));
        const __half* Bb = Bsm + buf * BBUF;
#pragma unroll
        for (int kk = 0; kk < 4; kk++) {
            uint32_t a[4][4], b[4][2];
#pragma unroll
            for (int mi = 0; mi < 4; mi++)
                ldsm_x4(a[mi], abuf + offA[mi] + (uint32_t)(kk * 32));
#pragma unroll
            for (int nj = 0; nj < 4; nj++) {
                int n = n0 + nj * 8 + gq;
                const uint32_t* bp =
                    (const uint32_t*)(Bb + n * BSTR + kk * 16 + tq * 2);
                b[nj][0] = bp[0]; b[nj][1] = bp[4];
            }
#pragma unroll
            for (int mi = 0; mi < 4; mi++)
#pragma unroll
                for (int nj = 0; nj < 4; nj++)
                    mma_f16(c[mi][nj], a[mi], b[nj]);
        }
    }

#pragma unroll
    for (int mi = 0; mi < 4; mi++) {
#pragma unroll
        for (int rs = 0; rs < 2; rs++) {
            int rloc = m0 + mi * 16 + gq + rs * 8;
            int grow = tile_r + rloc;
            float gt = 0.f; int tok = 0;
            if (SECOND) { gt = g_gate[grow]; tok = g_token[grow]; }
#pragma unroll
            for (int nj = 0; nj < 4; nj++) {
                int gcol = tile_c + n0 + nj * 8 + tq * 2;
                float v0 = c[mi][nj][rs * 2 + 0] + bias[e * NWW + gcol];
                float v1 = c[mi][nj][rs * 2 + 1] + bias[e * NWW + gcol + 1];
                if (!SECOND) {
                    *reinterpret_cast<__half2*>(&g_h[(size_t)grow * NWW + gcol]) =
                        __floats2half2_rn(gelu_exact(v0), gelu_exact(v1));
                } else {
                    atomicAdd(&y[(size_t)tok * NWW + gcol],     v0 * gt);
                    atomicAdd(&y[(size_t)tok * NWW + gcol + 1], v1 * gt);
                }
            }
        }
    }
}

// ---------------- loss (hoisted: depends only on gating) ----------------
__global__ void k_loss(float* __restrict__ out, int out_size) {
    __shared__ float simp[256][NEXP];
    __shared__ float s_imp[NEXP];
    int tid = threadIdx.x;
    float local[NEXP];
#pragma unroll
    for (int e = 0; e < NEXP; e++) local[e] = 0.f;
    for (int i = tid; i < 2 * NTOK; i += 256) {
        int e = g_top2_idx[i];
        float gv = g_top2_gate[i];
#pragma unroll
        for (int q = 0; q < NEXP; q++) local[q] += (q == e) ? gv : 0.f;
    }
#pragma unroll
    for (int e = 0; e < NEXP; e++) simp[tid][e] = local[e];
    __syncthreads();
    if (tid < NEXP) {
        float s = 0.f;
        for (int i = 0; i < 256; i++) s += simp[i][tid];
        s_imp[tid] = s;
    }
    __syncthreads();
    if (tid == 0) {
        int cnt_e[NEXP];
        for (int e = 0; e < NEXP; e++) {
            int cum = 0;
            for (int b = 0; b < NB; b++) cum += g_cnt_eb[e * NB + b];
            cnt_e[e] = cum;
        }
        float mi = 0.f, ml = 0.f;
        for (int e = 0; e < NEXP; e++) { mi += s_imp[e]; ml += (float)cnt_e[e]; }
        mi *= (1.f / NEXP); ml *= (1.f / NEXP);
        float vi = 0.f, vl = 0.f;
        for (int e = 0; e < NEXP; e++) {
            float di = s_imp[e] - mi;        vi += di * di;
            float dl = (float)cnt_e[e] - ml; vl += dl * dl;
        }
        vi *= (1.f / (NEXP - 1)); vl *= (1.f / (NEXP - 1));
        float loss = 0.01f * (vi / (mi * mi + 1e-10f) + vl / (ml * ml + 1e-10f));
        if (out_size > NTOK * NOUT) out[(size_t)NTOK * NOUT] = loss;
    }
}

// ---------------- launch: forked prologue, joined mainline ----------------
extern "C" void kernel_launch(void* const* d_in, const int* in_sizes, int n_in,
                              void* d_out, int out_size) {
    const float* x      = (const float*)d_in[0];
    const int*   band   = (const int*)d_in[1];
    const float* w_gate = (const float*)d_in[2];
    const float* W1     = (const float*)d_in[3];
    const float* b1     = (const float*)d_in[4];
    const float* W2     = (const float*)d_in[5];
    const float* b2     = (const float*)d_in[6];
    const float* A1     = (const float*)d_in[7];
    const float* B1     = (const float*)d_in[8];
    const float* A2     = (const float*)d_in[9];
    const float* B2     = (const float*)d_in[10];
    float* y = (float*)d_out;

    static bool inited = false;
    static cudaStream_t s1, s2;
    static cudaEvent_t evA, ev1, ev2;
    if (!inited) {
        cudaStreamCreateWithFlags(&s1, cudaStreamNonBlocking);
        cudaStreamCreateWithFlags(&s2, cudaStreamNonBlocking);
        cudaEventCreateWithFlags(&evA, cudaEventDisableTiming);
        cudaEventCreateWithFlags(&ev1, cudaEventDisableTiming);
        cudaEventCreateWithFlags(&ev2, cudaEventDisableTiming);
        inited = true;
    }

    __half *w1h, *w2h;
    cudaGetSymbolAddress((void**)&w1h, g_w1h);
    cudaGetSymbolAddress((void**)&w2h, g_w2h);
    cudaFuncSetAttribute(k_gemm<DIM, HID, false>,
                         cudaFuncAttributeMaxDynamicSharedMemorySize, GEMM_SMEM);
    cudaFuncSetAttribute(k_gemm<HID, NOUT, true>,
                         cudaFuncAttributeMaxDynamicSharedMemorySize, GEMM_SMEM);

    // fork: s1 = weight prep, s2 = big init, s0(default) = gating chain
    cudaEventRecord(evA, 0);
    cudaStreamWaitEvent(s1, evA, 0);
    cudaStreamWaitEvent(s2, evA, 0);

    k_prep<<<PS5, 256, 0, s1>>>(W1, B1, W2, B2, A1, A2);
    k_binit<<<16384, 256, 0, s2>>>(y, x);

    k_zinit<<<PMAX / 256, 256>>>();
    k_gate<<<2048, 256>>>(x, w_gate, band);
    k_scatter<<<128, 256>>>(band);
    k_loss<<<1, 256>>>(y, out_size);

    // join
    cudaEventRecord(ev1, s1);
    cudaEventRecord(ev2, s2);
    cudaStreamWaitEvent(0, ev1, 0);
    cudaStreamWaitEvent(0, ev2, 0);

    // mainline
    k_lmma<DIM, false><<<PMAX / 128, 256, LMMA_SMEM>>>();
    k_gemm<DIM, HID, false><<<dim3(HID / 128, PMAX / 256), 512, GEMM_SMEM>>>(w1h, b1, y);
    k_lmma<HID, true><<<PMAX / 128, 256, LMMA_SMEM>>>();
    k_gemm<HID, NOUT, true><<<dim3(NOUT / 128, PMAX / 256), 512, GEMM_SMEM>>>(w2h, b2, y);
}

// round 13
// speedup vs baseline: 4.1028x; 1.0441x over previous
#include <cuda_runtime.h>
#include <cuda_fp16.h>
#include <math.h>
#include <stdint.h>

// ---------------- problem constants ----------------
#define NTOK 16384
#define DIM  1024
#define HID  4096
#define NOUT 1024
#define NEXP 8
#define NB   4
#define PMAX 34816            // array capacity; g_total <= 2*NTOK + 8*128 = 33792 (128-aligned)

// ---------------- device scratch (static: no allocs allowed) ----------------
__device__ __half g_h  [(size_t)PMAX * HID];              // post-gelu hidden (fp16)
__device__ __half g_xh [(size_t)NTOK * DIM];              // fp16(x)
__device__ __half g_w1h[(size_t)NEXP * HID * (DIM + 64)]; // [E][H][1088] = W1^T ++ B1^T
__device__ __half g_w2h[(size_t)NEXP * NOUT * (HID + 64)];// [E][O][4160] = W2^T ++ B2^T
__device__ __half g_a1t[(size_t)NEXP * 64 * DIM];         // [E][j=b*16+r][D]
__device__ __half g_a2t[(size_t)NEXP * 64 * HID];         // [E][j][H]
__device__ __half g_t1 [(size_t)PMAX * 64];
__device__ __half g_t2 [(size_t)PMAX * 64];
__device__ int   g_token[PMAX];
__device__ int   g_band[PMAX];
__device__ int   g_expert[PMAX];
__device__ float g_gate[PMAX];
__device__ int   g_top2_idx[NTOK * 2];
__device__ float g_top2_gate[NTOK * 2];
__device__ int   g_cnt_eb[NEXP * NB];
__device__ int   g_cur_eb[NEXP * NB];
__device__ int   g_total;

// ---------------- helpers ----------------
__device__ __forceinline__ void cp16(const void* smem, const void* gmem) {
    uint32_t s = (uint32_t)__cvta_generic_to_shared(smem);
    asm volatile("cp.async.cg.shared.global [%0], [%1], 16;" :: "r"(s), "l"(gmem));
}
__device__ __forceinline__ void cp_commit() { asm volatile("cp.async.commit_group;" ::: "memory"); }
template <int n> __device__ __forceinline__ void cp_wait() {
    asm volatile("cp.async.wait_group %0;" :: "n"(n) : "memory");
}
__device__ __forceinline__ void mma_f16(float* c, const uint32_t* a, const uint32_t* b) {
    asm volatile(
        "mma.sync.aligned.m16n8k16.row.col.f32.f16.f16.f32 "
        "{%0,%1,%2,%3}, {%4,%5,%6,%7}, {%8,%9}, {%0,%1,%2,%3};"
        : "+f"(c[0]), "+f"(c[1]), "+f"(c[2]), "+f"(c[3])
        : "r"(a[0]), "r"(a[1]), "r"(a[2]), "r"(a[3]), "r"(b[0]), "r"(b[1]));
}
__device__ __forceinline__ void ldsm_x4(uint32_t* d, uint32_t addr) {
    asm volatile("ldmatrix.sync.aligned.m8n8.x4.shared.b16 {%0,%1,%2,%3}, [%4];"
                 : "=r"(d[0]), "=r"(d[1]), "=r"(d[2]), "=r"(d[3]) : "r"(addr));
}
__device__ __forceinline__ float gelu_exact(float x) {
    return 0.5f * x * (1.0f + erff(x * 0.70710678118654752440f));
}

// ---------------- 1a. zinit ----------------
__global__ void k_zinit() {
    int i = blockIdx.x * 256 + threadIdx.x;
    g_token[i] = 0; g_band[i] = 0; g_expert[i] = 0; g_gate[i] = 0.f;
    if (i < NEXP * NB) { g_cnt_eb[i] = 0; g_cur_eb[i] = 0; }
}

// ---------------- 1b. binit (side stream) ----------------
__global__ void k_binit(float* __restrict__ y, const float* __restrict__ x) {
    size_t i = (size_t)blockIdx.x * 256 + threadIdx.x;
    reinterpret_cast<float4*>(y)[i] = make_float4(0.f, 0.f, 0.f, 0.f);
    float4 v = reinterpret_cast<const float4*>(x)[i];
    __half2* d = reinterpret_cast<__half2*>(g_xh + i * 4);
    d[0] = __floats2half2_rn(v.x, v.y);
    d[1] = __floats2half2_rn(v.z, v.w);
}

// ---------------- 2. mega-prep (side stream) ----------------
#define PS0 32768
#define PS1 65536
#define PS2 73728
#define PS3 75776
#define PS4 77824
#define PS5 86016

__global__ void k_prep(const float* __restrict__ W1, const float* __restrict__ B1,
                       const float* __restrict__ W2, const float* __restrict__ B2,
                       const float* __restrict__ A1, const float* __restrict__ A2) {
    __shared__ float t[32][33];
    int bid = blockIdx.x;
    int tid = threadIdx.x;
    int tx = tid & 31, ty = tid >> 5;
    if (bid < PS1) {
        const float* src; __half* dst; int KD, NW, KROW, kt, nt, e;
        if (bid < PS0) {
            src = W1; dst = g_w1h; KD = DIM; NW = HID; KROW = DIM + 64;
            e = bid >> 12; int r2 = bid & 4095; kt = r2 >> 7; nt = r2 & 127;
        } else {
            int b2 = bid - PS0;
            src = W2; dst = g_w2h; KD = HID; NW = NOUT; KROW = HID + 64;
            e = b2 >> 12; int r2 = b2 & 4095; kt = r2 >> 5; nt = r2 & 31;
        }
        int k0 = kt * 32, n0 = nt * 32;
#pragma unroll
        for (int i = 0; i < 4; i++)
            t[ty + i * 8][tx] = src[((size_t)e * KD + k0 + ty + i * 8) * NW + n0 + tx];
        __syncthreads();
#pragma unroll
        for (int i = 0; i < 4; i++)
            dst[((size_t)e * NW + n0 + ty + i * 8) * KROW + k0 + tx] =
                __float2half(t[tx][ty + i * 8]);
    } else if (bid < PS2) {
        size_t idx = (size_t)(bid - PS1) * 256 + tid;
        int j = (int)(idx & 63); int n = (int)((idx >> 6) & 4095); int e = (int)(idx >> 18);
        g_w1h[((size_t)e * HID + n) * (DIM + 64) + DIM + j] =
            __float2half(B1[((size_t)e * 64 + j) * HID + n]);
    } else if (bid < PS3) {
        size_t idx = (size_t)(bid - PS2) * 256 + tid;
        int j = (int)(idx & 63); int n = (int)((idx >> 6) & 1023); int e = (int)(idx >> 16);
        g_w2h[((size_t)e * NOUT + n) * (HID + 64) + HID + j] =
            __float2half(B2[((size_t)e * 64 + j) * NOUT + n]);
    } else if (bid < PS4) {
        size_t idx = (size_t)(bid - PS3) * 256 + tid;
        int d = (int)(idx & 1023); int j = (int)((idx >> 10) & 63); int e = (int)(idx >> 16);
        g_a1t[((size_t)e * 64 + j) * DIM + d] =
            __float2half(A1[(((size_t)e * NB + (j >> 4)) * DIM + d) * 16 + (j & 15)]);
    } else if (bid < PS5) {
        size_t idx = (size_t)(bid - PS4) * 256 + tid;
        int d = (int)(idx & 4095); int j = (int)((idx >> 12) & 63); int e = (int)(idx >> 18);
        g_a2t[((size_t)e * 64 + j) * HID + d] =
            __float2half(A2[(((size_t)e * NB + (j >> 4)) * HID + d) * 16 + (j & 15)]);
    }
}

// ---------------- 3. gating (float4 x loads) ----------------
__global__ void k_gate(const float* __restrict__ x, const float* __restrict__ wg,
                       const int* __restrict__ band) {
    int gtid = blockIdx.x * blockDim.x + threadIdx.x;
    int tok  = gtid >> 5;
    int lane = threadIdx.x & 31;
    if (tok >= NTOK) return;
    const float* xr = x + (size_t)tok * DIM;
    float acc[NEXP];
#pragma unroll
    for (int e = 0; e < NEXP; e++) acc[e] = 0.f;
#pragma unroll
    for (int it = 0; it < 8; it++) {
        int d0 = lane * 4 + it * 128;
        float4 xv = *reinterpret_cast<const float4*>(xr + d0);
        float xs[4] = {xv.x, xv.y, xv.z, xv.w};
#pragma unroll
        for (int j = 0; j < 4; j++) {
            const float4* w4 = reinterpret_cast<const float4*>(wg + (size_t)(d0 + j) * NEXP);
            float4 wa = w4[0], wb = w4[1];
            float xvj = xs[j];
            acc[0] += xvj * wa.x; acc[1] += xvj * wa.y; acc[2] += xvj * wa.z; acc[3] += xvj * wa.w;
            acc[4] += xvj * wb.x; acc[5] += xvj * wb.y; acc[6] += xvj * wb.z; acc[7] += xvj * wb.w;
        }
    }
#pragma unroll
    for (int e = 0; e < NEXP; e++)
#pragma unroll
        for (int off = 16; off; off >>= 1)
            acc[e] += __shfl_xor_sync(0xffffffffu, acc[e], off);
    int i0 = 0; float v0 = acc[0];
#pragma unroll
    for (int e = 1; e < NEXP; e++) if (acc[e] > v0) { v0 = acc[e]; i0 = e; }
    int i1 = -1; float v1 = -3.4e38f;
#pragma unroll
    for (int e = 0; e < NEXP; e++) if (e != i0 && acc[e] > v1) { v1 = acc[e]; i1 = e; }
    float ex = expf(v1 - v0);
    float den = 1.f + ex;
    if (lane == 0) {
        int b = band[tok];
        g_top2_idx[tok * 2] = i0;  g_top2_idx[tok * 2 + 1] = i1;
        g_top2_gate[tok * 2] = 1.f / den;  g_top2_gate[tok * 2 + 1] = ex / den;
        atomicAdd(&g_cnt_eb[i0 * NB + b], 1);
        atomicAdd(&g_cnt_eb[i1 * NB + b], 1);
    }
}

// ---------------- 4. scatter (128-pad: GEMM/lmma tiles are 128 rows) ----------------
__global__ void k_scatter(const int* __restrict__ band) {
    int i = blockIdx.x * 256 + threadIdx.x;
    if (i >= 2 * NTOK) return;
    int pob[NEXP * NB];
    int p = 0;
#pragma unroll
    for (int e = 0; e < NEXP; e++) {
        int cum = 0;
#pragma unroll
        for (int b = 0; b < NB; b++) {
            pob[e * NB + b] = p + cum;
            cum += __ldg(&g_cnt_eb[e * NB + b]);
        }
        p += (cum + 127) & ~127;
    }
    if (i == 0) g_total = p;
    int t = i >> 1;
    int e = g_top2_idx[i];
    int b = band[t];
    int pos = pob[e * NB + b] + atomicAdd(&g_cur_eb[e * NB + b], 1);
    g_token[pos]  = t;
    g_gate[pos]   = g_top2_gate[i];
    g_band[pos]   = b;
    g_expert[pos] = e;
}

// ---------------- 5/7. lora down-proj mma (fp16) ----------------
#define L_ASTR 40
#define L_BSTR 40
#define L_ABUF (128 * L_ASTR)
#define L_BBUF (64 * L_BSTR)
#define LMMA_SMEM ((2 * (L_ABUF + L_BBUF)) * 2 + 2048)

template <int KD, bool SECOND>
__global__ void __launch_bounds__(256, 2)
k_lmma() {
    const int tile_r = blockIdx.x * 128;
    if (tile_r >= g_total) return;
    const int e = g_expert[tile_r];

    extern __shared__ __half smh[];
    __half* Asm = smh;
    __half* Bsm = smh + 2 * L_ABUF;
    int*   stok  = (int*)(smh + 2 * (L_ABUF + L_BBUF));
    int*   sband = stok + 128;

    const int tid  = threadIdx.x;
    const int wid  = tid >> 5;
    const int lane = tid & 31;
    const int gq   = lane >> 2;
    const int tq   = lane & 3;
    const int m0   = (wid & 3) * 32;
    const int n0   = (wid >> 2) * 32;

    if (tid < 128) {
        stok[tid]  = SECOND ? (tile_r + tid) : g_token[tile_r + tid];
        sband[tid] = g_band[tile_r + tid];
    }
    __syncthreads();

    const __half* Bp = (SECOND ? g_a2t : g_a1t) + (size_t)e * 64 * KD;

    auto load_stage = [&](int s, int buf) {
        const int k0 = s * 32;
        __half* Ab = Asm + buf * L_ABUF;
        __half* Bb = Bsm + buf * L_BBUF;
#pragma unroll
        for (int i2 = 0; i2 < 2; i2++) {
            int idx = tid + i2 * 256;
            int r = idx >> 2, c = (idx & 3) * 8;
            const __half* src = (SECOND ? (g_h + (size_t)(tile_r + r) * KD)
                                        : (g_xh + (size_t)stok[r] * KD)) + k0 + c;
            cp16(Ab + r * L_ASTR + c, src);
        }
        {
            int n = tid >> 2, c = (tid & 3) * 8;
            cp16(Bb + n * L_BSTR + c, Bp + (size_t)n * KD + k0 + c);
        }
        cp_commit();
    };

    const uint32_t a_base = (uint32_t)__cvta_generic_to_shared(Asm);
    const int lr = lane & 15, lc = lane >> 4;
    uint32_t offA[2];
#pragma unroll
    for (int mi = 0; mi < 2; mi++)
        offA[mi] = (uint32_t)(((m0 + mi * 16 + lr) * L_ASTR + lc * 8) * 2);

    float c[2][4][4];
#pragma unroll
    for (int mi = 0; mi < 2; mi++)
#pragma unroll
        for (int nj = 0; nj < 4; nj++)
#pragma unroll
            for (int q = 0; q < 4; q++) c[mi][nj][q] = 0.f;

    constexpr int NIT = KD / 32;
    load_stage(0, 0);
    for (int it = 0; it < NIT; ++it) {
        const int buf = it & 1;
        if (it + 1 < NIT) { load_stage(it + 1, buf ^ 1); cp_wait<1>(); }
        else              { cp_wait<0>(); }
        __syncthreads();
        const uint32_t abuf = a_base + (uint32_t)(buf * (L_ABUF * 2));
        const __half* Bb = Bsm + buf * L_BBUF;
#pragma unroll
        for (int kk = 0; kk < 2; kk++) {
            uint32_t a[2][4], b[4][2];
#pragma unroll
            for (int mi = 0; mi < 2; mi++)
                ldsm_x4(a[mi], abuf + offA[mi] + (uint32_t)(kk * 32));
#pragma unroll
            for (int nj = 0; nj < 4; nj++) {
                int n = n0 + nj * 8 + gq;
                const uint32_t* bp =
                    (const uint32_t*)(Bb + n * L_BSTR + kk * 16 + tq * 2);
                b[nj][0] = bp[0]; b[nj][1] = bp[4];
            }
#pragma unroll
            for (int mi = 0; mi < 2; mi++)
#pragma unroll
                for (int nj = 0; nj < 4; nj++)
                    mma_f16(c[mi][nj], a[mi], b[nj]);
        }
        __syncthreads();
    }

    __half* T = (SECOND ? g_t2 : g_t1);
#pragma unroll
    for (int mi = 0; mi < 2; mi++) {
#pragma unroll
        for (int rs = 0; rs < 2; rs++) {
            int rloc = m0 + mi * 16 + gq + rs * 8;
            int bd = sband[rloc];
            __half* trow = T + (size_t)(tile_r + rloc) * 64;
#pragma unroll
            for (int nj = 0; nj < 4; nj++) {
                int gcol = n0 + nj * 8 + tq * 2;
                bool in0 = ((gcol >> 4) == bd);
                float v0 = in0 ? 2.0f * c[mi][nj][rs * 2 + 0] : 0.f;
                float v1 = in0 ? 2.0f * c[mi][nj][rs * 2 + 1] : 0.f;
                *reinterpret_cast<__half2*>(trow + gcol) = __floats2half2_rn(v0, v1);
            }
        }
    }
}

// ---------------- 6/8. grouped GEMM: fp16 m16n8k16, 128x128 tile, K-stage 64 ------
// 3-buffer cp.async pipeline, ONE barrier/stage, 256 threads, 2 CTAs/SM.
#define ASTR 72
#define BSTR 72
#define ABUF (128 * ASTR)
#define BBUF (128 * BSTR)
#define NBUF 3
#define GEMM_SMEM ((NBUF * (ABUF + BBUF)) * 2 + 1024)

template <int KMAIN, int NWW, bool SECOND>
__global__ void __launch_bounds__(256, 2)
k_gemm(const __half* __restrict__ Bw, const float* __restrict__ bias,
       float* __restrict__ y) {
    const int tile_r = blockIdx.y * 128;
    if (tile_r >= g_total) return;
    const int tile_c = blockIdx.x * 128;
    const int e = g_expert[tile_r];
    constexpr int KROW = KMAIN + 64;

    extern __shared__ __half smh[];
    __half* Asm = smh;
    __half* Bsm = smh + NBUF * ABUF;
    int*   stok = (int*)(smh + NBUF * (ABUF + BBUF));

    const int tid  = threadIdx.x;
    const int wid  = tid >> 5;
    const int lane = tid & 31;
    const int gq   = lane >> 2;
    const int tq   = lane & 3;
    const int m0   = (wid & 1) * 64;
    const int n0   = (wid >> 1) * 32;

    if (!SECOND && tid < 128) stok[tid] = g_token[tile_r + tid];
    __syncthreads();

    const __half* Bp = Bw + ((size_t)e * NWW + tile_c) * KROW;
    const __half* Aext = (SECOND ? g_t2 : g_t1) + (size_t)tile_r * 64;

    auto load_stage = [&](int s, int buf) {
        const int k0 = s * 64;
        const bool mn = (k0 < KMAIN);   // stage never straddles main/ext
        __half* Ab = Asm + buf * ABUF;
        __half* Bb = Bsm + buf * BBUF;
#pragma unroll
        for (int i = 0; i < 4; i++) {                    // A: 128x64 halves = 1024 cp16
            int idx = tid + i * 256;
            int r = idx >> 3, c = (idx & 7) * 8;
            const __half* src;
            if (mn) src = (SECOND ? (g_h + (size_t)(tile_r + r) * KMAIN)
                                  : (g_xh + (size_t)stok[r] * KMAIN)) + k0 + c;
            else    src = Aext + (size_t)r * 64 + c;
            cp16(Ab + r * ASTR + c, src);
        }
#pragma unroll
        for (int i = 0; i < 4; i++) {                    // B: 128x64 halves = 1024 cp16
            int idx = tid + i * 256;
            int n = idx >> 3, c = (idx & 7) * 8;
            cp16(Bb + n * BSTR + c, Bp + (size_t)n * KROW + k0 + c);
        }
        cp_commit();
    };

    const uint32_t a_base = (uint32_t)__cvta_generic_to_shared(Asm);
    const int lr = lane & 15, lc = lane >> 4;
    uint32_t offA[4];
#pragma unroll
    for (int mi = 0; mi < 4; mi++)
        offA[mi] = (uint32_t)(((m0 + mi * 16 + lr) * ASTR + lc * 8) * 2);

    float c[4][4][4];
#pragma unroll
    for (int mi = 0; mi < 4; mi++)
#pragma unroll
        for (int nj = 0; nj < 4; nj++)
#pragma unroll
            for (int qq = 0; qq < 4; qq++) c[mi][nj][qq] = 0.f;

    constexpr int NIT = KROW / 64;
    load_stage(0, 0);
    load_stage(1, 1);

    int buf = 0;
    for (int it = 0; it < NIT; ++it) {
        cp_wait<1>();
        __syncthreads();
        if (it + 2 < NIT) {
            int nb = buf + 2; if (nb >= NBUF) nb -= NBUF;
            load_stage(it + 2, nb);       // writes buf (it-1)%3: consumed pre-barrier
        } else {
            cp_commit();
        }

        const uint32_t abuf = a_base + (uint32_t)(buf * (ABUF * 2));
        const __half* Bb = Bsm + buf * BBUF;
#pragma unroll
        for (int kk = 0; kk < 4; kk++) {
            uint32_t a[4][4], b[4][2];
#pragma unroll
            for (int mi = 0; mi < 4; mi++)
                ldsm_x4(a[mi], abuf + offA[mi] + (uint32_t)(kk * 32));
#pragma unroll
            for (int nj = 0; nj < 4; nj++) {
                int n = n0 + nj * 8 + gq;
                const uint32_t* bp =
                    (const uint32_t*)(Bb + n * BSTR + kk * 16 + tq * 2);
                b[nj][0] = bp[0]; b[nj][1] = bp[4];
            }
#pragma unroll
            for (int mi = 0; mi < 4; mi++)
#pragma unroll
                for (int nj = 0; nj < 4; nj++)
                    mma_f16(c[mi][nj], a[mi], b[nj]);
        }
        if (++buf >= NBUF) buf = 0;
    }

#pragma unroll
    for (int mi = 0; mi < 4; mi++) {
#pragma unroll
        for (int rs = 0; rs < 2; rs++) {
            int rloc = m0 + mi * 16 + gq + rs * 8;
            int grow = tile_r + rloc;
            float gt = 0.f; int tok = 0;
            if (SECOND) { gt = g_gate[grow]; tok = g_token[grow]; }
#pragma unroll
            for (int nj = 0; nj < 4; nj++) {
                int gcol = tile_c + n0 + nj * 8 + tq * 2;
                float v0 = c[mi][nj][rs * 2 + 0] + bias[e * NWW + gcol];
                float v1 = c[mi][nj][rs * 2 + 1] + bias[e * NWW + gcol + 1];
                if (!SECOND) {
                    *reinterpret_cast<__half2*>(&g_h[(size_t)grow * NWW + gcol]) =
                        __floats2half2_rn(gelu_exact(v0), gelu_exact(v1));
                } else {
                    atomicAdd(&y[(size_t)tok * NWW + gcol],     v0 * gt);
                    atomicAdd(&y[(size_t)tok * NWW + gcol + 1], v1 * gt);
                }
            }
        }
    }
}

// ---------------- loss ----------------
__global__ void k_loss(float* __restrict__ out, int out_size) {
    __shared__ float simp[256][NEXP];
    __shared__ float s_imp[NEXP];
    int tid = threadIdx.x;
    float local[NEXP];
#pragma unroll
    for (int e = 0; e < NEXP; e++) local[e] = 0.f;
    for (int i = tid; i < 2 * NTOK; i += 256) {
        int e = g_top2_idx[i];
        float gv = g_top2_gate[i];
#pragma unroll
        for (int q = 0; q < NEXP; q++) local[q] += (q == e) ? gv : 0.f;
    }
#pragma unroll
    for (int e = 0; e < NEXP; e++) simp[tid][e] = local[e];
    __syncthreads();
    if (tid < NEXP) {
        float s = 0.f;
        for (int i = 0; i < 256; i++) s += simp[i][tid];
        s_imp[tid] = s;
    }
    __syncthreads();
    if (tid == 0) {
        int cnt_e[NEXP];
        for (int e = 0; e < NEXP; e++) {
            int cum = 0;
            for (int b = 0; b < NB; b++) cum += g_cnt_eb[e * NB + b];
            cnt_e[e] = cum;
        }
        float mi = 0.f, ml = 0.f;
        for (int e = 0; e < NEXP; e++) { mi += s_imp[e]; ml += (float)cnt_e[e]; }
        mi *= (1.f / NEXP); ml *= (1.f / NEXP);
        float vi = 0.f, vl = 0.f;
        for (int e = 0; e < NEXP; e++) {
            float di = s_imp[e] - mi;        vi += di * di;
            float dl = (float)cnt_e[e] - ml; vl += dl * dl;
        }
        vi *= (1.f / (NEXP - 1)); vl *= (1.f / (NEXP - 1));
        float loss = 0.01f * (vi / (mi * mi + 1e-10f) + vl / (ml * ml + 1e-10f));
        if (out_size > NTOK * NOUT) out[(size_t)NTOK * NOUT] = loss;
    }
}

// ---------------- launch: forked prologue, joined mainline ----------------
extern "C" void kernel_launch(void* const* d_in, const int* in_sizes, int n_in,
                              void* d_out, int out_size) {
    const float* x      = (const float*)d_in[0];
    const int*   band   = (const int*)d_in[1];
    const float* w_gate = (const float*)d_in[2];
    const float* W1     = (const float*)d_in[3];
    const float* b1     = (const float*)d_in[4];
    const float* W2     = (const float*)d_in[5];
    const float* b2     = (const float*)d_in[6];
    const float* A1     = (const float*)d_in[7];
    const float* B1     = (const float*)d_in[8];
    const float* A2     = (const float*)d_in[9];
    const float* B2     = (const float*)d_in[10];
    float* y = (float*)d_out;

    static bool inited = false;
    static cudaStream_t s1, s2;
    static cudaEvent_t evA, ev1, ev2;
    if (!inited) {
        cudaStreamCreateWithFlags(&s1, cudaStreamNonBlocking);
        cudaStreamCreateWithFlags(&s2, cudaStreamNonBlocking);
        cudaEventCreateWithFlags(&evA, cudaEventDisableTiming);
        cudaEventCreateWithFlags(&ev1, cudaEventDisableTiming);
        cudaEventCreateWithFlags(&ev2, cudaEventDisableTiming);
        inited = true;
    }

    __half *w1h, *w2h;
    cudaGetSymbolAddress((void**)&w1h, g_w1h);
    cudaGetSymbolAddress((void**)&w2h, g_w2h);
    cudaFuncSetAttribute(k_gemm<DIM, HID, false>,
                         cudaFuncAttributeMaxDynamicSharedMemorySize, GEMM_SMEM);
    cudaFuncSetAttribute(k_gemm<HID, NOUT, true>,
                         cudaFuncAttributeMaxDynamicSharedMemorySize, GEMM_SMEM);

    // fork: s1 = weight prep, s2 = big init, default = gating chain
    cudaEventRecord(evA, 0);
    cudaStreamWaitEvent(s1, evA, 0);
    cudaStreamWaitEvent(s2, evA, 0);

    k_prep<<<PS5, 256, 0, s1>>>(W1, B1, W2, B2, A1, A2);
    k_binit<<<16384, 256, 0, s2>>>(y, x);

    k_zinit<<<PMAX / 256, 256>>>();
    k_gate<<<2048, 256>>>(x, w_gate, band);
    k_scatter<<<128, 256>>>(band);
    k_loss<<<1, 256>>>(y, out_size);

    // join
    cudaEventRecord(ev1, s1);
    cudaEventRecord(ev2, s2);
    cudaStreamWaitEvent(0, ev1, 0);
    cudaStreamWaitEvent(0, ev2, 0);

    // mainline
    k_lmma<DIM, false><<<PMAX / 128, 256, LMMA_SMEM>>>();
    k_gemm<DIM, HID, false><<<dim3(HID / 128, PMAX / 128), 256, GEMM_SMEM>>>(w1h, b1, y);
    k_lmma<HID, true><<<PMAX / 128, 256, LMMA_SMEM>>>();
    k_gemm<HID, NOUT, true><<<dim3(NOUT / 128, PMAX / 128), 256, GEMM_SMEM>>>(w2h, b2, y);
}

// round 14
// speedup vs baseline: 4.2453x; 1.0347x over previous
#include <cuda_runtime.h>
#include <cuda_fp16.h>
#include <math.h>
#include <stdint.h>

// ---------------- problem constants ----------------
#define NTOK 16384
#define DIM  1024
#define HID  4096
#define NOUT 1024
#define NEXP 8
#define NB   4
#define PMAX 34816            // array capacity; g_total <= 2*NTOK + 8*128 = 33792 (128-aligned)

// ---------------- device scratch (static: no allocs allowed) ----------------
__device__ __half g_h  [(size_t)PMAX * HID];              // post-gelu hidden (fp16)
__device__ __half g_xh [(size_t)NTOK * DIM];              // fp16(x)
__device__ __half g_w1h[(size_t)NEXP * HID * (DIM + 64)]; // [E][H][1088] = W1^T ++ B1^T
__device__ __half g_w2h[(size_t)NEXP * NOUT * (HID + 64)];// [E][O][4160] = W2^T ++ B2^T
__device__ __half g_a1t[(size_t)NEXP * 64 * DIM];         // [E][j=b*16+r][D]
__device__ __half g_a2t[(size_t)NEXP * 64 * HID];         // [E][j][H]
__device__ __half g_t1 [(size_t)PMAX * 64];
__device__ __half g_t2 [(size_t)PMAX * 64];
__device__ int   g_token[PMAX];
__device__ int   g_band[PMAX];
__device__ int   g_expert[PMAX];
__device__ float g_gate[PMAX];
__device__ int   g_top2_idx[NTOK * 2];
__device__ float g_top2_gate[NTOK * 2];
__device__ int   g_cnt_eb[NEXP * NB];
__device__ int   g_cur_eb[NEXP * NB];
__device__ int   g_total;

// ---------------- helpers ----------------
__device__ __forceinline__ void cp16(const void* smem, const void* gmem) {
    uint32_t s = (uint32_t)__cvta_generic_to_shared(smem);
    asm volatile("cp.async.cg.shared.global [%0], [%1], 16;" :: "r"(s), "l"(gmem));
}
__device__ __forceinline__ void cp_commit() { asm volatile("cp.async.commit_group;" ::: "memory"); }
template <int n> __device__ __forceinline__ void cp_wait() {
    asm volatile("cp.async.wait_group %0;" :: "n"(n) : "memory");
}
__device__ __forceinline__ void mma_f16(float* c, const uint32_t* a, const uint32_t* b) {
    asm volatile(
        "mma.sync.aligned.m16n8k16.row.col.f32.f16.f16.f32 "
        "{%0,%1,%2,%3}, {%4,%5,%6,%7}, {%8,%9}, {%0,%1,%2,%3};"
        : "+f"(c[0]), "+f"(c[1]), "+f"(c[2]), "+f"(c[3])
        : "r"(a[0]), "r"(a[1]), "r"(a[2]), "r"(a[3]), "r"(b[0]), "r"(b[1]));
}
__device__ __forceinline__ void ldsm_x4(uint32_t* d, uint32_t addr) {
    asm volatile("ldmatrix.sync.aligned.m8n8.x4.shared.b16 {%0,%1,%2,%3}, [%4];"
                 : "=r"(d[0]), "=r"(d[1]), "=r"(d[2]), "=r"(d[3]) : "r"(addr));
}
__device__ __forceinline__ float gelu_exact(float x) {
    return 0.5f * x * (1.0f + erff(x * 0.70710678118654752440f));
}

// ---------------- 1a. zinit ----------------
__global__ void k_zinit() {
    int i = blockIdx.x * 256 + threadIdx.x;
    g_token[i] = 0; g_band[i] = 0; g_expert[i] = 0; g_gate[i] = 0.f;
    if (i < NEXP * NB) { g_cnt_eb[i] = 0; g_cur_eb[i] = 0; }
}

// ---------------- 1b. binit (side stream) ----------------
__global__ void k_binit(float* __restrict__ y, const float* __restrict__ x) {
    size_t i = (size_t)blockIdx.x * 256 + threadIdx.x;
    reinterpret_cast<float4*>(y)[i] = make_float4(0.f, 0.f, 0.f, 0.f);
    float4 v = reinterpret_cast<const float4*>(x)[i];
    __half2* d = reinterpret_cast<__half2*>(g_xh + i * 4);
    d[0] = __floats2half2_rn(v.x, v.y);
    d[1] = __floats2half2_rn(v.z, v.w);
}

// ---------------- 2. mega-prep (side stream) ----------------
#define PS0 32768
#define PS1 65536
#define PS2 73728
#define PS3 75776
#define PS4 77824
#define PS5 86016

__global__ void k_prep(const float* __restrict__ W1, const float* __restrict__ B1,
                       const float* __restrict__ W2, const float* __restrict__ B2,
                       const float* __restrict__ A1, const float* __restrict__ A2) {
    __shared__ float t[32][33];
    int bid = blockIdx.x;
    int tid = threadIdx.x;
    int tx = tid & 31, ty = tid >> 5;
    if (bid < PS1) {
        const float* src; __half* dst; int KD, NW, KROW, kt, nt, e;
        if (bid < PS0) {
            src = W1; dst = g_w1h; KD = DIM; NW = HID; KROW = DIM + 64;
            e = bid >> 12; int r2 = bid & 4095; kt = r2 >> 7; nt = r2 & 127;
        } else {
            int b2 = bid - PS0;
            src = W2; dst = g_w2h; KD = HID; NW = NOUT; KROW = HID + 64;
            e = b2 >> 12; int r2 = b2 & 4095; kt = r2 >> 5; nt = r2 & 31;
        }
        int k0 = kt * 32, n0 = nt * 32;
#pragma unroll
        for (int i = 0; i < 4; i++)
            t[ty + i * 8][tx] = src[((size_t)e * KD + k0 + ty + i * 8) * NW + n0 + tx];
        __syncthreads();
#pragma unroll
        for (int i = 0; i < 4; i++)
            dst[((size_t)e * NW + n0 + ty + i * 8) * KROW + k0 + tx] =
                __float2half(t[tx][ty + i * 8]);
    } else if (bid < PS2) {
        size_t idx = (size_t)(bid - PS1) * 256 + tid;
        int j = (int)(idx & 63); int n = (int)((idx >> 6) & 4095); int e = (int)(idx >> 18);
        g_w1h[((size_t)e * HID + n) * (DIM + 64) + DIM + j] =
            __float2half(B1[((size_t)e * 64 + j) * HID + n]);
    } else if (bid < PS3) {
        size_t idx = (size_t)(bid - PS2) * 256 + tid;
        int j = (int)(idx & 63); int n = (int)((idx >> 6) & 1023); int e = (int)(idx >> 16);
        g_w2h[((size_t)e * NOUT + n) * (HID + 64) + HID + j] =
            __float2half(B2[((size_t)e * 64 + j) * NOUT + n]);
    } else if (bid < PS4) {
        size_t idx = (size_t)(bid - PS3) * 256 + tid;
        int d = (int)(idx & 1023); int j = (int)((idx >> 10) & 63); int e = (int)(idx >> 16);
        g_a1t[((size_t)e * 64 + j) * DIM + d] =
            __float2half(A1[(((size_t)e * NB + (j >> 4)) * DIM + d) * 16 + (j & 15)]);
    } else if (bid < PS5) {
        size_t idx = (size_t)(bid - PS4) * 256 + tid;
        int d = (int)(idx & 4095); int j = (int)((idx >> 12) & 63); int e = (int)(idx >> 18);
        g_a2t[((size_t)e * 64 + j) * HID + d] =
            __float2half(A2[(((size_t)e * NB + (j >> 4)) * HID + d) * 16 + (j & 15)]);
    }
}

// ---------------- 3. gating (R12 access pattern: stride-32 scalar x, 2x float4 w) ----
__global__ void k_gate(const float* __restrict__ x, const float* __restrict__ wg,
                       const int* __restrict__ band) {
    int gtid = blockIdx.x * blockDim.x + threadIdx.x;
    int tok  = gtid >> 5;
    int lane = threadIdx.x & 31;
    if (tok >= NTOK) return;
    const float* xr = x + (size_t)tok * DIM;
    float acc[NEXP];
#pragma unroll
    for (int e = 0; e < NEXP; e++) acc[e] = 0.f;
    for (int d = lane; d < DIM; d += 32) {
        float xv = xr[d];
        const float4* w4 = reinterpret_cast<const float4*>(wg + (size_t)d * NEXP);
        float4 wa = w4[0], wb = w4[1];
        acc[0] += xv * wa.x; acc[1] += xv * wa.y; acc[2] += xv * wa.z; acc[3] += xv * wa.w;
        acc[4] += xv * wb.x; acc[5] += xv * wb.y; acc[6] += xv * wb.z; acc[7] += xv * wb.w;
    }
#pragma unroll
    for (int e = 0; e < NEXP; e++)
#pragma unroll
        for (int off = 16; off; off >>= 1)
            acc[e] += __shfl_xor_sync(0xffffffffu, acc[e], off);
    int i0 = 0; float v0 = acc[0];
#pragma unroll
    for (int e = 1; e < NEXP; e++) if (acc[e] > v0) { v0 = acc[e]; i0 = e; }
    int i1 = -1; float v1 = -3.4e38f;
#pragma unroll
    for (int e = 0; e < NEXP; e++) if (e != i0 && acc[e] > v1) { v1 = acc[e]; i1 = e; }
    float ex = expf(v1 - v0);
    float den = 1.f + ex;
    if (lane == 0) {
        int b = band[tok];
        g_top2_idx[tok * 2] = i0;  g_top2_idx[tok * 2 + 1] = i1;
        g_top2_gate[tok * 2] = 1.f / den;  g_top2_gate[tok * 2 + 1] = ex / den;
        atomicAdd(&g_cnt_eb[i0 * NB + b], 1);
        atomicAdd(&g_cnt_eb[i1 * NB + b], 1);
    }
}

// ---------------- 4. scatter (128-pad) ----------------
__global__ void k_scatter(const int* __restrict__ band) {
    int i = blockIdx.x * 256 + threadIdx.x;
    if (i >= 2 * NTOK) return;
    int pob[NEXP * NB];
    int p = 0;
#pragma unroll
    for (int e = 0; e < NEXP; e++) {
        int cum = 0;
#pragma unroll
        for (int b = 0; b < NB; b++) {
            pob[e * NB + b] = p + cum;
            cum += __ldg(&g_cnt_eb[e * NB + b]);
        }
        p += (cum + 127) & ~127;
    }
    if (i == 0) g_total = p;
    int t = i >> 1;
    int e = g_top2_idx[i];
    int b = band[t];
    int pos = pob[e * NB + b] + atomicAdd(&g_cur_eb[e * NB + b], 1);
    g_token[pos]  = t;
    g_gate[pos]   = g_top2_gate[i];
    g_band[pos]   = b;
    g_expert[pos] = e;
}

// ---------------- 5/7. lora down-proj mma (fp16) ----------------
#define L_ASTR 40
#define L_BSTR 40
#define L_ABUF (128 * L_ASTR)
#define L_BBUF (64 * L_BSTR)
#define LMMA_SMEM ((2 * (L_ABUF + L_BBUF)) * 2 + 2048)

template <int KD, bool SECOND>
__global__ void __launch_bounds__(256, 2)
k_lmma() {
    const int tile_r = blockIdx.x * 128;
    if (tile_r >= g_total) return;
    const int e = g_expert[tile_r];

    extern __shared__ __half smh[];
    __half* Asm = smh;
    __half* Bsm = smh + 2 * L_ABUF;
    int*   stok  = (int*)(smh + 2 * (L_ABUF + L_BBUF));
    int*   sband = stok + 128;

    const int tid  = threadIdx.x;
    const int wid  = tid >> 5;
    const int lane = tid & 31;
    const int gq   = lane >> 2;
    const int tq   = lane & 3;
    const int m0   = (wid & 3) * 32;
    const int n0   = (wid >> 2) * 32;

    if (tid < 128) {
        stok[tid]  = SECOND ? (tile_r + tid) : g_token[tile_r + tid];
        sband[tid] = g_band[tile_r + tid];
    }
    __syncthreads();

    const __half* Bp = (SECOND ? g_a2t : g_a1t) + (size_t)e * 64 * KD;

    auto load_stage = [&](int s, int buf) {
        const int k0 = s * 32;
        __half* Ab = Asm + buf * L_ABUF;
        __half* Bb = Bsm + buf * L_BBUF;
#pragma unroll
        for (int i2 = 0; i2 < 2; i2++) {
            int idx = tid + i2 * 256;
            int r = idx >> 2, c = (idx & 3) * 8;
            const __half* src = (SECOND ? (g_h + (size_t)(tile_r + r) * KD)
                                        : (g_xh + (size_t)stok[r] * KD)) + k0 + c;
            cp16(Ab + r * L_ASTR + c, src);
        }
        {
            int n = tid >> 2, c = (tid & 3) * 8;
            cp16(Bb + n * L_BSTR + c, Bp + (size_t)n * KD + k0 + c);
        }
        cp_commit();
    };

    const uint32_t a_base = (uint32_t)__cvta_generic_to_shared(Asm);
    const int lr = lane & 15, lc = lane >> 4;
    uint32_t offA[2];
#pragma unroll
    for (int mi = 0; mi < 2; mi++)
        offA[mi] = (uint32_t)(((m0 + mi * 16 + lr) * L_ASTR + lc * 8) * 2);

    float c[2][4][4];
#pragma unroll
    for (int mi = 0; mi < 2; mi++)
#pragma unroll
        for (int nj = 0; nj < 4; nj++)
#pragma unroll
            for (int q = 0; q < 4; q++) c[mi][nj][q] = 0.f;

    constexpr int NIT = KD / 32;
    load_stage(0, 0);
    for (int it = 0; it < NIT; ++it) {
        const int buf = it & 1;
        if (it + 1 < NIT) { load_stage(it + 1, buf ^ 1); cp_wait<1>(); }
        else              { cp_wait<0>(); }
        __syncthreads();
        const uint32_t abuf = a_base + (uint32_t)(buf * (L_ABUF * 2));
        const __half* Bb = Bsm + buf * L_BBUF;
#pragma unroll
        for (int kk = 0; kk < 2; kk++) {
            uint32_t a[2][4], b[4][2];
#pragma unroll
            for (int mi = 0; mi < 2; mi++)
                ldsm_x4(a[mi], abuf + offA[mi] + (uint32_t)(kk * 32));
#pragma unroll
            for (int nj = 0; nj < 4; nj++) {
                int n = n0 + nj * 8 + gq;
                const uint32_t* bp =
                    (const uint32_t*)(Bb + n * L_BSTR + kk * 16 + tq * 2);
                b[nj][0] = bp[0]; b[nj][1] = bp[4];
            }
#pragma unroll
            for (int mi = 0; mi < 2; mi++)
#pragma unroll
                for (int nj = 0; nj < 4; nj++)
                    mma_f16(c[mi][nj], a[mi], b[nj]);
        }
        __syncthreads();
    }

    __half* T = (SECOND ? g_t2 : g_t1);
#pragma unroll
    for (int mi = 0; mi < 2; mi++) {
#pragma unroll
        for (int rs = 0; rs < 2; rs++) {
            int rloc = m0 + mi * 16 + gq + rs * 8;
            int bd = sband[rloc];
            __half* trow = T + (size_t)(tile_r + rloc) * 64;
#pragma unroll
            for (int nj = 0; nj < 4; nj++) {
                int gcol = n0 + nj * 8 + tq * 2;
                bool in0 = ((gcol >> 4) == bd);
                float v0 = in0 ? 2.0f * c[mi][nj][rs * 2 + 0] : 0.f;
                float v1 = in0 ? 2.0f * c[mi][nj][rs * 2 + 1] : 0.f;
                *reinterpret_cast<__half2*>(trow + gcol) = __floats2half2_rn(v0, v1);
            }
        }
    }
}

// ---------------- 6/8. grouped GEMM: fp16 m16n8k16, 128x128 tile, K-stage 64 ------
// 3-buffer cp.async pipeline, ONE barrier/stage, 256 threads, 2 CTAs/SM.
#define ASTR 72
#define BSTR 72
#define ABUF (128 * ASTR)
#define BBUF (128 * BSTR)
#define NBUF 3
#define GEMM_SMEM ((NBUF * (ABUF + BBUF)) * 2 + 1024)

template <int KMAIN, int NWW, bool SECOND>
__global__ void __launch_bounds__(256, 2)
k_gemm(const __half* __restrict__ Bw, const float* __restrict__ bias,
       float* __restrict__ y) {
    const int tile_r = blockIdx.y * 128;
    if (tile_r >= g_total) return;
    const int tile_c = blockIdx.x * 128;
    const int e = g_expert[tile_r];
    constexpr int KROW = KMAIN + 64;

    extern __shared__ __half smh[];
    __half* Asm = smh;
    __half* Bsm = smh + NBUF * ABUF;
    int*   stok = (int*)(smh + NBUF * (ABUF + BBUF));

    const int tid  = threadIdx.x;
    const int wid  = tid >> 5;
    const int lane = tid & 31;
    const int gq   = lane >> 2;
    const int tq   = lane & 3;
    const int m0   = (wid & 1) * 64;
    const int n0   = (wid >> 1) * 32;

    if (!SECOND && tid < 128) stok[tid] = g_token[tile_r + tid];
    __syncthreads();

    const __half* Bp = Bw + ((size_t)e * NWW + tile_c) * KROW;
    const __half* Aext = (SECOND ? g_t2 : g_t1) + (size_t)tile_r * 64;

    auto load_stage = [&](int s, int buf) {
        const int k0 = s * 64;
        const bool mn = (k0 < KMAIN);   // stage never straddles main/ext
        __half* Ab = Asm + buf * ABUF;
        __half* Bb = Bsm + buf * BBUF;
#pragma unroll
        for (int i = 0; i < 4; i++) {                    // A: 128x64 halves = 1024 cp16
            int idx = tid + i * 256;
            int r = idx >> 3, c = (idx & 7) * 8;
            const __half* src;
            if (mn) src = (SECOND ? (g_h + (size_t)(tile_r + r) * KMAIN)
                                  : (g_xh + (size_t)stok[r] * KMAIN)) + k0 + c;
            else    src = Aext + (size_t)r * 64 + c;
            cp16(Ab + r * ASTR + c, src);
        }
#pragma unroll
        for (int i = 0; i < 4; i++) {                    // B: 128x64 halves = 1024 cp16
            int idx = tid + i * 256;
            int n = idx >> 3, c = (idx & 7) * 8;
            cp16(Bb + n * BSTR + c, Bp + (size_t)n * KROW + k0 + c);
        }
        cp_commit();
    };

    const uint32_t a_base = (uint32_t)__cvta_generic_to_shared(Asm);
    const int lr = lane & 15, lc = lane >> 4;
    uint32_t offA[4];
#pragma unroll
    for (int mi = 0; mi < 4; mi++)
        offA[mi] = (uint32_t)(((m0 + mi * 16 + lr) * ASTR + lc * 8) * 2);

    float c[4][4][4];
#pragma unroll
    for (int mi = 0; mi < 4; mi++)
#pragma unroll
        for (int nj = 0; nj < 4; nj++)
#pragma unroll
            for (int qq = 0; qq < 4; qq++) c[mi][nj][qq] = 0.f;

    constexpr int NIT = KROW / 64;
    load_stage(0, 0);
    load_stage(1, 1);

    int buf = 0;
    for (int it = 0; it < NIT; ++it) {
        cp_wait<1>();
        __syncthreads();
        if (it + 2 < NIT) {
            int nb = buf + 2; if (nb >= NBUF) nb -= NBUF;
            load_stage(it + 2, nb);       // writes buf (it-1)%3: consumed pre-barrier
        } else {
            cp_commit();
        }

        const uint32_t abuf = a_base + (uint32_t)(buf * (ABUF * 2));
        const __half* Bb = Bsm + buf * BBUF;
#pragma unroll
        for (int kk = 0; kk < 4; kk++) {
            uint32_t a[4][4], b[4][2];
#pragma unroll
            for (int mi = 0; mi < 4; mi++)
                ldsm_x4(a[mi], abuf + offA[mi] + (uint32_t)(kk * 32));
#pragma unroll
            for (int nj = 0; nj < 4; nj++) {
                int n = n0 + nj * 8 + gq;
                const uint32_t* bp =
                    (const uint32_t*)(Bb + n * BSTR + kk * 16 + tq * 2);
                b[nj][0] = bp[0]; b[nj][1] = bp[4];
            }
#pragma unroll
            for (int mi = 0; mi < 4; mi++)
#pragma unroll
                for (int nj = 0; nj < 4; nj++)
                    mma_f16(c[mi][nj], a[mi], b[nj]);
        }
        if (++buf >= NBUF) buf = 0;
    }

#pragma unroll
    for (int mi = 0; mi < 4; mi++) {
#pragma unroll
        for (int rs = 0; rs < 2; rs++) {
            int rloc = m0 + mi * 16 + gq + rs * 8;
            int grow = tile_r + rloc;
            float gt = 0.f; int tok = 0;
            if (SECOND) { gt = g_gate[grow]; tok = g_token[grow]; }
#pragma unroll
            for (int nj = 0; nj < 4; nj++) {
                int gcol = tile_c + n0 + nj * 8 + tq * 2;
                float v0 = c[mi][nj][rs * 2 + 0] + bias[e * NWW + gcol];
                float v1 = c[mi][nj][rs * 2 + 1] + bias[e * NWW + gcol + 1];
                if (!SECOND) {
                    *reinterpret_cast<__half2*>(&g_h[(size_t)grow * NWW + gcol]) =
                        __floats2half2_rn(gelu_exact(v0), gelu_exact(v1));
                } else {
                    atomicAdd(&y[(size_t)tok * NWW + gcol],     v0 * gt);
                    atomicAdd(&y[(size_t)tok * NWW + gcol + 1], v1 * gt);
                }
            }
        }
    }
}

// ---------------- loss ----------------
__global__ void k_loss(float* __restrict__ out, int out_size) {
    __shared__ float simp[256][NEXP];
    __shared__ float s_imp[NEXP];
    int tid = threadIdx.x;
    float local[NEXP];
#pragma unroll
    for (int e = 0; e < NEXP; e++) local[e] = 0.f;
    for (int i = tid; i < 2 * NTOK; i += 256) {
        int e = g_top2_idx[i];
        float gv = g_top2_gate[i];
#pragma unroll
        for (int q = 0; q < NEXP; q++) local[q] += (q == e) ? gv : 0.f;
    }
#pragma unroll
    for (int e = 0; e < NEXP; e++) simp[tid][e] = local[e];
    __syncthreads();
    if (tid < NEXP) {
        float s = 0.f;
        for (int i = 0; i < 256; i++) s += simp[i][tid];
        s_imp[tid] = s;
    }
    __syncthreads();
    if (tid == 0) {
        int cnt_e[NEXP];
        for (int e = 0; e < NEXP; e++) {
            int cum = 0;
            for (int b = 0; b < NB; b++) cum += g_cnt_eb[e * NB + b];
            cnt_e[e] = cum;
        }
        float mi = 0.f, ml = 0.f;
        for (int e = 0; e < NEXP; e++) { mi += s_imp[e]; ml += (float)cnt_e[e]; }
        mi *= (1.f / NEXP); ml *= (1.f / NEXP);
        float vi = 0.f, vl = 0.f;
        for (int e = 0; e < NEXP; e++) {
            float di = s_imp[e] - mi;        vi += di * di;
            float dl = (float)cnt_e[e] - ml; vl += dl * dl;
        }
        vi *= (1.f / (NEXP - 1)); vl *= (1.f / (NEXP - 1));
        float loss = 0.01f * (vi / (mi * mi + 1e-10f) + vl / (ml * ml + 1e-10f));
        if (out_size > NTOK * NOUT) out[(size_t)NTOK * NOUT] = loss;
    }
}

// ---------------- launch: forked prologue, joined mainline ----------------
extern "C" void kernel_launch(void* const* d_in, const int* in_sizes, int n_in,
                              void* d_out, int out_size) {
    const float* x      = (const float*)d_in[0];
    const int*   band   = (const int*)d_in[1];
    const float* w_gate = (const float*)d_in[2];
    const float* W1     = (const float*)d_in[3];
    const float* b1     = (const float*)d_in[4];
    const float* W2     = (const float*)d_in[5];
    const float* b2     = (const float*)d_in[6];
    const float* A1     = (const float*)d_in[7];
    const float* B1     = (const float*)d_in[8];
    const float* A2     = (const float*)d_in[9];
    const float* B2     = (const float*)d_in[10];
    float* y = (float*)d_out;

    static bool inited = false;
    static cudaStream_t s1, s2;
    static cudaEvent_t evA, ev1, ev2;
    if (!inited) {
        cudaStreamCreateWithFlags(&s1, cudaStreamNonBlocking);
        cudaStreamCreateWithFlags(&s2, cudaStreamNonBlocking);
        cudaEventCreateWithFlags(&evA, cudaEventDisableTiming);
        cudaEventCreateWithFlags(&ev1, cudaEventDisableTiming);
        cudaEventCreateWithFlags(&ev2, cudaEventDisableTiming);
        inited = true;
    }

    __half *w1h, *w2h;
    cudaGetSymbolAddress((void**)&w1h, g_w1h);
    cudaGetSymbolAddress((void**)&w2h, g_w2h);
    cudaFuncSetAttribute(k_gemm<DIM, HID, false>,
                         cudaFuncAttributeMaxDynamicSharedMemorySize, GEMM_SMEM);
    cudaFuncSetAttribute(k_gemm<HID, NOUT, true>,
                         cudaFuncAttributeMaxDynamicSharedMemorySize, GEMM_SMEM);

    // fork: s1 = weight prep, s2 = big init, default = gating chain
    cudaEventRecord(evA, 0);
    cudaStreamWaitEvent(s1, evA, 0);
    cudaStreamWaitEvent(s2, evA, 0);

    k_prep<<<PS5, 256, 0, s1>>>(W1, B1, W2, B2, A1, A2);
    k_binit<<<16384, 256, 0, s2>>>(y, x);

    k_zinit<<<PMAX / 256, 256>>>();
    k_gate<<<2048, 256>>>(x, w_gate, band);
    k_scatter<<<128, 256>>>(band);
    k_loss<<<1, 256>>>(y, out_size);

    // join
    cudaEventRecord(ev1, s1);
    cudaEventRecord(ev2, s2);
    cudaStreamWaitEvent(0, ev1, 0);
    cudaStreamWaitEvent(0, ev2, 0);

    // mainline
    k_lmma<DIM, false><<<PMAX / 128, 256, LMMA_SMEM>>>();
    k_gemm<DIM, HID, false><<<dim3(HID / 128, PMAX / 128), 256, GEMM_SMEM>>>(w1h, b1, y);
    k_lmma<HID, true><<<PMAX / 128, 256, LMMA_SMEM>>>();
    k_gemm<HID, NOUT, true><<<dim3(NOUT / 128, PMAX / 128), 256, GEMM_SMEM>>>(w2h, b2, y);
}

// round 15
// speedup vs baseline: 4.2673x; 1.0052x over previous
#include <cuda_runtime.h>
#include <cuda_fp16.h>
#include <math.h>
#include <stdint.h>

// ---------------- problem constants ----------------
#define NTOK 16384
#define DIM  1024
#define HID  4096
#define NOUT 1024
#define NEXP 8
#define NB   4
#define PMAX 34816            // array capacity; g_total <= 2*NTOK + 8*128 = 33792 (128-aligned)

// ---------------- device scratch (static: no allocs allowed) ----------------
__device__ __half g_h  [(size_t)PMAX * HID];              // post-gelu hidden (fp16)
__device__ __half g_xh [(size_t)NTOK * DIM];              // fp16(x)
__device__ __half g_w1h[(size_t)NEXP * HID * (DIM + 64)]; // [E][H][1088] = W1^T ++ B1^T
__device__ __half g_w2h[(size_t)NEXP * NOUT * (HID + 64)];// [E][O][4160] = W2^T ++ B2^T
__device__ __half g_a1t[(size_t)NEXP * 64 * DIM];         // [E][j=b*16+r][D]
__device__ __half g_a2t[(size_t)NEXP * 64 * HID];         // [E][j][H]
__device__ __half g_t1 [(size_t)PMAX * 64];
__device__ __half g_t2 [(size_t)PMAX * 64];
__device__ int   g_token[PMAX];
__device__ int   g_band[PMAX];
__device__ int   g_expert[PMAX];
__device__ float g_gate[PMAX];
__device__ int   g_top2_idx[NTOK * 2];
__device__ float g_top2_gate[NTOK * 2];
__device__ int   g_cnt_eb[NEXP * NB];
__device__ int   g_cur_eb[NEXP * NB];
__device__ int   g_total;

// ---------------- helpers ----------------
__device__ __forceinline__ void cp16(const void* smem, const void* gmem) {
    uint32_t s = (uint32_t)__cvta_generic_to_shared(smem);
    asm volatile("cp.async.cg.shared.global [%0], [%1], 16;" :: "r"(s), "l"(gmem));
}
__device__ __forceinline__ void cp_commit() { asm volatile("cp.async.commit_group;" ::: "memory"); }
template <int n> __device__ __forceinline__ void cp_wait() {
    asm volatile("cp.async.wait_group %0;" :: "n"(n) : "memory");
}
__device__ __forceinline__ void mma_f16(float* c, const uint32_t* a, const uint32_t* b) {
    asm volatile(
        "mma.sync.aligned.m16n8k16.row.col.f32.f16.f16.f32 "
        "{%0,%1,%2,%3}, {%4,%5,%6,%7}, {%8,%9}, {%0,%1,%2,%3};"
        : "+f"(c[0]), "+f"(c[1]), "+f"(c[2]), "+f"(c[3])
        : "r"(a[0]), "r"(a[1]), "r"(a[2]), "r"(a[3]), "r"(b[0]), "r"(b[1]));
}
__device__ __forceinline__ void ldsm_x4(uint32_t* d, uint32_t addr) {
    asm volatile("ldmatrix.sync.aligned.m8n8.x4.shared.b16 {%0,%1,%2,%3}, [%4];"
                 : "=r"(d[0]), "=r"(d[1]), "=r"(d[2]), "=r"(d[3]) : "r"(addr));
}
__device__ __forceinline__ float gelu_exact(float x) {
    return 0.5f * x * (1.0f + erff(x * 0.70710678118654752440f));
}

// ---------------- 1a. zinit (pad rows get band = NB-1: keeps bands non-decreasing
//                  within every 128-row tile, since pads follow the band-3 group) ----
__global__ void k_zinit() {
    int i = blockIdx.x * 256 + threadIdx.x;
    g_token[i] = 0; g_band[i] = NB - 1; g_expert[i] = 0; g_gate[i] = 0.f;
    if (i < NEXP * NB) { g_cnt_eb[i] = 0; g_cur_eb[i] = 0; }
}

// ---------------- 1b. binit (side stream) ----------------
__global__ void k_binit(float* __restrict__ y, const float* __restrict__ x) {
    size_t i = (size_t)blockIdx.x * 256 + threadIdx.x;
    reinterpret_cast<float4*>(y)[i] = make_float4(0.f, 0.f, 0.f, 0.f);
    float4 v = reinterpret_cast<const float4*>(x)[i];
    __half2* d = reinterpret_cast<__half2*>(g_xh + i * 4);
    d[0] = __floats2half2_rn(v.x, v.y);
    d[1] = __floats2half2_rn(v.z, v.w);
}

// ---------------- 2. mega-prep (side stream) ----------------
#define PS0 32768
#define PS1 65536
#define PS2 73728
#define PS3 75776
#define PS4 77824
#define PS5 86016

__global__ void k_prep(const float* __restrict__ W1, const float* __restrict__ B1,
                       const float* __restrict__ W2, const float* __restrict__ B2,
                       const float* __restrict__ A1, const float* __restrict__ A2) {
    __shared__ float t[32][33];
    int bid = blockIdx.x;
    int tid = threadIdx.x;
    int tx = tid & 31, ty = tid >> 5;
    if (bid < PS1) {
        const float* src; __half* dst; int KD, NW, KROW, kt, nt, e;
        if (bid < PS0) {
            src = W1; dst = g_w1h; KD = DIM; NW = HID; KROW = DIM + 64;
            e = bid >> 12; int r2 = bid & 4095; kt = r2 >> 7; nt = r2 & 127;
        } else {
            int b2 = bid - PS0;
            src = W2; dst = g_w2h; KD = HID; NW = NOUT; KROW = HID + 64;
            e = b2 >> 12; int r2 = b2 & 4095; kt = r2 >> 5; nt = r2 & 31;
        }
        int k0 = kt * 32, n0 = nt * 32;
#pragma unroll
        for (int i = 0; i < 4; i++)
            t[ty + i * 8][tx] = src[((size_t)e * KD + k0 + ty + i * 8) * NW + n0 + tx];
        __syncthreads();
#pragma unroll
        for (int i = 0; i < 4; i++)
            dst[((size_t)e * NW + n0 + ty + i * 8) * KROW + k0 + tx] =
                __float2half(t[tx][ty + i * 8]);
    } else if (bid < PS2) {
        size_t idx = (size_t)(bid - PS1) * 256 + tid;
        int j = (int)(idx & 63); int n = (int)((idx >> 6) & 4095); int e = (int)(idx >> 18);
        g_w1h[((size_t)e * HID + n) * (DIM + 64) + DIM + j] =
            __float2half(B1[((size_t)e * 64 + j) * HID + n]);
    } else if (bid < PS3) {
        size_t idx = (size_t)(bid - PS2) * 256 + tid;
        int j = (int)(idx & 63); int n = (int)((idx >> 6) & 1023); int e = (int)(idx >> 16);
        g_w2h[((size_t)e * NOUT + n) * (HID + 64) + HID + j] =
            __float2half(B2[((size_t)e * 64 + j) * NOUT + n]);
    } else if (bid < PS4) {
        size_t idx = (size_t)(bid - PS3) * 256 + tid;
        int d = (int)(idx & 1023); int j = (int)((idx >> 10) & 63); int e = (int)(idx >> 16);
        g_a1t[((size_t)e * 64 + j) * DIM + d] =
            __float2half(A1[(((size_t)e * NB + (j >> 4)) * DIM + d) * 16 + (j & 15)]);
    } else if (bid < PS5) {
        size_t idx = (size_t)(bid - PS4) * 256 + tid;
        int d = (int)(idx & 4095); int j = (int)((idx >> 12) & 63); int e = (int)(idx >> 18);
        g_a2t[((size_t)e * 64 + j) * HID + d] =
            __float2half(A2[(((size_t)e * NB + (j >> 4)) * HID + d) * 16 + (j & 15)]);
    }
}

// ---------------- 3. gating ----------------
__global__ void k_gate(const float* __restrict__ x, const float* __restrict__ wg,
                       const int* __restrict__ band) {
    int gtid = blockIdx.x * blockDim.x + threadIdx.x;
    int tok  = gtid >> 5;
    int lane = threadIdx.x & 31;
    if (tok >= NTOK) return;
    const float* xr = x + (size_t)tok * DIM;
    float acc[NEXP];
#pragma unroll
    for (int e = 0; e < NEXP; e++) acc[e] = 0.f;
    for (int d = lane; d < DIM; d += 32) {
        float xv = xr[d];
        const float4* w4 = reinterpret_cast<const float4*>(wg + (size_t)d * NEXP);
        float4 wa = w4[0], wb = w4[1];
        acc[0] += xv * wa.x; acc[1] += xv * wa.y; acc[2] += xv * wa.z; acc[3] += xv * wa.w;
        acc[4] += xv * wb.x; acc[5] += xv * wb.y; acc[6] += xv * wb.z; acc[7] += xv * wb.w;
    }
#pragma unroll
    for (int e = 0; e < NEXP; e++)
#pragma unroll
        for (int off = 16; off; off >>= 1)
            acc[e] += __shfl_xor_sync(0xffffffffu, acc[e], off);
    int i0 = 0; float v0 = acc[0];
#pragma unroll
    for (int e = 1; e < NEXP; e++) if (acc[e] > v0) { v0 = acc[e]; i0 = e; }
    int i1 = -1; float v1 = -3.4e38f;
#pragma unroll
    for (int e = 0; e < NEXP; e++) if (e != i0 && acc[e] > v1) { v1 = acc[e]; i1 = e; }
    float ex = expf(v1 - v0);
    float den = 1.f + ex;
    if (lane == 0) {
        int b = band[tok];
        g_top2_idx[tok * 2] = i0;  g_top2_idx[tok * 2 + 1] = i1;
        g_top2_gate[tok * 2] = 1.f / den;  g_top2_gate[tok * 2 + 1] = ex / den;
        atomicAdd(&g_cnt_eb[i0 * NB + b], 1);
        atomicAdd(&g_cnt_eb[i1 * NB + b], 1);
    }
}

// ---------------- 4. scatter (128-pad) ----------------
__global__ void k_scatter(const int* __restrict__ band) {
    int i = blockIdx.x * 256 + threadIdx.x;
    if (i >= 2 * NTOK) return;
    int pob[NEXP * NB];
    int p = 0;
#pragma unroll
    for (int e = 0; e < NEXP; e++) {
        int cum = 0;
#pragma unroll
        for (int b = 0; b < NB; b++) {
            pob[e * NB + b] = p + cum;
            cum += __ldg(&g_cnt_eb[e * NB + b]);
        }
        p += (cum + 127) & ~127;
    }
    if (i == 0) g_total = p;
    int t = i >> 1;
    int e = g_top2_idx[i];
    int b = band[t];
    int pos = pob[e * NB + b] + atomicAdd(&g_cur_eb[e * NB + b], 1);
    g_token[pos]  = t;
    g_gate[pos]   = g_top2_gate[i];
    g_band[pos]   = b;
    g_expert[pos] = e;
}

// ---------------- 5/7. lora down-proj mma (fp16), band-range pruned ----------------
// Rows sorted by (e,band), pads have band NB-1 => band non-decreasing per tile.
// Only 8-col chunks whose band lies in [sband[0], sband[127]] are loaded/computed;
// all other chunks were masked to zero in the epilogue anyway (bit-identical).
#define L_ASTR 40
#define L_BSTR 40
#define L_ABUF (128 * L_ASTR)
#define L_BBUF (64 * L_BSTR)
#define LMMA_SMEM ((2 * (L_ABUF + L_BBUF)) * 2 + 2048)

template <int KD, bool SECOND>
__global__ void __launch_bounds__(256, 2)
k_lmma() {
    const int tile_r = blockIdx.x * 128;
    if (tile_r >= g_total) return;
    const int e = g_expert[tile_r];

    extern __shared__ __half smh[];
    __half* Asm = smh;
    __half* Bsm = smh + 2 * L_ABUF;
    int*   stok  = (int*)(smh + 2 * (L_ABUF + L_BBUF));
    int*   sband = stok + 128;

    const int tid  = threadIdx.x;
    const int wid  = tid >> 5;
    const int lane = tid & 31;
    const int gq   = lane >> 2;
    const int tq   = lane & 3;
    const int m0   = (wid & 3) * 32;
    const int n0   = (wid >> 2) * 32;

    if (tid < 128) {
        stok[tid]  = SECOND ? (tile_r + tid) : g_token[tile_r + tid];
        sband[tid] = g_band[tile_r + tid];
    }
    __syncthreads();
    const int bmin = sband[0], bmax = sband[127];   // sorted per tile

    const __half* Bp = (SECOND ? g_a2t : g_a1t) + (size_t)e * 64 * KD;

    auto load_stage = [&](int s, int buf) {
        const int k0 = s * 32;
        __half* Ab = Asm + buf * L_ABUF;
        __half* Bb = Bsm + buf * L_BBUF;
#pragma unroll
        for (int i2 = 0; i2 < 2; i2++) {
            int idx = tid + i2 * 256;
            int r = idx >> 2, c = (idx & 3) * 8;
            const __half* src = (SECOND ? (g_h + (size_t)(tile_r + r) * KD)
                                        : (g_xh + (size_t)stok[r] * KD)) + k0 + c;
            cp16(Ab + r * L_ASTR + c, src);
        }
        {
            int n = tid >> 2, c = (tid & 3) * 8;
            int nb = n >> 4;
            if (nb >= bmin && nb <= bmax)
                cp16(Bb + n * L_BSTR + c, Bp + (size_t)n * KD + k0 + c);
        }
        cp_commit();
    };

    const uint32_t a_base = (uint32_t)__cvta_generic_to_shared(Asm);
    const int lr = lane & 15, lc = lane >> 4;
    uint32_t offA[2];
#pragma unroll
    for (int mi = 0; mi < 2; mi++)
        offA[mi] = (uint32_t)(((m0 + mi * 16 + lr) * L_ASTR + lc * 8) * 2);

    float c[2][4][4];
#pragma unroll
    for (int mi = 0; mi < 2; mi++)
#pragma unroll
        for (int nj = 0; nj < 4; nj++)
#pragma unroll
            for (int q = 0; q < 4; q++) c[mi][nj][q] = 0.f;

    constexpr int NIT = KD / 32;
    load_stage(0, 0);
    for (int it = 0; it < NIT; ++it) {
        const int buf = it & 1;
        if (it + 1 < NIT) { load_stage(it + 1, buf ^ 1); cp_wait<1>(); }
        else              { cp_wait<0>(); }
        __syncthreads();
        const uint32_t abuf = a_base + (uint32_t)(buf * (L_ABUF * 2));
        const __half* Bb = Bsm + buf * L_BBUF;
#pragma unroll
        for (int kk = 0; kk < 2; kk++) {
            uint32_t a[2][4], b[2];
#pragma unroll
            for (int mi = 0; mi < 2; mi++)
                ldsm_x4(a[mi], abuf + offA[mi] + (uint32_t)(kk * 32));
#pragma unroll
            for (int nj = 0; nj < 4; nj++) {
                int njb = (n0 + nj * 8) >> 4;        // warp-uniform chunk band
                if (njb < bmin || njb > bmax) continue;
                int n = n0 + nj * 8 + gq;
                const uint32_t* bp =
                    (const uint32_t*)(Bb + n * L_BSTR + kk * 16 + tq * 2);
                b[0] = bp[0]; b[1] = bp[4];
#pragma unroll
                for (int mi = 0; mi < 2; mi++)
                    mma_f16(c[mi][nj], a[mi], b);
            }
        }
        __syncthreads();
    }

    __half* T = (SECOND ? g_t2 : g_t1);
#pragma unroll
    for (int mi = 0; mi < 2; mi++) {
#pragma unroll
        for (int rs = 0; rs < 2; rs++) {
            int rloc = m0 + mi * 16 + gq + rs * 8;
            int bd = sband[rloc];
            __half* trow = T + (size_t)(tile_r + rloc) * 64;
#pragma unroll
            for (int nj = 0; nj < 4; nj++) {
                int gcol = n0 + nj * 8 + tq * 2;
                bool in0 = ((gcol >> 4) == bd);
                float v0 = in0 ? 2.0f * c[mi][nj][rs * 2 + 0] : 0.f;
                float v1 = in0 ? 2.0f * c[mi][nj][rs * 2 + 1] : 0.f;
                *reinterpret_cast<__half2*>(trow + gcol) = __floats2half2_rn(v0, v1);
            }
        }
    }
}

// ---------------- 6/8. grouped GEMM: fp16 m16n8k16, 128x128 tile, K-stage 64 ------
// 3-buffer cp.async pipeline, ONE barrier/stage, 256 threads, 2 CTAs/SM. (frozen)
#define ASTR 72
#define BSTR 72
#define ABUF (128 * ASTR)
#define BBUF (128 * BSTR)
#define NBUF 3
#define GEMM_SMEM ((NBUF * (ABUF + BBUF)) * 2 + 1024)

template <int KMAIN, int NWW, bool SECOND>
__global__ void __launch_bounds__(256, 2)
k_gemm(const __half* __restrict__ Bw, const float* __restrict__ bias,
       float* __restrict__ y) {
    const int tile_r = blockIdx.y * 128;
    if (tile_r >= g_total) return;
    const int tile_c = blockIdx.x * 128;
    const int e = g_expert[tile_r];
    constexpr int KROW = KMAIN + 64;

    extern __shared__ __half smh[];
    __half* Asm = smh;
    __half* Bsm = smh + NBUF * ABUF;
    int*   stok = (int*)(smh + NBUF * (ABUF + BBUF));

    const int tid  = threadIdx.x;
    const int wid  = tid >> 5;
    const int lane = tid & 31;
    const int gq   = lane >> 2;
    const int tq   = lane & 3;
    const int m0   = (wid & 1) * 64;
    const int n0   = (wid >> 1) * 32;

    if (!SECOND && tid < 128) stok[tid] = g_token[tile_r + tid];
    __syncthreads();

    const __half* Bp = Bw + ((size_t)e * NWW + tile_c) * KROW;
    const __half* Aext = (SECOND ? g_t2 : g_t1) + (size_t)tile_r * 64;

    auto load_stage = [&](int s, int buf) {
        const int k0 = s * 64;
        const bool mn = (k0 < KMAIN);
        __half* Ab = Asm + buf * ABUF;
        __half* Bb = Bsm + buf * BBUF;
#pragma unroll
        for (int i = 0; i < 4; i++) {
            int idx = tid + i * 256;
            int r = idx >> 3, c = (idx & 7) * 8;
            const __half* src;
            if (mn) src = (SECOND ? (g_h + (size_t)(tile_r + r) * KMAIN)
                                  : (g_xh + (size_t)stok[r] * KMAIN)) + k0 + c;
            else    src = Aext + (size_t)r * 64 + c;
            cp16(Ab + r * ASTR + c, src);
        }
#pragma unroll
        for (int i = 0; i < 4; i++) {
            int idx = tid + i * 256;
            int n = idx >> 3, c = (idx & 7) * 8;
            cp16(Bb + n * BSTR + c, Bp + (size_t)n * KROW + k0 + c);
        }
        cp_commit();
    };

    const uint32_t a_base = (uint32_t)__cvta_generic_to_shared(Asm);
    const int lr = lane & 15, lc = lane >> 4;
    uint32_t offA[4];
#pragma unroll
    for (int mi = 0; mi < 4; mi++)
        offA[mi] = (uint32_t)(((m0 + mi * 16 + lr) * ASTR + lc * 8) * 2);

    float c[4][4][4];
#pragma unroll
    for (int mi = 0; mi < 4; mi++)
#pragma unroll
        for (int nj = 0; nj < 4; nj++)
#pragma unroll
            for (int qq = 0; qq < 4; qq++) c[mi][nj][qq] = 0.f;

    constexpr int NIT = KROW / 64;
    load_stage(0, 0);
    load_stage(1, 1);

    int buf = 0;
    for (int it = 0; it < NIT; ++it) {
        cp_wait<1>();
        __syncthreads();
        if (it + 2 < NIT) {
            int nb = buf + 2; if (nb >= NBUF) nb -= NBUF;
            load_stage(it + 2, nb);
        } else {
            cp_commit();
        }

        const uint32_t abuf = a_base + (uint32_t)(buf * (ABUF * 2));
        const __half* Bb = Bsm + buf * BBUF;
#pragma unroll
        for (int kk = 0; kk < 4; kk++) {
            uint32_t a[4][4], b[4][2];
#pragma unroll
            for (int mi = 0; mi < 4; mi++)
                ldsm_x4(a[mi], abuf + offA[mi] + (uint32_t)(kk * 32));
#pragma unroll
            for (int nj = 0; nj < 4; nj++) {
                int n = n0 + nj * 8 + gq;
                const uint32_t* bp =
                    (const uint32_t*)(Bb + n * BSTR + kk * 16 + tq * 2);
                b[nj][0] = bp[0]; b[nj][1] = bp[4];
            }
#pragma unroll
            for (int mi = 0; mi < 4; mi++)
#pragma unroll
                for (int nj = 0; nj < 4; nj++)
                    mma_f16(c[mi][nj], a[mi], b[nj]);
        }
        if (++buf >= NBUF) buf = 0;
    }

#pragma unroll
    for (int mi = 0; mi < 4; mi++) {
#pragma unroll
        for (int rs = 0; rs < 2; rs++) {
            int rloc = m0 + mi * 16 + gq + rs * 8;
            int grow = tile_r + rloc;
            float gt = 0.f; int tok = 0;
            if (SECOND) { gt = g_gate[grow]; tok = g_token[grow]; }
#pragma unroll
            for (int nj = 0; nj < 4; nj++) {
                int gcol = tile_c + n0 + nj * 8 + tq * 2;
                float v0 = c[mi][nj][rs * 2 + 0] + bias[e * NWW + gcol];
                float v1 = c[mi][nj][rs * 2 + 1] + bias[e * NWW + gcol + 1];
                if (!SECOND) {
                    *reinterpret_cast<__half2*>(&g_h[(size_t)grow * NWW + gcol]) =
                        __floats2half2_rn(gelu_exact(v0), gelu_exact(v1));
                } else {
                    atomicAdd(&y[(size_t)tok * NWW + gcol],     v0 * gt);
                    atomicAdd(&y[(size_t)tok * NWW + gcol + 1], v1 * gt);
                }
            }
        }
    }
}

// ---------------- loss (depends only on gating; hidden on s2) ----------------
__global__ void k_loss(float* __restrict__ out, int out_size) {
    __shared__ float simp[256][NEXP];
    __shared__ float s_imp[NEXP];
    int tid = threadIdx.x;
    float local[NEXP];
#pragma unroll
    for (int e = 0; e < NEXP; e++) local[e] = 0.f;
    for (int i = tid; i < 2 * NTOK; i += 256) {
        int e = g_top2_idx[i];
        float gv = g_top2_gate[i];
#pragma unroll
        for (int q = 0; q < NEXP; q++) local[q] += (q == e) ? gv : 0.f;
    }
#pragma unroll
    for (int e = 0; e < NEXP; e++) simp[tid][e] = local[e];
    __syncthreads();
    if (tid < NEXP) {
        float s = 0.f;
        for (int i = 0; i < 256; i++) s += simp[i][tid];
        s_imp[tid] = s;
    }
    __syncthreads();
    if (tid == 0) {
        int cnt_e[NEXP];
        for (int e = 0; e < NEXP; e++) {
            int cum = 0;
            for (int b = 0; b < NB; b++) cum += g_cnt_eb[e * NB + b];
            cnt_e[e] = cum;
        }
        float mi = 0.f, ml = 0.f;
        for (int e = 0; e < NEXP; e++) { mi += s_imp[e]; ml += (float)cnt_e[e]; }
        mi *= (1.f / NEXP); ml *= (1.f / NEXP);
        float vi = 0.f, vl = 0.f;
        for (int e = 0; e < NEXP; e++) {
            float di = s_imp[e] - mi;        vi += di * di;
            float dl = (float)cnt_e[e] - ml; vl += dl * dl;
        }
        vi *= (1.f / (NEXP - 1)); vl *= (1.f / (NEXP - 1));
        float loss = 0.01f * (vi / (mi * mi + 1e-10f) + vl / (ml * ml + 1e-10f));
        if (out_size > NTOK * NOUT) out[(size_t)NTOK * NOUT] = loss;
    }
}

// ---------------- launch: forked prologue, joined mainline ----------------
extern "C" void kernel_launch(void* const* d_in, const int* in_sizes, int n_in,
                              void* d_out, int out_size) {
    const float* x      = (const float*)d_in[0];
    const int*   band   = (const int*)d_in[1];
    const float* w_gate = (const float*)d_in[2];
    const float* W1     = (const float*)d_in[3];
    const float* b1     = (const float*)d_in[4];
    const float* W2     = (const float*)d_in[5];
    const float* b2     = (const float*)d_in[6];
    const float* A1     = (const float*)d_in[7];
    const float* B1     = (const float*)d_in[8];
    const float* A2     = (const float*)d_in[9];
    const float* B2     = (const float*)d_in[10];
    float* y = (float*)d_out;

    static bool inited = false;
    static cudaStream_t s1, s2;
    static cudaEvent_t evA, evG, ev1, ev2;
    if (!inited) {
        cudaStreamCreateWithFlags(&s1, cudaStreamNonBlocking);
        cudaStreamCreateWithFlags(&s2, cudaStreamNonBlocking);
        cudaEventCreateWithFlags(&evA, cudaEventDisableTiming);
        cudaEventCreateWithFlags(&evG, cudaEventDisableTiming);
        cudaEventCreateWithFlags(&ev1, cudaEventDisableTiming);
        cudaEventCreateWithFlags(&ev2, cudaEventDisableTiming);
        inited = true;
    }

    __half *w1h, *w2h;
    cudaGetSymbolAddress((void**)&w1h, g_w1h);
    cudaGetSymbolAddress((void**)&w2h, g_w2h);
    cudaFuncSetAttribute(k_gemm<DIM, HID, false>,
                         cudaFuncAttributeMaxDynamicSharedMemorySize, GEMM_SMEM);
    cudaFuncSetAttribute(k_gemm<HID, NOUT, true>,
                         cudaFuncAttributeMaxDynamicSharedMemorySize, GEMM_SMEM);

    // fork: s1 = weight prep, s2 = big init (+loss after gate), default = gating chain
    cudaEventRecord(evA, 0);
    cudaStreamWaitEvent(s1, evA, 0);
    cudaStreamWaitEvent(s2, evA, 0);

    k_prep<<<PS5, 256, 0, s1>>>(W1, B1, W2, B2, A1, A2);
    k_binit<<<16384, 256, 0, s2>>>(y, x);

    k_zinit<<<PMAX / 256, 256>>>();
    k_gate<<<2048, 256>>>(x, w_gate, band);
    cudaEventRecord(evG, 0);
    cudaStreamWaitEvent(s2, evG, 0);
    k_loss<<<1, 256, 0, s2>>>(y, out_size);     // hidden under k_prep on s1
    k_scatter<<<128, 256>>>(band);

    // join
    cudaEventRecord(ev1, s1);
    cudaEventRecord(ev2, s2);
    cudaStreamWaitEvent(0, ev1, 0);
    cudaStreamWaitEvent(0, ev2, 0);

    // mainline
    k_lmma<DIM, false><<<PMAX / 128, 256, LMMA_SMEM>>>();
    k_gemm<DIM, HID, false><<<dim3(HID / 128, PMAX / 128), 256, GEMM_SMEM>>>(w1h, b1, y);
    k_lmma<HID, true><<<PMAX / 128, 256, LMMA_SMEM>>>();
    k_gemm<HID, NOUT, true><<<dim3(NOUT / 128, PMAX / 128), 256, GEMM_SMEM>>>(w2h, b2, y);
}